// round 7
// baseline (speedup 1.0000x reference)
#include <cuda_runtime.h>
#include <math.h>
#include <stdint.h>

// Problem constants
#define NB 16      // batch
#define CC 64      // channels
#define TT 64      // time
#define VV 25      // vertices
#define HH 4       // heads
#define DD 64      // head dim
#define LL (TT*VV) // 1600 tokens
#define HD (HH*DD) // 256

// Scratch (device globals; no runtime allocation allowed)
__device__ float g_q[NB*HH*LL*DD];
__device__ float g_k[NB*HH*LL*DD];
__device__ float g_v[NB*HH*LL*DD];
__device__ float g_o[NB*HD*LL];    // attention out in [N, H*D, T, V] layout
__device__ float g_wt[2304*64];    // W_out transposed to [k'=kw*256+ci][c]

// ---- tf32 mma helper (raw fp32 bits as tf32 operands) ---------------------
__device__ __forceinline__ void mma_tf32(float c[4], const uint32_t a[4],
                                         uint32_t b0, uint32_t b1) {
    asm("mma.sync.aligned.m16n8k8.row.col.f32.tf32.tf32.f32 "
        "{%0,%1,%2,%3},{%4,%5,%6,%7},{%8,%9},{%0,%1,%2,%3};"
        : "+f"(c[0]), "+f"(c[1]), "+f"(c[2]), "+f"(c[3])
        : "r"(a[0]), "r"(a[1]), "r"(a[2]), "r"(a[3]), "r"(b0), "r"(b1));
}
__device__ __forceinline__ uint32_t fbits(float f) { return __float_as_uint(f); }

// ---- cp.async helpers -----------------------------------------------------
__device__ __forceinline__ void cp16(uint32_t saddr, const void* gptr) {
    asm volatile("cp.async.cg.shared.global [%0], [%1], 16;\n"
                 :: "r"(saddr), "l"(gptr));
}
__device__ __forceinline__ void cp4z(uint32_t saddr, const void* gptr, int srcsz) {
    // 4-byte cp.async; srcsz=0 -> zero-fill (predicated load)
    asm volatile("cp.async.ca.shared.global [%0], [%1], 4, %2;\n"
                 :: "r"(saddr), "l"(gptr), "r"(srcsz));
}
__device__ __forceinline__ void cp_commit() {
    asm volatile("cp.async.commit_group;\n");
}

// ---------------------------------------------------------------------------
// Kernel 0: transpose W_out [c][ci*9+kw] -> g_wt[(kw*256+ci)][c]
// ---------------------------------------------------------------------------
__global__ void wt_kernel(const float* __restrict__ W) {
    int idx = blockIdx.x * 256 + threadIdx.x;
    if (idx < 2304 * 64) {
        int c  = idx & 63;
        int kp = idx >> 6;
        int kw = kp >> 8;
        int ci = kp & 255;
        g_wt[idx] = W[c * 2304 + ci * 9 + kw];
    }
}

// ---------------------------------------------------------------------------
// Kernel 1: QKV projection with tf32 MMA (proven R4 version).
// ---------------------------------------------------------------------------
__global__ void qkv_kernel(const float* __restrict__ x,
                           const float* __restrict__ Wq,
                           const float* __restrict__ bq) {
    __shared__ float Xs[64 * 68];   // [c][l_local]
    __shared__ float Ws[64 * 68];   // [c][j_local]
    const int bx = blockIdx.x;
    const int by = blockIdx.y;
    const int tid = threadIdx.x;
    const int warp = tid >> 5, lane = tid & 31;
    const int wr = warp >> 1, wc = warp & 1;
    const int r0 = wr * 16, c0 = wc * 32;
    const int grp = lane >> 2, qd = lane & 3;

    const int row_base = by * 64;
    const int n  = row_base / LL;
    const int l0 = row_base % LL;

    const float* xb = x + (size_t)n * CC * LL + l0;
#pragma unroll
    for (int it = 0; it < 16; it++) {
        int idx = tid + it * 256;
        int c = idx >> 6, ll = idx & 63;
        Xs[c * 68 + ll] = xb[c * LL + ll];
    }
    const float* wb = Wq + bx * 64;
#pragma unroll
    for (int it = 0; it < 16; it++) {
        int idx = tid + it * 256;
        int c = idx >> 6, j = idx & 63;
        Ws[c * 68 + j] = wb[c * 768 + j];
    }
    __syncthreads();

    float acc[4][4] = {};
#pragma unroll
    for (int ks = 0; ks < 8; ks++) {
        int k = ks * 8;
        uint32_t a[4];
        a[0] = fbits(Xs[(k + qd)     * 68 + r0 + grp]);
        a[1] = fbits(Xs[(k + qd)     * 68 + r0 + grp + 8]);
        a[2] = fbits(Xs[(k + qd + 4) * 68 + r0 + grp]);
        a[3] = fbits(Xs[(k + qd + 4) * 68 + r0 + grp + 8]);
#pragma unroll
        for (int ns = 0; ns < 4; ns++) {
            int nn = c0 + ns * 8 + grp;
            uint32_t b0 = fbits(Ws[(k + qd)     * 68 + nn]);
            uint32_t b1 = fbits(Ws[(k + qd + 4) * 68 + nn]);
            mma_tf32(acc[ns], a, b0, b1);
        }
    }

    const int part = bx >> 2;
    const int h    = bx & 3;
    float* outp = (part == 0) ? g_q : (part == 1) ? g_k : g_v;
    const int lA = l0 + r0 + grp;
    const int lB = lA + 8;
    float* baseA = outp + ((size_t)(n * HH + h) * LL + lA) * DD;
    float* baseB = outp + ((size_t)(n * HH + h) * LL + lB) * DD;
#pragma unroll
    for (int ns = 0; ns < 4; ns++) {
        int d = c0 + ns * 8 + qd * 2;
        float bb0 = bq[bx * 64 + d];
        float bb1 = bq[bx * 64 + d + 1];
        *(float2*)&baseA[d] = make_float2(acc[ns][0] + bb0, acc[ns][1] + bb1);
        *(float2*)&baseB[d] = make_float2(acc[ns][2] + bb0, acc[ns][3] + bb1);
    }
}

// ---------------------------------------------------------------------------
// Kernel 2: flash attention v3 (proven R6): 128-row q-blocks, no-max softmax,
// cp.async double-buffered K/V.
// ---------------------------------------------------------------------------
#define KPAD 68
#define VPAD 72
#define PPAD 68
#define OPAD 132
extern __shared__ float attn_sm[];
__global__ void attn_kernel() {
    float* Kb = attn_sm;              // [2][64*KPAD]
    float* Vb = Kb + 2 * 64 * KPAD;   // [2][64*VPAD]
    float* Ps = Vb + 2 * 64 * VPAD;   // [8][16*PPAD] per-warp P/Q staging

    const int qb  = blockIdx.x;
    const int nh  = blockIdx.y;
    const int tid = threadIdx.x;
    const int warp = tid >> 5, lane = tid & 31;
    const int grp = lane >> 2, qd = lane & 3;
    float* Pw = Ps + warp * 16 * PPAD;

    int qrow = qb * 128 + warp * 16;
    const bool store_ok = (qrow < LL);
    if (!store_ok) qrow -= 64;

    const float* qp  = g_q + ((size_t)nh * LL + qrow) * DD;
    const float* kp0 = g_k + (size_t)nh * LL * DD;
    const float* vp0 = g_v + (size_t)nh * LL * DD;

#pragma unroll
    for (int it = 0; it < 8; it++) {
        int idx4 = lane + it * 32;
        int r = idx4 >> 4, d0 = (idx4 & 15) * 4;
        float4 f = *(const float4*)&qp[r * DD + d0];
        Pw[r * PPAD + d0 + 0] = f.x * 0.125f;
        Pw[r * PPAD + d0 + 1] = f.y * 0.125f;
        Pw[r * PPAD + d0 + 2] = f.z * 0.125f;
        Pw[r * PPAD + d0 + 3] = f.w * 0.125f;
    }
    __syncwarp();
    uint32_t qfrag[8][4];
#pragma unroll
    for (int ks = 0; ks < 8; ks++) {
        int k = ks * 8;
        qfrag[ks][0] = fbits(Pw[(grp)     * PPAD + k + qd]);
        qfrag[ks][1] = fbits(Pw[(grp + 8) * PPAD + k + qd]);
        qfrag[ks][2] = fbits(Pw[(grp)     * PPAD + k + qd + 4]);
        qfrag[ks][3] = fbits(Pw[(grp + 8) * PPAD + k + qd + 4]);
    }

    {
        uint32_t ka = (uint32_t)__cvta_generic_to_shared(Kb);
        uint32_t va = (uint32_t)__cvta_generic_to_shared(Vb);
#pragma unroll
        for (int it = 0; it < 4; it++) {
            int idx4 = tid + it * 256;
            int r = idx4 >> 4, d0 = (idx4 & 15) * 4;
            cp16(ka + (r * KPAD + d0) * 4, kp0 + r * DD + d0);
            cp16(va + (r * VPAD + d0) * 4, vp0 + r * DD + d0);
        }
        cp_commit();
    }

    float oacc[8][4] = {};
    float l0 = 0.f, l1 = 0.f;

    for (int kb = 0; kb < 25; kb++) {
        const int cur = kb & 1;
        __syncthreads();
        if (kb < 24) {
            const int nxt = (kb + 1) & 1;
            const float* kp = kp0 + (size_t)(kb + 1) * 64 * DD;
            const float* vp = vp0 + (size_t)(kb + 1) * 64 * DD;
            uint32_t ka = (uint32_t)__cvta_generic_to_shared(Kb + nxt * 64 * KPAD);
            uint32_t va = (uint32_t)__cvta_generic_to_shared(Vb + nxt * 64 * VPAD);
#pragma unroll
            for (int it = 0; it < 4; it++) {
                int idx4 = tid + it * 256;
                int r = idx4 >> 4, d0 = (idx4 & 15) * 4;
                cp16(ka + (r * KPAD + d0) * 4, kp + r * DD + d0);
                cp16(va + (r * VPAD + d0) * 4, vp + r * DD + d0);
            }
            cp_commit();
            asm volatile("cp.async.wait_group 1;\n");
        } else {
            asm volatile("cp.async.wait_group 0;\n");
        }
        __syncthreads();

        const float* Kc = Kb + cur * 64 * KPAD;
        const float* Vc = Vb + cur * 64 * VPAD;

        float sacc[8][4] = {};
#pragma unroll
        for (int ks = 0; ks < 8; ks++) {
            int k = ks * 8;
#pragma unroll
            for (int ns = 0; ns < 8; ns++) {
                uint32_t b0 = fbits(Kc[(ns * 8 + grp) * KPAD + k + qd]);
                uint32_t b1 = fbits(Kc[(ns * 8 + grp) * KPAD + k + qd + 4]);
                mma_tf32(sacc[ns], qfrag[ks], b0, b1);
            }
        }

#pragma unroll
        for (int ns = 0; ns < 8; ns++) {
            float p0 = __expf(sacc[ns][0] - 8.f);
            float p1 = __expf(sacc[ns][1] - 8.f);
            float p2 = __expf(sacc[ns][2] - 8.f);
            float p3 = __expf(sacc[ns][3] - 8.f);
            sacc[ns][0] = p0; sacc[ns][1] = p1;
            sacc[ns][2] = p2; sacc[ns][3] = p3;
            l0 += p0 + p1;
            l1 += p2 + p3;
        }

#pragma unroll
        for (int ns = 0; ns < 8; ns++) {
            int c = ns * 8 + qd * 2;
            *(float2*)&Pw[(grp)     * PPAD + c] = make_float2(sacc[ns][0], sacc[ns][1]);
            *(float2*)&Pw[(grp + 8) * PPAD + c] = make_float2(sacc[ns][2], sacc[ns][3]);
        }
        __syncwarp();

#pragma unroll
        for (int ks = 0; ks < 8; ks++) {
            int k = ks * 8;
            uint32_t a[4];
            a[0] = fbits(Pw[(grp)     * PPAD + k + qd]);
            a[1] = fbits(Pw[(grp + 8) * PPAD + k + qd]);
            a[2] = fbits(Pw[(grp)     * PPAD + k + qd + 4]);
            a[3] = fbits(Pw[(grp + 8) * PPAD + k + qd + 4]);
#pragma unroll
            for (int ns = 0; ns < 8; ns++) {
                int d0 = ns * 8;
                uint32_t b0 = fbits(Vc[(k + qd)     * VPAD + d0 + grp]);
                uint32_t b1 = fbits(Vc[(k + qd + 4) * VPAD + d0 + grp]);
                mma_tf32(oacc[ns], a, b0, b1);
            }
        }
        __syncwarp();
    }

    l0 += __shfl_xor_sync(0xFFFFFFFFu, l0, 1);
    l0 += __shfl_xor_sync(0xFFFFFFFFu, l0, 2);
    l1 += __shfl_xor_sync(0xFFFFFFFFu, l1, 1);
    l1 += __shfl_xor_sync(0xFFFFFFFFu, l1, 2);

    __syncthreads();
    float* Ot = Kb;   // [64 d][OPAD l_local]
    if (store_ok) {
        float linv0 = 1.f / l0;
        float linv1 = 1.f / l1;
        int lA = warp * 16 + grp;
#pragma unroll
        for (int ns = 0; ns < 8; ns++) {
            int d = ns * 8 + qd * 2;
            Ot[(d)     * OPAD + lA]     = oacc[ns][0] * linv0;
            Ot[(d + 1) * OPAD + lA]     = oacc[ns][1] * linv0;
            Ot[(d)     * OPAD + lA + 8] = oacc[ns][2] * linv1;
            Ot[(d + 1) * OPAD + lA + 8] = oacc[ns][3] * linv1;
        }
    }
    __syncthreads();

    const int n = nh >> 2, h = nh & 3;
    const int Lrem = min(128, LL - qb * 128);
    float* ob = g_o + ((size_t)n * HD + h * DD) * LL + qb * 128;
#pragma unroll
    for (int it = 0; it < 32; it++) {
        int idx = tid + it * 256;
        int d = idx >> 7, ll = idx & 127;
        if (ll < Lrem)
            ob[(size_t)d * LL + ll] = Ot[d * OPAD + ll];
    }
}

// ---------------------------------------------------------------------------
// Kernel 3: (1,9) conv (256->64) + BN1 + res + relu  FUSED WITH
//           1x1 conv (64->64) + BN2 + res + relu -> out
// 128-spatial tile, 8 warps (warp = 16ch x 64sp), cp.async double-buffered,
// k' = kw*256+ci ordering (kw constant per 32-chunk).
// ---------------------------------------------------------------------------
#define CAP 68
#define CBP 132
extern __shared__ float conv_sm[];
__global__ void conv_kernel(const float* __restrict__ x,
                            const float* __restrict__ bias,
                            const float* __restrict__ g1,
                            const float* __restrict__ be1,
                            const float* __restrict__ mu1,
                            const float* __restrict__ va1,
                            const float* __restrict__ Wff,
                            const float* __restrict__ bff,
                            const float* __restrict__ g2,
                            const float* __restrict__ be2,
                            const float* __restrict__ mu2,
                            const float* __restrict__ va2,
                            float* __restrict__ out) {
    float* As = conv_sm;                 // [2][32*CAP]
    float* Bs = conv_sm + 2 * 32 * CAP;  // [2][32*CBP]
    float* Ys = conv_sm;                 // epi: [64][CBP] (reuse)
    float* Wf = conv_sm + 64 * CBP;      // epi: [64][CAP]

    const int tid = threadIdx.x;
    const int warp = tid >> 5, lane = tid & 31;
    const int grp = lane >> 2, qd = lane & 3;
    const int wr = warp & 3, wc = warp >> 2;
    const int r0 = wr * 16, c0 = wc * 64;
    const int sbase = blockIdx.x * 128;

    // ---- per-thread B geometry (one spatial column, 16 ci-rows) ----
    const int sl   = tid & 127;
    const int half = tid >> 7;           // rows [half*16, half*16+16)
    const int s    = sbase + sl;
    const int n    = s / LL;
    const int rem  = s - n * LL;
    const int tt   = rem / VV;
    const int v    = rem - tt * VV;
    const float* pb = g_o + ((size_t)n * HD + half * 16) * LL + rem - 4;

    // ---- per-thread A geometry ----
    const int akl = tid >> 3;            // 0..31
    const int ac0 = (tid & 7) * 8;

    auto prefetch = [&](int kb, int buf) {
        const int kw = kb >> 3;
        const int cibase = (kb & 7) * 32;
        uint32_t ab = (uint32_t)__cvta_generic_to_shared(As + buf * 32 * CAP);
        uint32_t bb = (uint32_t)__cvta_generic_to_shared(Bs + buf * 32 * CBP);
        const float* ap = g_wt + (size_t)kb * 2048;
        cp16(ab + (akl * CAP + ac0) * 4,     ap + akl * 64 + ac0);
        cp16(ab + (akl * CAP + ac0 + 4) * 4, ap + akl * 64 + ac0 + 4);
        const int vi = v + kw - 4;
        const int oksz = (vi >= 0 && vi < VV) ? 4 : 0;
        const float* bp = pb + (size_t)cibase * LL + kw;
#pragma unroll
        for (int r = 0; r < 16; r++)
            cp4z(bb + ((half * 16 + r) * CBP + sl) * 4, bp + (size_t)r * LL, oksz);
        cp_commit();
    };

    prefetch(0, 0);
    float acc[8][4] = {};

    for (int kb = 0; kb < 72; kb++) {
        const int cur = kb & 1;
        __syncthreads();
        if (kb < 71) {
            prefetch(kb + 1, cur ^ 1);
            asm volatile("cp.async.wait_group 1;\n");
        } else {
            asm volatile("cp.async.wait_group 0;\n");
        }
        __syncthreads();

        const float* Ac = As + cur * 32 * CAP;
        const float* Bc = Bs + cur * 32 * CBP;
#pragma unroll
        for (int ks = 0; ks < 4; ks++) {
            int k = ks * 8;
            uint32_t a[4];
            a[0] = fbits(Ac[(k + qd)     * CAP + r0 + grp]);
            a[1] = fbits(Ac[(k + qd)     * CAP + r0 + grp + 8]);
            a[2] = fbits(Ac[(k + qd + 4) * CAP + r0 + grp]);
            a[3] = fbits(Ac[(k + qd + 4) * CAP + r0 + grp + 8]);
#pragma unroll
            for (int ns = 0; ns < 8; ns++) {
                int nn = c0 + ns * 8 + grp;
                uint32_t b0 = fbits(Bc[(k + qd)     * CBP + nn]);
                uint32_t b1 = fbits(Bc[(k + qd + 4) * CBP + nn]);
                mma_tf32(acc[ns], a, b0, b1);
            }
        }
    }
    __syncthreads();   // done reading As/Bs; smem will be reused as Ys/Wf

    // ---- epilogue 1: y = relu(bn1(conv + bias) + x), staged into Ys ----
    const int cA = r0 + grp, cB = cA + 8;
    {
        float invA = g1[cA] * rsqrtf(va1[cA] + 1e-5f);
        float addA = be1[cA] - mu1[cA] * invA + bias[cA] * invA;
        float invB = g1[cB] * rsqrtf(va1[cB] + 1e-5f);
        float addB = be1[cB] - mu1[cB] * invB + bias[cB] * invB;
#pragma unroll
        for (int ns = 0; ns < 8; ns++) {
            int col = c0 + ns * 8 + qd * 2;
            int ss = sbase + col;
            int n2 = ss / LL;
            int rem2 = ss - n2 * LL;
            float2 xA = *(const float2*)&x[((size_t)(n2 * CC + cA)) * LL + rem2];
            float2 xB = *(const float2*)&x[((size_t)(n2 * CC + cB)) * LL + rem2];
            float y0 = fmaxf(acc[ns][0] * invA + addA + xA.x, 0.f);
            float y1 = fmaxf(acc[ns][1] * invA + addA + xA.y, 0.f);
            float y2 = fmaxf(acc[ns][2] * invB + addB + xB.x, 0.f);
            float y3 = fmaxf(acc[ns][3] * invB + addB + xB.y, 0.f);
            *(float2*)&Ys[cA * CBP + col] = make_float2(y0, y1);
            *(float2*)&Ys[cB * CBP + col] = make_float2(y2, y3);
        }
    }
    // stage Wff transposed: Wf[ci][c]
#pragma unroll
    for (int it = 0; it < 16; it++) {
        int idx = tid + it * 256;
        int ci = idx & 63, cc = idx >> 6;
        Wf[ci * CAP + cc] = Wff[cc * 64 + ci];
    }
    __syncthreads();

    // ---- ff GEMM: z[c][s] = sum_ci Wff[c][ci] * y[ci][s] ----
    float fac[8][4] = {};
#pragma unroll
    for (int ks = 0; ks < 8; ks++) {
        int k = ks * 8;
        uint32_t a[4];
        a[0] = fbits(Wf[(k + qd)     * CAP + r0 + grp]);
        a[1] = fbits(Wf[(k + qd)     * CAP + r0 + grp + 8]);
        a[2] = fbits(Wf[(k + qd + 4) * CAP + r0 + grp]);
        a[3] = fbits(Wf[(k + qd + 4) * CAP + r0 + grp + 8]);
#pragma unroll
        for (int ns = 0; ns < 8; ns++) {
            int nn = c0 + ns * 8 + grp;
            uint32_t b0 = fbits(Ys[(k + qd)     * CBP + nn]);
            uint32_t b1 = fbits(Ys[(k + qd + 4) * CBP + nn]);
            mma_tf32(fac[ns], a, b0, b1);
        }
    }

    // ---- epilogue 2: out = relu(bn2(z + bff) + y) ----
    {
        float invA = g2[cA] * rsqrtf(va2[cA] + 1e-5f);
        float addA = be2[cA] - mu2[cA] * invA + bff[cA] * invA;
        float invB = g2[cB] * rsqrtf(va2[cB] + 1e-5f);
        float addB = be2[cB] - mu2[cB] * invB + bff[cB] * invB;
#pragma unroll
        for (int ns = 0; ns < 8; ns++) {
            int col = c0 + ns * 8 + qd * 2;
            int ss = sbase + col;
            int n2 = ss / LL;
            int rem2 = ss - n2 * LL;
            float2 yA = *(const float2*)&Ys[cA * CBP + col];
            float2 yB = *(const float2*)&Ys[cB * CBP + col];
            float z0 = fmaxf(fac[ns][0] * invA + addA + yA.x, 0.f);
            float z1 = fmaxf(fac[ns][1] * invA + addA + yA.y, 0.f);
            float z2 = fmaxf(fac[ns][2] * invB + addB + yB.x, 0.f);
            float z3 = fmaxf(fac[ns][3] * invB + addB + yB.y, 0.f);
            *(float2*)&out[((size_t)(n2 * CC + cA)) * LL + rem2] = make_float2(z0, z1);
            *(float2*)&out[((size_t)(n2 * CC + cB)) * LL + rem2] = make_float2(z2, z3);
        }
    }
}

// ---------------------------------------------------------------------------
extern "C" void kernel_launch(void* const* d_in, const int* in_sizes, int n_in,
                              void* d_out, int out_size) {
    const float* x     = (const float*)d_in[0];
    const float* W_qkv = (const float*)d_in[1];
    const float* b_qkv = (const float*)d_in[2];
    const float* W_out = (const float*)d_in[3];
    const float* b_out = (const float*)d_in[4];
    const float* g1    = (const float*)d_in[5];
    const float* be1   = (const float*)d_in[6];
    const float* mu1   = (const float*)d_in[7];
    const float* va1   = (const float*)d_in[8];
    const float* W_ff  = (const float*)d_in[9];
    const float* b_ff  = (const float*)d_in[10];
    const float* g2    = (const float*)d_in[11];
    const float* be2   = (const float*)d_in[12];
    const float* mu2   = (const float*)d_in[13];
    const float* va2   = (const float*)d_in[14];
    float* out = (float*)d_out;

    const int ATTN_SMEM = (2*64*KPAD + 2*64*VPAD + 8*16*PPAD) * (int)sizeof(float);
    cudaFuncSetAttribute(attn_kernel,
                         cudaFuncAttributeMaxDynamicSharedMemorySize, ATTN_SMEM);
    const int CONV_SMEM = (2*32*CAP + 2*32*CBP) * (int)sizeof(float);  // 51200
    cudaFuncSetAttribute(conv_kernel,
                         cudaFuncAttributeMaxDynamicSharedMemorySize, CONV_SMEM);

    wt_kernel<<<576, 256>>>(W_out);
    qkv_kernel<<<dim3(12, 400), 256>>>(x, W_qkv, b_qkv);
    attn_kernel<<<dim3(13, 64), 256, ATTN_SMEM>>>();
    conv_kernel<<<200, 256, CONV_SMEM>>>(x, b_out, g1, be1, mu1, va1,
                                         W_ff, b_ff, g2, be2, mu2, va2, out);
}

// round 8
// speedup vs baseline: 1.0183x; 1.0183x over previous
#include <cuda_runtime.h>
#include <math.h>
#include <stdint.h>

// Problem constants
#define NB 16      // batch
#define CC 64      // channels
#define TT 64      // time
#define VV 25      // vertices
#define HH 4       // heads
#define DD 64      // head dim
#define LL (TT*VV) // 1600 tokens
#define HD (HH*DD) // 256

// Scratch (device globals; no runtime allocation allowed)
__device__ float g_q[NB*HH*LL*DD];
__device__ float g_k[NB*HH*LL*DD];
__device__ float g_v[NB*HH*LL*DD];
__device__ float g_o[NB*HD*LL];    // attention out in [N, H*D, T, V] layout
__device__ float g_y[NB*CC*LL];    // after out_nets
__device__ float g_wt[2304*64];    // W_out transposed to [k'=kw*256+ci][c]

// ---- tf32 mma helper (raw fp32 bits as tf32 operands) ---------------------
__device__ __forceinline__ void mma_tf32(float c[4], const uint32_t a[4],
                                         uint32_t b0, uint32_t b1) {
    asm("mma.sync.aligned.m16n8k8.row.col.f32.tf32.tf32.f32 "
        "{%0,%1,%2,%3},{%4,%5,%6,%7},{%8,%9},{%0,%1,%2,%3};"
        : "+f"(c[0]), "+f"(c[1]), "+f"(c[2]), "+f"(c[3])
        : "r"(a[0]), "r"(a[1]), "r"(a[2]), "r"(a[3]), "r"(b0), "r"(b1));
}
__device__ __forceinline__ uint32_t fbits(float f) { return __float_as_uint(f); }

// ---- cp.async helpers -----------------------------------------------------
__device__ __forceinline__ void cp16(uint32_t saddr, const void* gptr) {
    asm volatile("cp.async.cg.shared.global [%0], [%1], 16;\n"
                 :: "r"(saddr), "l"(gptr));
}
__device__ __forceinline__ void cp4z(uint32_t saddr, const void* gptr, int srcsz) {
    asm volatile("cp.async.ca.shared.global [%0], [%1], 4, %2;\n"
                 :: "r"(saddr), "l"(gptr), "r"(srcsz));
}
__device__ __forceinline__ void cp_commit() {
    asm volatile("cp.async.commit_group;\n");
}

// ---------------------------------------------------------------------------
// Kernel 0: transpose W_out [c][ci*9+kw] -> g_wt[(kw*256+ci)][c]
// ---------------------------------------------------------------------------
__global__ void wt_kernel(const float* __restrict__ W) {
    int idx = blockIdx.x * 256 + threadIdx.x;
    if (idx < 2304 * 64) {
        int c  = idx & 63;
        int kp = idx >> 6;
        int kw = kp >> 8;
        int ci = kp & 255;
        g_wt[idx] = W[c * 2304 + ci * 9 + kw];
    }
}

// ---------------------------------------------------------------------------
// Kernel 1: QKV projection with tf32 MMA (proven).
// ---------------------------------------------------------------------------
__global__ void qkv_kernel(const float* __restrict__ x,
                           const float* __restrict__ Wq,
                           const float* __restrict__ bq) {
    __shared__ float Xs[64 * 68];   // [c][l_local]
    __shared__ float Ws[64 * 68];   // [c][j_local]
    const int bx = blockIdx.x;
    const int by = blockIdx.y;
    const int tid = threadIdx.x;
    const int warp = tid >> 5, lane = tid & 31;
    const int wr = warp >> 1, wc = warp & 1;
    const int r0 = wr * 16, c0 = wc * 32;
    const int grp = lane >> 2, qd = lane & 3;

    const int row_base = by * 64;
    const int n  = row_base / LL;
    const int l0 = row_base % LL;

    const float* xb = x + (size_t)n * CC * LL + l0;
#pragma unroll
    for (int it = 0; it < 16; it++) {
        int idx = tid + it * 256;
        int c = idx >> 6, ll = idx & 63;
        Xs[c * 68 + ll] = xb[c * LL + ll];
    }
    const float* wb = Wq + bx * 64;
#pragma unroll
    for (int it = 0; it < 16; it++) {
        int idx = tid + it * 256;
        int c = idx >> 6, j = idx & 63;
        Ws[c * 68 + j] = wb[c * 768 + j];
    }
    __syncthreads();

    float acc[4][4] = {};
#pragma unroll
    for (int ks = 0; ks < 8; ks++) {
        int k = ks * 8;
        uint32_t a[4];
        a[0] = fbits(Xs[(k + qd)     * 68 + r0 + grp]);
        a[1] = fbits(Xs[(k + qd)     * 68 + r0 + grp + 8]);
        a[2] = fbits(Xs[(k + qd + 4) * 68 + r0 + grp]);
        a[3] = fbits(Xs[(k + qd + 4) * 68 + r0 + grp + 8]);
#pragma unroll
        for (int ns = 0; ns < 4; ns++) {
            int nn = c0 + ns * 8 + grp;
            uint32_t b0 = fbits(Ws[(k + qd)     * 68 + nn]);
            uint32_t b1 = fbits(Ws[(k + qd + 4) * 68 + nn]);
            mma_tf32(acc[ns], a, b0, b1);
        }
    }

    const int part = bx >> 2;
    const int h    = bx & 3;
    float* outp = (part == 0) ? g_q : (part == 1) ? g_k : g_v;
    const int lA = l0 + r0 + grp;
    const int lB = lA + 8;
    float* baseA = outp + ((size_t)(n * HH + h) * LL + lA) * DD;
    float* baseB = outp + ((size_t)(n * HH + h) * LL + lB) * DD;
#pragma unroll
    for (int ns = 0; ns < 4; ns++) {
        int d = c0 + ns * 8 + qd * 2;
        float bb0 = bq[bx * 64 + d];
        float bb1 = bq[bx * 64 + d + 1];
        *(float2*)&baseA[d] = make_float2(acc[ns][0] + bb0, acc[ns][1] + bb1);
        *(float2*)&baseB[d] = make_float2(acc[ns][2] + bb0, acc[ns][3] + bb1);
    }
}

// ---------------------------------------------------------------------------
// Kernel 2: flash attention (proven R6): 128-row q-blocks, no-max softmax,
// cp.async double-buffered K/V.
// ---------------------------------------------------------------------------
#define KPAD 68
#define VPAD 72
#define PPAD 68
#define OPAD 132
extern __shared__ float attn_sm[];
__global__ void attn_kernel() {
    float* Kb = attn_sm;              // [2][64*KPAD]
    float* Vb = Kb + 2 * 64 * KPAD;   // [2][64*VPAD]
    float* Ps = Vb + 2 * 64 * VPAD;   // [8][16*PPAD] per-warp P/Q staging

    const int qb  = blockIdx.x;
    const int nh  = blockIdx.y;
    const int tid = threadIdx.x;
    const int warp = tid >> 5, lane = tid & 31;
    const int grp = lane >> 2, qd = lane & 3;
    float* Pw = Ps + warp * 16 * PPAD;

    int qrow = qb * 128 + warp * 16;
    const bool store_ok = (qrow < LL);
    if (!store_ok) qrow -= 64;

    const float* qp  = g_q + ((size_t)nh * LL + qrow) * DD;
    const float* kp0 = g_k + (size_t)nh * LL * DD;
    const float* vp0 = g_v + (size_t)nh * LL * DD;

#pragma unroll
    for (int it = 0; it < 8; it++) {
        int idx4 = lane + it * 32;
        int r = idx4 >> 4, d0 = (idx4 & 15) * 4;
        float4 f = *(const float4*)&qp[r * DD + d0];
        Pw[r * PPAD + d0 + 0] = f.x * 0.125f;
        Pw[r * PPAD + d0 + 1] = f.y * 0.125f;
        Pw[r * PPAD + d0 + 2] = f.z * 0.125f;
        Pw[r * PPAD + d0 + 3] = f.w * 0.125f;
    }
    __syncwarp();
    uint32_t qfrag[8][4];
#pragma unroll
    for (int ks = 0; ks < 8; ks++) {
        int k = ks * 8;
        qfrag[ks][0] = fbits(Pw[(grp)     * PPAD + k + qd]);
        qfrag[ks][1] = fbits(Pw[(grp + 8) * PPAD + k + qd]);
        qfrag[ks][2] = fbits(Pw[(grp)     * PPAD + k + qd + 4]);
        qfrag[ks][3] = fbits(Pw[(grp + 8) * PPAD + k + qd + 4]);
    }

    {
        uint32_t ka = (uint32_t)__cvta_generic_to_shared(Kb);
        uint32_t va = (uint32_t)__cvta_generic_to_shared(Vb);
#pragma unroll
        for (int it = 0; it < 4; it++) {
            int idx4 = tid + it * 256;
            int r = idx4 >> 4, d0 = (idx4 & 15) * 4;
            cp16(ka + (r * KPAD + d0) * 4, kp0 + r * DD + d0);
            cp16(va + (r * VPAD + d0) * 4, vp0 + r * DD + d0);
        }
        cp_commit();
    }

    float oacc[8][4] = {};
    float l0 = 0.f, l1 = 0.f;

    for (int kb = 0; kb < 25; kb++) {
        const int cur = kb & 1;
        __syncthreads();
        if (kb < 24) {
            const int nxt = (kb + 1) & 1;
            const float* kp = kp0 + (size_t)(kb + 1) * 64 * DD;
            const float* vp = vp0 + (size_t)(kb + 1) * 64 * DD;
            uint32_t ka = (uint32_t)__cvta_generic_to_shared(Kb + nxt * 64 * KPAD);
            uint32_t va = (uint32_t)__cvta_generic_to_shared(Vb + nxt * 64 * VPAD);
#pragma unroll
            for (int it = 0; it < 4; it++) {
                int idx4 = tid + it * 256;
                int r = idx4 >> 4, d0 = (idx4 & 15) * 4;
                cp16(ka + (r * KPAD + d0) * 4, kp + r * DD + d0);
                cp16(va + (r * VPAD + d0) * 4, vp + r * DD + d0);
            }
            cp_commit();
            asm volatile("cp.async.wait_group 1;\n");
        } else {
            asm volatile("cp.async.wait_group 0;\n");
        }
        __syncthreads();

        const float* Kc = Kb + cur * 64 * KPAD;
        const float* Vc = Vb + cur * 64 * VPAD;

        float sacc[8][4] = {};
#pragma unroll
        for (int ks = 0; ks < 8; ks++) {
            int k = ks * 8;
#pragma unroll
            for (int ns = 0; ns < 8; ns++) {
                uint32_t b0 = fbits(Kc[(ns * 8 + grp) * KPAD + k + qd]);
                uint32_t b1 = fbits(Kc[(ns * 8 + grp) * KPAD + k + qd + 4]);
                mma_tf32(sacc[ns], qfrag[ks], b0, b1);
            }
        }

#pragma unroll
        for (int ns = 0; ns < 8; ns++) {
            float p0 = __expf(sacc[ns][0] - 8.f);
            float p1 = __expf(sacc[ns][1] - 8.f);
            float p2 = __expf(sacc[ns][2] - 8.f);
            float p3 = __expf(sacc[ns][3] - 8.f);
            sacc[ns][0] = p0; sacc[ns][1] = p1;
            sacc[ns][2] = p2; sacc[ns][3] = p3;
            l0 += p0 + p1;
            l1 += p2 + p3;
        }

#pragma unroll
        for (int ns = 0; ns < 8; ns++) {
            int c = ns * 8 + qd * 2;
            *(float2*)&Pw[(grp)     * PPAD + c] = make_float2(sacc[ns][0], sacc[ns][1]);
            *(float2*)&Pw[(grp + 8) * PPAD + c] = make_float2(sacc[ns][2], sacc[ns][3]);
        }
        __syncwarp();

#pragma unroll
        for (int ks = 0; ks < 8; ks++) {
            int k = ks * 8;
            uint32_t a[4];
            a[0] = fbits(Pw[(grp)     * PPAD + k + qd]);
            a[1] = fbits(Pw[(grp + 8) * PPAD + k + qd]);
            a[2] = fbits(Pw[(grp)     * PPAD + k + qd + 4]);
            a[3] = fbits(Pw[(grp + 8) * PPAD + k + qd + 4]);
#pragma unroll
            for (int ns = 0; ns < 8; ns++) {
                int d0 = ns * 8;
                uint32_t b0 = fbits(Vc[(k + qd)     * VPAD + d0 + grp]);
                uint32_t b1 = fbits(Vc[(k + qd + 4) * VPAD + d0 + grp]);
                mma_tf32(oacc[ns], a, b0, b1);
            }
        }
        __syncwarp();
    }

    l0 += __shfl_xor_sync(0xFFFFFFFFu, l0, 1);
    l0 += __shfl_xor_sync(0xFFFFFFFFu, l0, 2);
    l1 += __shfl_xor_sync(0xFFFFFFFFu, l1, 1);
    l1 += __shfl_xor_sync(0xFFFFFFFFu, l1, 2);

    __syncthreads();
    float* Ot = Kb;   // [64 d][OPAD l_local]
    if (store_ok) {
        float linv0 = 1.f / l0;
        float linv1 = 1.f / l1;
        int lA = warp * 16 + grp;
#pragma unroll
        for (int ns = 0; ns < 8; ns++) {
            int d = ns * 8 + qd * 2;
            Ot[(d)     * OPAD + lA]     = oacc[ns][0] * linv0;
            Ot[(d + 1) * OPAD + lA]     = oacc[ns][1] * linv0;
            Ot[(d)     * OPAD + lA + 8] = oacc[ns][2] * linv1;
            Ot[(d + 1) * OPAD + lA + 8] = oacc[ns][3] * linv1;
        }
    }
    __syncthreads();

    const int n = nh >> 2, h = nh & 3;
    const int Lrem = min(128, LL - qb * 128);
    float* ob = g_o + ((size_t)n * HD + h * DD) * LL + qb * 128;
#pragma unroll
    for (int it = 0; it < 32; it++) {
        int idx = tid + it * 256;
        int d = idx >> 7, ll = idx & 127;
        if (ll < Lrem)
            ob[(size_t)d * LL + ll] = Ot[d * OPAD + ll];
    }
}

// ---------------------------------------------------------------------------
// Kernel 3: (1,9) conv (256->64) — R6 tiling (400 blocks, 64sp x 64ch,
// k'=kw*256+ci ordering) + cp.async DOUBLE-BUFFERED loads.
// Fused bias+BN1+residual(x)+relu -> g_y.
// ---------------------------------------------------------------------------
#define CAP 68
extern __shared__ float conv_sm[];
__global__ void conv_kernel(const float* __restrict__ x,
                            const float* __restrict__ bias,
                            const float* __restrict__ g1,
                            const float* __restrict__ be1,
                            const float* __restrict__ mu1,
                            const float* __restrict__ va1) {
    float* As = conv_sm;                 // [2][32*CAP]  [kl][out_ch]
    float* Bs = conv_sm + 2 * 32 * CAP;  // [2][32*CAP]  [kl][s_local]

    const int tid = threadIdx.x;
    const int sbase = blockIdx.x * 64;
    const int warp = tid >> 5, lane = tid & 31;
    const int wr = warp >> 1, wc = warp & 1;
    const int r0 = wr * 16, c0 = wc * 32;
    const int grp = lane >> 2, qd = lane & 3;

    // per-thread B geometry (one spatial column, 8 ci-rows strided by 4)
    const int sl = tid & 63;
    const int klrow = tid >> 6;          // 0..3
    const int s = sbase + sl;
    const int n = s / LL;
    const int rem = s - n * LL;
    const int t = rem / VV;
    const int v = rem - t * VV;
    const float* obase = g_o + ((size_t)(n * HD + klrow)) * LL + rem - 4;

    // per-thread A geometry (8 consecutive floats)
    const int akl = tid >> 3;            // 0..31
    const int ac0 = (tid & 7) * 8;

    const uint32_t asm0 = (uint32_t)__cvta_generic_to_shared(As);
    const uint32_t bsm0 = (uint32_t)__cvta_generic_to_shared(Bs);

    auto prefetch = [&](int kb, int buf) {
        const int kw = kb >> 3;
        const int cibase = (kb & 7) * 32;
        const float* ap = g_wt + (size_t)kb * 2048;
        uint32_t ab = asm0 + buf * 32 * CAP * 4;
        uint32_t bb = bsm0 + buf * 32 * CAP * 4;
        cp16(ab + (akl * CAP + ac0) * 4,     ap + akl * 64 + ac0);
        cp16(ab + (akl * CAP + ac0 + 4) * 4, ap + akl * 64 + ac0 + 4);
        const int vi = v + kw - 4;
        const int oksz = (vi >= 0 && vi < VV) ? 4 : 0;
        const float* bp = obase + (size_t)cibase * LL + kw;
#pragma unroll
        for (int r = 0; r < 8; r++) {
            int kl = klrow + r * 4;
            cp4z(bb + (kl * CAP + sl) * 4, bp + (size_t)r * 4 * LL, oksz);
        }
        cp_commit();
    };

    prefetch(0, 0);
    float acc[4][4] = {};

    for (int kb = 0; kb < 72; kb++) {
        const int cur = kb & 1;
        __syncthreads();
        if (kb < 71) {
            prefetch(kb + 1, cur ^ 1);
            asm volatile("cp.async.wait_group 1;\n");
        } else {
            asm volatile("cp.async.wait_group 0;\n");
        }
        __syncthreads();

        const float* Ac = As + cur * 32 * CAP;
        const float* Bc = Bs + cur * 32 * CAP;
#pragma unroll
        for (int ks = 0; ks < 4; ks++) {
            int k = ks * 8;
            uint32_t a[4];
            a[0] = fbits(Ac[(k + qd)     * CAP + r0 + grp]);
            a[1] = fbits(Ac[(k + qd)     * CAP + r0 + grp + 8]);
            a[2] = fbits(Ac[(k + qd + 4) * CAP + r0 + grp]);
            a[3] = fbits(Ac[(k + qd + 4) * CAP + r0 + grp + 8]);
#pragma unroll
            for (int ns = 0; ns < 4; ns++) {
                int nn = c0 + ns * 8 + grp;
                uint32_t b0 = fbits(Bc[(k + qd)     * CAP + nn]);
                uint32_t b1 = fbits(Bc[(k + qd + 4) * CAP + nn]);
                mma_tf32(acc[ns], a, b0, b1);
            }
        }
    }

    // epilogue: bn1(conv + bias) + x, relu
    const int cA = r0 + grp, cB = cA + 8;
    float invA = g1[cA] * rsqrtf(va1[cA] + 1e-5f);
    float addA = be1[cA] - mu1[cA] * invA + bias[cA] * invA;
    float invB = g1[cB] * rsqrtf(va1[cB] + 1e-5f);
    float addB = be1[cB] - mu1[cB] * invB + bias[cB] * invB;
#pragma unroll
    for (int ns = 0; ns < 4; ns++) {
#pragma unroll
        for (int jj = 0; jj < 2; jj++) {
            int ss = sbase + c0 + ns * 8 + qd * 2 + jj;
            int nn2 = ss / LL;
            int rem2 = ss - nn2 * LL;
            size_t aA = ((size_t)(nn2 * CC + cA)) * LL + rem2;
            size_t aB = ((size_t)(nn2 * CC + cB)) * LL + rem2;
            float vA = acc[ns][jj]     * invA + addA + x[aA];
            float vB = acc[ns][jj + 2] * invB + addB + x[aB];
            g_y[aA] = fmaxf(vA, 0.f);
            g_y[aB] = fmaxf(vB, 0.f);
        }
    }
}

// ---------------------------------------------------------------------------
// Kernel 4: 1x1 conv + BN2 + residual + relu (proven scalar; ~13us).
// ---------------------------------------------------------------------------
__global__ void ff_kernel(const float* __restrict__ Wff,
                          const float* __restrict__ bff,
                          const float* __restrict__ g2,
                          const float* __restrict__ be2,
                          const float* __restrict__ mu2,
                          const float* __restrict__ va2,
                          float* __restrict__ out) {
    __shared__ float Ws[64 * 65];
    __shared__ float Ys[64 * 65];
    const int tid = threadIdx.x;
    const int sbase = blockIdx.x * 64;
    const int n  = sbase / LL;
    const int lo = sbase % LL;

#pragma unroll
    for (int it = 0; it < 16; it++) {
        int idx = tid + it * 256;
        int c = idx >> 6, ci = idx & 63;
        Ws[c * 65 + ci] = Wff[c * 64 + ci];
    }
    const float* yb = g_y + (size_t)n * CC * LL + lo;
#pragma unroll
    for (int it = 0; it < 16; it++) {
        int idx = tid + it * 256;
        int ci = idx >> 6, sl = idx & 63;
        Ys[ci * 65 + sl] = yb[ci * LL + sl];
    }
    __syncthreads();

    const int ty = tid >> 4, tx = tid & 15;
    float acc[4][4] = {};
#pragma unroll
    for (int kk = 0; kk < 64; kk++) {
        float a[4], b[4];
#pragma unroll
        for (int i = 0; i < 4; i++) a[i] = Ws[(ty * 4 + i) * 65 + kk];
#pragma unroll
        for (int j = 0; j < 4; j++) b[j] = Ys[kk * 65 + tx * 4 + j];
#pragma unroll
        for (int i = 0; i < 4; i++)
#pragma unroll
            for (int j = 0; j < 4; j++) acc[i][j] = fmaf(a[i], b[j], acc[i][j]);
    }

#pragma unroll
    for (int i = 0; i < 4; i++) {
        int c = ty * 4 + i;
        float inv = g2[c] * rsqrtf(va2[c] + 1e-5f);
        float add = be2[c] - mu2[c] * inv + bff[c] * inv;
#pragma unroll
        for (int j = 0; j < 4; j++) {
            int sl = tx * 4 + j;
            float resid = Ys[c * 65 + sl];
            float val = acc[i][j] * inv + add + resid;
            out[((size_t)(n * CC + c)) * LL + lo + sl] = fmaxf(val, 0.f);
        }
    }
}

// ---------------------------------------------------------------------------
extern "C" void kernel_launch(void* const* d_in, const int* in_sizes, int n_in,
                              void* d_out, int out_size) {
    const float* x     = (const float*)d_in[0];
    const float* W_qkv = (const float*)d_in[1];
    const float* b_qkv = (const float*)d_in[2];
    const float* W_out = (const float*)d_in[3];
    const float* b_out = (const float*)d_in[4];
    const float* g1    = (const float*)d_in[5];
    const float* be1   = (const float*)d_in[6];
    const float* mu1   = (const float*)d_in[7];
    const float* va1   = (const float*)d_in[8];
    const float* W_ff  = (const float*)d_in[9];
    const float* b_ff  = (const float*)d_in[10];
    const float* g2    = (const float*)d_in[11];
    const float* be2   = (const float*)d_in[12];
    const float* mu2   = (const float*)d_in[13];
    const float* va2   = (const float*)d_in[14];
    float* out = (float*)d_out;

    const int ATTN_SMEM = (2*64*KPAD + 2*64*VPAD + 8*16*PPAD) * (int)sizeof(float);
    cudaFuncSetAttribute(attn_kernel,
                         cudaFuncAttributeMaxDynamicSharedMemorySize, ATTN_SMEM);
    const int CONV_SMEM = (4 * 32 * CAP) * (int)sizeof(float);  // 34816 B
    cudaFuncSetAttribute(conv_kernel,
                         cudaFuncAttributeMaxDynamicSharedMemorySize, CONV_SMEM);

    wt_kernel<<<576, 256>>>(W_out);
    qkv_kernel<<<dim3(12, 400), 256>>>(x, W_qkv, b_qkv);
    attn_kernel<<<dim3(13, 64), 256, ATTN_SMEM>>>();
    conv_kernel<<<400, 256, CONV_SMEM>>>(x, b_out, g1, be1, mu1, va1);
    ff_kernel<<<400, 256>>>(W_ff, b_ff, g2, be2, mu2, va2, out);
}

// round 11
// speedup vs baseline: 1.3837x; 1.3588x over previous
#include <cuda_runtime.h>
#include <cuda_fp16.h>
#include <math.h>
#include <stdint.h>

// Problem constants
#define NB 16      // batch
#define CC 64      // channels
#define TT 64      // time
#define VV 25      // vertices
#define HH 4       // heads
#define DD 64      // head dim
#define LL (TT*VV) // 1600 tokens
#define HD (HH*DD) // 256

// Scratch (device globals; no runtime allocation allowed)
__device__ __half g_q[NB*HH*LL*DD];   // [nh][l][d], pre-scaled by 0.125
__device__ __half g_k[NB*HH*LL*DD];   // [nh][l][d]
__device__ __half g_v[NB*HH*DD*LL];   // [nh][d][l]  (TRANSPOSED)
__device__ float  g_o[NB*HD*LL];      // attention out, [N, H*D, T, V]
__device__ float  g_y[NB*CC*LL];      // after out_nets
__device__ float  g_wt[2304*64];      // W_out transposed to [k'=kw*256+ci][c]

// ---- legacy tf32 mma (qkv/conv GEMMs, proven) ------------------------------
__device__ __forceinline__ void mma_tf32(float c[4], const uint32_t a[4],
                                         uint32_t b0, uint32_t b1) {
    asm("mma.sync.aligned.m16n8k8.row.col.f32.tf32.tf32.f32 "
        "{%0,%1,%2,%3},{%4,%5,%6,%7},{%8,%9},{%0,%1,%2,%3};"
        : "+f"(c[0]), "+f"(c[1]), "+f"(c[2]), "+f"(c[3])
        : "r"(a[0]), "r"(a[1]), "r"(a[2]), "r"(a[3]), "r"(b0), "r"(b1));
}
// ---- fp16 mma m16n8k16 (attention) -----------------------------------------
__device__ __forceinline__ void mma_f16(float c[4], const uint32_t a[4],
                                        uint32_t b0, uint32_t b1) {
    asm("mma.sync.aligned.m16n8k16.row.col.f32.f16.f16.f32 "
        "{%0,%1,%2,%3},{%4,%5,%6,%7},{%8,%9},{%0,%1,%2,%3};"
        : "+f"(c[0]), "+f"(c[1]), "+f"(c[2]), "+f"(c[3])
        : "r"(a[0]), "r"(a[1]), "r"(a[2]), "r"(a[3]), "r"(b0), "r"(b1));
}
__device__ __forceinline__ uint32_t fbits(float f) { return __float_as_uint(f); }
__device__ __forceinline__ uint32_t h2bits(float lo, float hi) {
    __half2 h = __floats2half2_rn(lo, hi);
    return *(uint32_t*)&h;
}

// ---- cp.async helpers -------------------------------------------------------
__device__ __forceinline__ void cp16(uint32_t saddr, const void* gptr) {
    asm volatile("cp.async.cg.shared.global [%0], [%1], 16;\n"
                 :: "r"(saddr), "l"(gptr));
}
__device__ __forceinline__ void cp4z(uint32_t saddr, const void* gptr, int srcsz) {
    asm volatile("cp.async.ca.shared.global [%0], [%1], 4, %2;\n"
                 :: "r"(saddr), "l"(gptr), "r"(srcsz));
}
__device__ __forceinline__ void cp_commit() {
    asm volatile("cp.async.commit_group;\n");
}

// ---------------------------------------------------------------------------
// Kernel 0: transpose W_out [c][ci*9+kw] -> g_wt[(kw*256+ci)][c]
// ---------------------------------------------------------------------------
__global__ void wt_kernel(const float* __restrict__ W) {
    int idx = blockIdx.x * 256 + threadIdx.x;
    if (idx < 2304 * 64) {
        int c  = idx & 63;
        int kp = idx >> 6;
        int kw = kp >> 8;
        int ci = kp & 255;
        g_wt[idx] = W[c * 2304 + ci * 9 + kw];
    }
}

// ---------------------------------------------------------------------------
// Kernel 1: QKV projection (tf32 MMA, proven) -> fp16 outputs.
// q pre-scaled by 0.125; v written TRANSPOSED [nh][d][l] via smem stage.
// ---------------------------------------------------------------------------
__global__ void qkv_kernel(const float* __restrict__ x,
                           const float* __restrict__ Wq,
                           const float* __restrict__ bq) {
    __shared__ float  Xs[64 * 68];     // [c][l_local]
    __shared__ float  Ws[64 * 68];     // [c][j_local]
    __shared__ __half Vt2[64 * 72];    // transpose stage [d][l_local]
    const int bx = blockIdx.x;
    const int by = blockIdx.y;
    const int tid = threadIdx.x;
    const int warp = tid >> 5, lane = tid & 31;
    const int wr = warp >> 1, wc = warp & 1;
    const int r0 = wr * 16, c0 = wc * 32;
    const int grp = lane >> 2, qd = lane & 3;

    const int row_base = by * 64;
    const int n  = row_base / LL;
    const int l0 = row_base % LL;

    const float* xb = x + (size_t)n * CC * LL + l0;
#pragma unroll
    for (int it = 0; it < 16; it++) {
        int idx = tid + it * 256;
        int c = idx >> 6, ll = idx & 63;
        Xs[c * 68 + ll] = xb[c * LL + ll];
    }
    const float* wb = Wq + bx * 64;
#pragma unroll
    for (int it = 0; it < 16; it++) {
        int idx = tid + it * 256;
        int c = idx >> 6, j = idx & 63;
        Ws[c * 68 + j] = wb[c * 768 + j];
    }
    __syncthreads();

    float acc[4][4] = {};
#pragma unroll
    for (int ks = 0; ks < 8; ks++) {
        int k = ks * 8;
        uint32_t a[4];
        a[0] = fbits(Xs[(k + qd)     * 68 + r0 + grp]);
        a[1] = fbits(Xs[(k + qd)     * 68 + r0 + grp + 8]);
        a[2] = fbits(Xs[(k + qd + 4) * 68 + r0 + grp]);
        a[3] = fbits(Xs[(k + qd + 4) * 68 + r0 + grp + 8]);
#pragma unroll
        for (int ns = 0; ns < 4; ns++) {
            int nn = c0 + ns * 8 + grp;
            uint32_t b0 = fbits(Ws[(k + qd)     * 68 + nn]);
            uint32_t b1 = fbits(Ws[(k + qd + 4) * 68 + nn]);
            mma_tf32(acc[ns], a, b0, b1);
        }
    }

    const int part = bx >> 2;
    const int h    = bx & 3;
    const int nh   = n * HH + h;

    if (part == 2) {
        // stage V transposed in smem, then coalesced fp16 store to [nh][d][L]
#pragma unroll
        for (int ns = 0; ns < 4; ns++) {
            int d = c0 + ns * 8 + qd * 2;
            float bb0 = bq[bx * 64 + d];
            float bb1 = bq[bx * 64 + d + 1];
            int la = r0 + grp, lb = la + 8;
            Vt2[(d)     * 72 + la] = __float2half_rn(acc[ns][0] + bb0);
            Vt2[(d + 1) * 72 + la] = __float2half_rn(acc[ns][1] + bb1);
            Vt2[(d)     * 72 + lb] = __float2half_rn(acc[ns][2] + bb0);
            Vt2[(d + 1) * 72 + lb] = __float2half_rn(acc[ns][3] + bb1);
        }
        __syncthreads();
        __half2* gv2 = (__half2*)g_v;
#pragma unroll
        for (int it = 0; it < 8; it++) {
            int idx = tid + it * 256;
            int d = idx >> 5, lh = idx & 31;
            __half2 hv = *(__half2*)&Vt2[d * 72 + lh * 2];
            gv2[(((size_t)nh * 64 + d) * LL + l0) / 2 + lh] = hv;
        }
    } else {
        const float scale = (part == 0) ? 0.125f : 1.f;
        __half2* dst2 = (__half2*)((part == 0) ? g_q : g_k);
        const int lA = l0 + r0 + grp;
        const int lB = lA + 8;
#pragma unroll
        for (int ns = 0; ns < 4; ns++) {
            int d = c0 + ns * 8 + qd * 2;
            float bb0 = bq[bx * 64 + d];
            float bb1 = bq[bx * 64 + d + 1];
            __half2 hA = __floats2half2_rn((acc[ns][0] + bb0) * scale,
                                           (acc[ns][1] + bb1) * scale);
            __half2 hB = __floats2half2_rn((acc[ns][2] + bb0) * scale,
                                           (acc[ns][3] + bb1) * scale);
            dst2[(((size_t)nh * LL + lA) * 64 + d) >> 1] = hA;
            dst2[(((size_t)nh * LL + lB) * 64 + d) >> 1] = hB;
        }
    }
}

// ---------------------------------------------------------------------------
// Kernel 2: fp16 flash attention (m16n8k16), 128-row q-blocks, 8 warps
// (256 threads), no-max softmax, cp.async double-buffered K and V (V is
// pre-transposed [d][l]). smem rows padded to 144 B for conflict-free frags.
// ---------------------------------------------------------------------------
#define ROWB 144
#define ASM_Q 0
#define ASM_K 18432
#define ASM_V 36864
#define ASM_P 55296
#define ASM_TOT 73728
#define KVBUF 9216
#define OPAD 132

extern __shared__ char attn_smc[];
__global__ void __launch_bounds__(256) attn_kernel() {
    char* smc = attn_smc;
    const uint32_t smb = (uint32_t)__cvta_generic_to_shared(smc);
    const int qb = blockIdx.x, nh = blockIdx.y;
    const int tid = threadIdx.x;
    const int warp = tid >> 5, lane = tid & 31;
    const int grp = lane >> 2, qd = lane & 3;
    const int q_base = (qb * 128 <= LL - 128) ? qb * 128 : (LL - 128);

    const char* qsrc = (const char*)(g_q + ((size_t)nh * LL + q_base) * 64);
    const char* ksrc = (const char*)(g_k + (size_t)nh * LL * 64);
    const char* vsrc = (const char*)(g_v + (size_t)nh * 64 * LL);

    // ---- group 0: Q + K0 + V0 ; group 1: K1 + V1 ----
#pragma unroll
    for (int it = 0; it < 4; it++) {           // Q: 128 rows x 8 chunks
        int idx = tid + it * 256;
        int r = idx >> 3, c = idx & 7;
        cp16(smb + ASM_Q + r * ROWB + c * 16, qsrc + r * 128 + c * 16);
    }
#pragma unroll
    for (int it = 0; it < 2; it++) {           // K0: 64 rows x 8 chunks
        int idx = tid + it * 256;
        int r = idx >> 3, c = idx & 7;
        cp16(smb + ASM_K + r * ROWB + c * 16, ksrc + r * 128 + c * 16);
    }
#pragma unroll
    for (int it = 0; it < 2; it++) {           // V0: rows = d, cols = keys
        int idx = tid + it * 256;
        int r = idx >> 3, c = idx & 7;
        cp16(smb + ASM_V + r * ROWB + c * 16, vsrc + (size_t)r * (LL * 2) + c * 16);
    }
    cp_commit();
#pragma unroll
    for (int it = 0; it < 2; it++) {           // K1 + V1
        int idx = tid + it * 256;
        int r = idx >> 3, c = idx & 7;
        cp16(smb + ASM_K + KVBUF + r * ROWB + c * 16,
             ksrc + 128 * 64 + r * 128 + c * 16);
        cp16(smb + ASM_V + KVBUF + r * ROWB + c * 16,
             vsrc + (size_t)r * (LL * 2) + 128 + c * 16);
    }
    cp_commit();
    asm volatile("cp.async.wait_group 1;\n");
    __syncthreads();

    // ---- persistent Q fragments (fp16, rows warp*16+grp / +8) ----
    uint32_t qfrag[4][4];
    {
        const uint32_t qr = (uint32_t)((warp * 16 + grp) * ROWB);
#pragma unroll
        for (int kk = 0; kk < 4; kk++) {
            uint32_t base = (uint32_t)(ASM_Q) + qr + kk * 32 + qd * 4;
            qfrag[kk][0] = *(const uint32_t*)(smc + base);
            qfrag[kk][1] = *(const uint32_t*)(smc + base + 8 * ROWB);
            qfrag[kk][2] = *(const uint32_t*)(smc + base + 16);
            qfrag[kk][3] = *(const uint32_t*)(smc + base + 8 * ROWB + 16);
        }
    }

    float oacc[8][4] = {};
    float l0 = 0.f, l1 = 0.f;
    const uint32_t pw = (uint32_t)(ASM_P + warp * 16 * ROWB);

    for (int t = 0; t < 25; t++) {
        const uint32_t kb = (uint32_t)(ASM_K + (t & 1) * KVBUF);
        const uint32_t vb = (uint32_t)(ASM_V + (t & 1) * KVBUF);

        // ---- S = Q @ K^T ----
        float sacc[8][4] = {};
#pragma unroll
        for (int kk = 0; kk < 4; kk++) {
#pragma unroll
            for (int ns = 0; ns < 8; ns++) {
                uint32_t ba = kb + (ns * 8 + grp) * ROWB + kk * 32 + qd * 4;
                uint32_t b0 = *(const uint32_t*)(smc + ba);
                uint32_t b1 = *(const uint32_t*)(smc + ba + 16);
                mma_f16(sacc[ns], qfrag[kk], b0, b1);
            }
        }

        // ---- no-max softmax: p = exp(s - 8); stage P as fp16 ----
#pragma unroll
        for (int ns = 0; ns < 8; ns++) {
            float p0 = __expf(sacc[ns][0] - 8.f);
            float p1 = __expf(sacc[ns][1] - 8.f);
            float p2 = __expf(sacc[ns][2] - 8.f);
            float p3 = __expf(sacc[ns][3] - 8.f);
            l0 += p0 + p1;
            l1 += p2 + p3;
            uint32_t po = pw + grp * ROWB + ns * 16 + qd * 4;
            *(uint32_t*)(smc + po)            = h2bits(p0, p1);
            *(uint32_t*)(smc + po + 8 * ROWB) = h2bits(p2, p3);
        }
        __syncwarp();

        // ---- O += P @ V ----
#pragma unroll
        for (int kk = 0; kk < 4; kk++) {
            uint32_t pa = pw + grp * ROWB + kk * 32 + qd * 4;
            uint32_t a[4];
            a[0] = *(const uint32_t*)(smc + pa);
            a[1] = *(const uint32_t*)(smc + pa + 8 * ROWB);
            a[2] = *(const uint32_t*)(smc + pa + 16);
            a[3] = *(const uint32_t*)(smc + pa + 8 * ROWB + 16);
#pragma unroll
            for (int ns = 0; ns < 8; ns++) {
                uint32_t ba = vb + (ns * 8 + grp) * ROWB + kk * 32 + qd * 4;
                uint32_t b0 = *(const uint32_t*)(smc + ba);
                uint32_t b1 = *(const uint32_t*)(smc + ba + 16);
                mma_f16(oacc[ns], a, b0, b1);
            }
        }
        __syncwarp();

        __syncthreads();                       // all warps done with buf t
        if (t + 2 <= 24) {                     // prefetch t+2 into buf t&1
            const char* kp = ksrc + (size_t)(t + 2) * 64 * 128;
            const char* vp = vsrc + (size_t)(t + 2) * 128;
            uint32_t kd = (uint32_t)(ASM_K + (t & 1) * KVBUF);
            uint32_t vd = (uint32_t)(ASM_V + (t & 1) * KVBUF);
#pragma unroll
            for (int it = 0; it < 2; it++) {
                int idx = tid + it * 256;
                int r = idx >> 3, c = idx & 7;
                cp16(smb + kd + r * ROWB + c * 16, kp + r * 128 + c * 16);
                cp16(smb + vd + r * ROWB + c * 16, vp + (size_t)r * (LL * 2) + c * 16);
            }
            cp_commit();
        }
        if (t + 1 <= 24) {
            if (t + 2 <= 24) asm volatile("cp.async.wait_group 1;\n");
            else             asm volatile("cp.async.wait_group 0;\n");
            __syncthreads();
        }
    }

    // ---- reduce row sums, stage O transposed (fp32), coalesced store ----
    l0 += __shfl_xor_sync(0xFFFFFFFFu, l0, 1);
    l0 += __shfl_xor_sync(0xFFFFFFFFu, l0, 2);
    l1 += __shfl_xor_sync(0xFFFFFFFFu, l1, 1);
    l1 += __shfl_xor_sync(0xFFFFFFFFu, l1, 2);
    const float linv0 = 1.f / l0;
    const float linv1 = 1.f / l1;

    __syncthreads();
    float* Ot = (float*)smc;   // [64 d][OPAD l], 33792 B (overlays Q+K regions)
    {
        int la = warp * 16 + grp, lb = la + 8;
#pragma unroll
        for (int ns = 0; ns < 8; ns++) {
            int d = ns * 8 + qd * 2;
            Ot[(d)     * OPAD + la] = oacc[ns][0] * linv0;
            Ot[(d + 1) * OPAD + la] = oacc[ns][1] * linv0;
            Ot[(d)     * OPAD + lb] = oacc[ns][2] * linv1;
            Ot[(d + 1) * OPAD + lb] = oacc[ns][3] * linv1;
        }
    }
    __syncthreads();

    const int n = nh >> 2, h4 = nh & 3;
    float* ob = g_o + ((size_t)n * HD + h4 * 64) * LL + q_base;
#pragma unroll
    for (int it = 0; it < 32; it++) {
        int idx = tid + it * 256;
        int d = idx >> 7, l = idx & 127;
        ob[(size_t)d * LL + l] = Ot[d * OPAD + l];
    }
}

// ---------------------------------------------------------------------------
// Kernel 3: (1,9) conv (proven R8): 400 blocks, cp.async double-buffered.
// ---------------------------------------------------------------------------
#define CAP 68
extern __shared__ float conv_sm[];
__global__ void conv_kernel(const float* __restrict__ x,
                            const float* __restrict__ bias,
                            const float* __restrict__ g1,
                            const float* __restrict__ be1,
                            const float* __restrict__ mu1,
                            const float* __restrict__ va1) {
    float* As = conv_sm;
    float* Bs = conv_sm + 2 * 32 * CAP;

    const int tid = threadIdx.x;
    const int sbase = blockIdx.x * 64;
    const int warp = tid >> 5, lane = tid & 31;
    const int wr = warp >> 1, wc = warp & 1;
    const int r0 = wr * 16, c0 = wc * 32;
    const int grp = lane >> 2, qd = lane & 3;

    const int sl = tid & 63;
    const int klrow = tid >> 6;
    const int s = sbase + sl;
    const int n = s / LL;
    const int rem = s - n * LL;
    const int t = rem / VV;
    const int v = rem - t * VV;
    const float* obase = g_o + ((size_t)(n * HD + klrow)) * LL + rem - 4;

    const int akl = tid >> 3;
    const int ac0 = (tid & 7) * 8;

    const uint32_t asm0 = (uint32_t)__cvta_generic_to_shared(As);
    const uint32_t bsm0 = (uint32_t)__cvta_generic_to_shared(Bs);

    auto prefetch = [&](int kb, int buf) {
        const int kw = kb >> 3;
        const int cibase = (kb & 7) * 32;
        const float* ap = g_wt + (size_t)kb * 2048;
        uint32_t ab = asm0 + buf * 32 * CAP * 4;
        uint32_t bb = bsm0 + buf * 32 * CAP * 4;
        cp16(ab + (akl * CAP + ac0) * 4,     ap + akl * 64 + ac0);
        cp16(ab + (akl * CAP + ac0 + 4) * 4, ap + akl * 64 + ac0 + 4);
        const int vi = v + kw - 4;
        const int oksz = (vi >= 0 && vi < VV) ? 4 : 0;
        const float* bp = obase + (size_t)cibase * LL + kw;
#pragma unroll
        for (int r = 0; r < 8; r++) {
            int kl = klrow + r * 4;
            cp4z(bb + (kl * CAP + sl) * 4, bp + (size_t)r * 4 * LL, oksz);
        }
        cp_commit();
    };

    prefetch(0, 0);
    float acc[4][4] = {};

    for (int kb = 0; kb < 72; kb++) {
        const int cur = kb & 1;
        __syncthreads();
        if (kb < 71) {
            prefetch(kb + 1, cur ^ 1);
            asm volatile("cp.async.wait_group 1;\n");
        } else {
            asm volatile("cp.async.wait_group 0;\n");
        }
        __syncthreads();

        const float* Ac = As + cur * 32 * CAP;
        const float* Bc = Bs + cur * 32 * CAP;
#pragma unroll
        for (int ks = 0; ks < 4; ks++) {
            int k = ks * 8;
            uint32_t a[4];
            a[0] = fbits(Ac[(k + qd)     * CAP + r0 + grp]);
            a[1] = fbits(Ac[(k + qd)     * CAP + r0 + grp + 8]);
            a[2] = fbits(Ac[(k + qd + 4) * CAP + r0 + grp]);
            a[3] = fbits(Ac[(k + qd + 4) * CAP + r0 + grp + 8]);
#pragma unroll
            for (int ns = 0; ns < 4; ns++) {
                int nn = c0 + ns * 8 + grp;
                uint32_t b0 = fbits(Bc[(k + qd)     * CAP + nn]);
                uint32_t b1 = fbits(Bc[(k + qd + 4) * CAP + nn]);
                mma_tf32(acc[ns], a, b0, b1);
            }
        }
    }

    const int cA = r0 + grp, cB = cA + 8;
    float invA = g1[cA] * rsqrtf(va1[cA] + 1e-5f);
    float addA = be1[cA] - mu1[cA] * invA + bias[cA] * invA;
    float invB = g1[cB] * rsqrtf(va1[cB] + 1e-5f);
    float addB = be1[cB] - mu1[cB] * invB + bias[cB] * invB;
#pragma unroll
    for (int ns = 0; ns < 4; ns++) {
#pragma unroll
        for (int jj = 0; jj < 2; jj++) {
            int ss = sbase + c0 + ns * 8 + qd * 2 + jj;
            int nn2 = ss / LL;
            int rem2 = ss - nn2 * LL;
            size_t aA = ((size_t)(nn2 * CC + cA)) * LL + rem2;
            size_t aB = ((size_t)(nn2 * CC + cB)) * LL + rem2;
            float vA = acc[ns][jj]     * invA + addA + x[aA];
            float vB = acc[ns][jj + 2] * invB + addB + x[aB];
            g_y[aA] = fmaxf(vA, 0.f);
            g_y[aB] = fmaxf(vB, 0.f);
        }
    }
}

// ---------------------------------------------------------------------------
// Kernel 4: 1x1 conv + BN2 + residual + relu (proven scalar).
// ---------------------------------------------------------------------------
__global__ void ff_kernel(const float* __restrict__ Wff,
                          const float* __restrict__ bff,
                          const float* __restrict__ g2,
                          const float* __restrict__ be2,
                          const float* __restrict__ mu2,
                          const float* __restrict__ va2,
                          float* __restrict__ out) {
    __shared__ float Ws[64 * 65];
    __shared__ float Ys[64 * 65];
    const int tid = threadIdx.x;
    const int sbase = blockIdx.x * 64;
    const int n  = sbase / LL;
    const int lo = sbase % LL;

#pragma unroll
    for (int it = 0; it < 16; it++) {
        int idx = tid + it * 256;
        int c = idx >> 6, ci = idx & 63;
        Ws[c * 65 + ci] = Wff[c * 64 + ci];
    }
    const float* yb = g_y + (size_t)n * CC * LL + lo;
#pragma unroll
    for (int it = 0; it < 16; it++) {
        int idx = tid + it * 256;
        int ci = idx >> 6, sl = idx & 63;
        Ys[ci * 65 + sl] = yb[ci * LL + sl];
    }
    __syncthreads();

    const int ty = tid >> 4, tx = tid & 15;
    float acc[4][4] = {};
#pragma unroll
    for (int kk = 0; kk < 64; kk++) {
        float a[4], b[4];
#pragma unroll
        for (int i = 0; i < 4; i++) a[i] = Ws[(ty * 4 + i) * 65 + kk];
#pragma unroll
        for (int j = 0; j < 4; j++) b[j] = Ys[kk * 65 + tx * 4 + j];
#pragma unroll
        for (int i = 0; i < 4; i++)
#pragma unroll
            for (int j = 0; j < 4; j++) acc[i][j] = fmaf(a[i], b[j], acc[i][j]);
    }

#pragma unroll
    for (int i = 0; i < 4; i++) {
        int c = ty * 4 + i;
        float inv = g2[c] * rsqrtf(va2[c] + 1e-5f);
        float add = be2[c] - mu2[c] * inv + bff[c] * inv;
#pragma unroll
        for (int j = 0; j < 4; j++) {
            int sl = tx * 4 + j;
            float resid = Ys[c * 65 + sl];
            float val = acc[i][j] * inv + add + resid;
            out[((size_t)(n * CC + c)) * LL + lo + sl] = fmaxf(val, 0.f);
        }
    }
}

// ---------------------------------------------------------------------------
extern "C" void kernel_launch(void* const* d_in, const int* in_sizes, int n_in,
                              void* d_out, int out_size) {
    const float* x     = (const float*)d_in[0];
    const float* W_qkv = (const float*)d_in[1];
    const float* b_qkv = (const float*)d_in[2];
    const float* W_out = (const float*)d_in[3];
    const float* b_out = (const float*)d_in[4];
    const float* g1    = (const float*)d_in[5];
    const float* be1   = (const float*)d_in[6];
    const float* mu1   = (const float*)d_in[7];
    const float* va1   = (const float*)d_in[8];
    const float* W_ff  = (const float*)d_in[9];
    const float* b_ff  = (const float*)d_in[10];
    const float* g2    = (const float*)d_in[11];
    const float* be2   = (const float*)d_in[12];
    const float* mu2   = (const float*)d_in[13];
    const float* va2   = (const float*)d_in[14];
    float* out = (float*)d_out;

    cudaFuncSetAttribute(attn_kernel,
                         cudaFuncAttributeMaxDynamicSharedMemorySize, ASM_TOT);
    const int CONV_SMEM = (4 * 32 * CAP) * (int)sizeof(float);
    cudaFuncSetAttribute(conv_kernel,
                         cudaFuncAttributeMaxDynamicSharedMemorySize, CONV_SMEM);

    wt_kernel<<<576, 256>>>(W_out);
    qkv_kernel<<<dim3(12, 400), 256>>>(x, W_qkv, b_qkv);
    attn_kernel<<<dim3(13, 64), 256, ASM_TOT>>>();
    conv_kernel<<<400, 256, CONV_SMEM>>>(x, b_out, g1, be1, mu1, va1);
    ff_kernel<<<400, 256>>>(W_ff, b_ff, g2, be2, mu2, va2, out);
}

// round 12
// speedup vs baseline: 1.8191x; 1.3147x over previous
#include <cuda_runtime.h>
#include <cuda_fp16.h>
#include <math.h>
#include <stdint.h>

// Problem constants
#define NB 16      // batch
#define CC 64      // channels
#define TT 64      // time
#define VV 25      // vertices
#define HH 4       // heads
#define DD 64      // head dim
#define LL (TT*VV) // 1600 tokens
#define HD (HH*DD) // 256

// Scratch (device globals; no runtime allocation allowed)
__device__ __half g_q[NB*HH*LL*DD];   // [nh][l][d], pre-scaled by 0.125
__device__ __half g_k[NB*HH*LL*DD];   // [nh][l][d]
__device__ __half g_v[NB*HH*DD*LL];   // [nh][d][l]  (TRANSPOSED)
__device__ __half g_o[NB*LL*HD];      // attention out, [n][l][ci]  (fp16!)
__device__ float  g_y[NB*CC*LL];      // after out_nets
__device__ __half g_wt[9*64*256];     // W_out as [kw][c][ci]  (fp16)

// ---- legacy tf32 mma (qkv GEMM, proven) ------------------------------------
__device__ __forceinline__ void mma_tf32(float c[4], const uint32_t a[4],
                                         uint32_t b0, uint32_t b1) {
    asm("mma.sync.aligned.m16n8k8.row.col.f32.tf32.tf32.f32 "
        "{%0,%1,%2,%3},{%4,%5,%6,%7},{%8,%9},{%0,%1,%2,%3};"
        : "+f"(c[0]), "+f"(c[1]), "+f"(c[2]), "+f"(c[3])
        : "r"(a[0]), "r"(a[1]), "r"(a[2]), "r"(a[3]), "r"(b0), "r"(b1));
}
// ---- fp16 mma m16n8k16 (attention + conv) ----------------------------------
__device__ __forceinline__ void mma_f16(float c[4], const uint32_t a[4],
                                        uint32_t b0, uint32_t b1) {
    asm("mma.sync.aligned.m16n8k16.row.col.f32.f16.f16.f32 "
        "{%0,%1,%2,%3},{%4,%5,%6,%7},{%8,%9},{%0,%1,%2,%3};"
        : "+f"(c[0]), "+f"(c[1]), "+f"(c[2]), "+f"(c[3])
        : "r"(a[0]), "r"(a[1]), "r"(a[2]), "r"(a[3]), "r"(b0), "r"(b1));
}
__device__ __forceinline__ uint32_t fbits(float f) { return __float_as_uint(f); }
__device__ __forceinline__ uint32_t h2bits(float lo, float hi) {
    __half2 h = __floats2half2_rn(lo, hi);
    return *(uint32_t*)&h;
}

// ---- cp.async helpers -------------------------------------------------------
__device__ __forceinline__ void cp16(uint32_t saddr, const void* gptr) {
    asm volatile("cp.async.cg.shared.global [%0], [%1], 16;\n"
                 :: "r"(saddr), "l"(gptr));
}
__device__ __forceinline__ void cp16z(uint32_t saddr, const void* gptr, int srcsz) {
    asm volatile("cp.async.cg.shared.global [%0], [%1], 16, %2;\n"
                 :: "r"(saddr), "l"(gptr), "r"(srcsz));
}
__device__ __forceinline__ void cp_commit() {
    asm volatile("cp.async.commit_group;\n");
}

// ---------------------------------------------------------------------------
// Kernel 0: W_out [c][ci*9+kw] -> g_wt[kw][c][ci]  (fp16)
// ---------------------------------------------------------------------------
__global__ void wt_kernel(const float* __restrict__ W) {
    int idx = blockIdx.x * 256 + threadIdx.x;
    if (idx < 9 * 64 * 256) {
        int ci = idx & 255;
        int c  = (idx >> 8) & 63;
        int kw = idx >> 14;
        g_wt[idx] = __float2half_rn(W[c * 2304 + ci * 9 + kw]);
    }
}

// ---------------------------------------------------------------------------
// Kernel 1: QKV projection (tf32 MMA, proven) -> fp16 outputs.
// q pre-scaled by 0.125; v written TRANSPOSED [nh][d][l] via smem stage.
// ---------------------------------------------------------------------------
__global__ void qkv_kernel(const float* __restrict__ x,
                           const float* __restrict__ Wq,
                           const float* __restrict__ bq) {
    __shared__ float  Xs[64 * 68];     // [c][l_local]
    __shared__ float  Ws[64 * 68];     // [c][j_local]
    __shared__ __half Vt2[64 * 72];    // transpose stage [d][l_local]
    const int bx = blockIdx.x;
    const int by = blockIdx.y;
    const int tid = threadIdx.x;
    const int warp = tid >> 5, lane = tid & 31;
    const int wr = warp >> 1, wc = warp & 1;
    const int r0 = wr * 16, c0 = wc * 32;
    const int grp = lane >> 2, qd = lane & 3;

    const int row_base = by * 64;
    const int n  = row_base / LL;
    const int l0 = row_base % LL;

    const float* xb = x + (size_t)n * CC * LL + l0;
#pragma unroll
    for (int it = 0; it < 16; it++) {
        int idx = tid + it * 256;
        int c = idx >> 6, ll = idx & 63;
        Xs[c * 68 + ll] = xb[c * LL + ll];
    }
    const float* wb = Wq + bx * 64;
#pragma unroll
    for (int it = 0; it < 16; it++) {
        int idx = tid + it * 256;
        int c = idx >> 6, j = idx & 63;
        Ws[c * 68 + j] = wb[c * 768 + j];
    }
    __syncthreads();

    float acc[4][4] = {};
#pragma unroll
    for (int ks = 0; ks < 8; ks++) {
        int k = ks * 8;
        uint32_t a[4];
        a[0] = fbits(Xs[(k + qd)     * 68 + r0 + grp]);
        a[1] = fbits(Xs[(k + qd)     * 68 + r0 + grp + 8]);
        a[2] = fbits(Xs[(k + qd + 4) * 68 + r0 + grp]);
        a[3] = fbits(Xs[(k + qd + 4) * 68 + r0 + grp + 8]);
#pragma unroll
        for (int ns = 0; ns < 4; ns++) {
            int nn = c0 + ns * 8 + grp;
            uint32_t b0 = fbits(Ws[(k + qd)     * 68 + nn]);
            uint32_t b1 = fbits(Ws[(k + qd + 4) * 68 + nn]);
            mma_tf32(acc[ns], a, b0, b1);
        }
    }

    const int part = bx >> 2;
    const int h    = bx & 3;
    const int nh   = n * HH + h;

    if (part == 2) {
        // stage V transposed in smem, then coalesced fp16 store to [nh][d][L]
#pragma unroll
        for (int ns = 0; ns < 4; ns++) {
            int d = c0 + ns * 8 + qd * 2;
            float bb0 = bq[bx * 64 + d];
            float bb1 = bq[bx * 64 + d + 1];
            int la = r0 + grp, lb = la + 8;
            Vt2[(d)     * 72 + la] = __float2half_rn(acc[ns][0] + bb0);
            Vt2[(d + 1) * 72 + la] = __float2half_rn(acc[ns][1] + bb1);
            Vt2[(d)     * 72 + lb] = __float2half_rn(acc[ns][2] + bb0);
            Vt2[(d + 1) * 72 + lb] = __float2half_rn(acc[ns][3] + bb1);
        }
        __syncthreads();
        __half2* gv2 = (__half2*)g_v;
#pragma unroll
        for (int it = 0; it < 8; it++) {
            int idx = tid + it * 256;
            int d = idx >> 5, lh = idx & 31;
            __half2 hv = *(__half2*)&Vt2[d * 72 + lh * 2];
            gv2[(((size_t)nh * 64 + d) * LL + l0) / 2 + lh] = hv;
        }
    } else {
        const float scale = (part == 0) ? 0.125f : 1.f;
        __half2* dst2 = (__half2*)((part == 0) ? g_q : g_k);
        const int lA = l0 + r0 + grp;
        const int lB = lA + 8;
#pragma unroll
        for (int ns = 0; ns < 4; ns++) {
            int d = c0 + ns * 8 + qd * 2;
            float bb0 = bq[bx * 64 + d];
            float bb1 = bq[bx * 64 + d + 1];
            __half2 hA = __floats2half2_rn((acc[ns][0] + bb0) * scale,
                                           (acc[ns][1] + bb1) * scale);
            __half2 hB = __floats2half2_rn((acc[ns][2] + bb0) * scale,
                                           (acc[ns][3] + bb1) * scale);
            dst2[(((size_t)nh * LL + lA) * 64 + d) >> 1] = hA;
            dst2[(((size_t)nh * LL + lB) * 64 + d) >> 1] = hB;
        }
    }
}

// ---------------------------------------------------------------------------
// Kernel 2: fp16 flash attention (proven R11) — epilogue now writes fp16
// g_o in [n][l][ci] layout (ci contiguous).
// ---------------------------------------------------------------------------
#define ROWB 144
#define ASM_Q 0
#define ASM_K 18432
#define ASM_V 36864
#define ASM_P 55296
#define ASM_TOT 73728
#define KVBUF 9216
#define OP2 88            // halves per staged O row (176 B, 16B-aligned)

extern __shared__ char attn_smc[];
__global__ void __launch_bounds__(256) attn_kernel() {
    char* smc = attn_smc;
    const uint32_t smb = (uint32_t)__cvta_generic_to_shared(smc);
    const int qb = blockIdx.x, nh = blockIdx.y;
    const int tid = threadIdx.x;
    const int warp = tid >> 5, lane = tid & 31;
    const int grp = lane >> 2, qd = lane & 3;
    const int q_base = (qb * 128 <= LL - 128) ? qb * 128 : (LL - 128);

    const char* qsrc = (const char*)(g_q + ((size_t)nh * LL + q_base) * 64);
    const char* ksrc = (const char*)(g_k + (size_t)nh * LL * 64);
    const char* vsrc = (const char*)(g_v + (size_t)nh * 64 * LL);

    // ---- group 0: Q + K0 + V0 ; group 1: K1 + V1 ----
#pragma unroll
    for (int it = 0; it < 4; it++) {
        int idx = tid + it * 256;
        int r = idx >> 3, c = idx & 7;
        cp16(smb + ASM_Q + r * ROWB + c * 16, qsrc + r * 128 + c * 16);
    }
#pragma unroll
    for (int it = 0; it < 2; it++) {
        int idx = tid + it * 256;
        int r = idx >> 3, c = idx & 7;
        cp16(smb + ASM_K + r * ROWB + c * 16, ksrc + r * 128 + c * 16);
    }
#pragma unroll
    for (int it = 0; it < 2; it++) {
        int idx = tid + it * 256;
        int r = idx >> 3, c = idx & 7;
        cp16(smb + ASM_V + r * ROWB + c * 16, vsrc + (size_t)r * (LL * 2) + c * 16);
    }
    cp_commit();
#pragma unroll
    for (int it = 0; it < 2; it++) {
        int idx = tid + it * 256;
        int r = idx >> 3, c = idx & 7;
        cp16(smb + ASM_K + KVBUF + r * ROWB + c * 16,
             ksrc + 128 * 64 + r * 128 + c * 16);
        cp16(smb + ASM_V + KVBUF + r * ROWB + c * 16,
             vsrc + (size_t)r * (LL * 2) + 128 + c * 16);
    }
    cp_commit();
    asm volatile("cp.async.wait_group 1;\n");
    __syncthreads();

    // ---- persistent Q fragments ----
    uint32_t qfrag[4][4];
    {
        const uint32_t qr = (uint32_t)((warp * 16 + grp) * ROWB);
#pragma unroll
        for (int kk = 0; kk < 4; kk++) {
            uint32_t base = (uint32_t)(ASM_Q) + qr + kk * 32 + qd * 4;
            qfrag[kk][0] = *(const uint32_t*)(smc + base);
            qfrag[kk][1] = *(const uint32_t*)(smc + base + 8 * ROWB);
            qfrag[kk][2] = *(const uint32_t*)(smc + base + 16);
            qfrag[kk][3] = *(const uint32_t*)(smc + base + 8 * ROWB + 16);
        }
    }

    float oacc[8][4] = {};
    float l0 = 0.f, l1 = 0.f;
    const uint32_t pw = (uint32_t)(ASM_P + warp * 16 * ROWB);

    for (int t = 0; t < 25; t++) {
        const uint32_t kb = (uint32_t)(ASM_K + (t & 1) * KVBUF);
        const uint32_t vb = (uint32_t)(ASM_V + (t & 1) * KVBUF);

        // ---- S = Q @ K^T ----
        float sacc[8][4] = {};
#pragma unroll
        for (int kk = 0; kk < 4; kk++) {
#pragma unroll
            for (int ns = 0; ns < 8; ns++) {
                uint32_t ba = kb + (ns * 8 + grp) * ROWB + kk * 32 + qd * 4;
                uint32_t b0 = *(const uint32_t*)(smc + ba);
                uint32_t b1 = *(const uint32_t*)(smc + ba + 16);
                mma_f16(sacc[ns], qfrag[kk], b0, b1);
            }
        }

        // ---- no-max softmax: p = exp(s - 8); stage P as fp16 ----
#pragma unroll
        for (int ns = 0; ns < 8; ns++) {
            float p0 = __expf(sacc[ns][0] - 8.f);
            float p1 = __expf(sacc[ns][1] - 8.f);
            float p2 = __expf(sacc[ns][2] - 8.f);
            float p3 = __expf(sacc[ns][3] - 8.f);
            l0 += p0 + p1;
            l1 += p2 + p3;
            uint32_t po = pw + grp * ROWB + ns * 16 + qd * 4;
            *(uint32_t*)(smc + po)            = h2bits(p0, p1);
            *(uint32_t*)(smc + po + 8 * ROWB) = h2bits(p2, p3);
        }
        __syncwarp();

        // ---- O += P @ V ----
#pragma unroll
        for (int kk = 0; kk < 4; kk++) {
            uint32_t pa = pw + grp * ROWB + kk * 32 + qd * 4;
            uint32_t a[4];
            a[0] = *(const uint32_t*)(smc + pa);
            a[1] = *(const uint32_t*)(smc + pa + 8 * ROWB);
            a[2] = *(const uint32_t*)(smc + pa + 16);
            a[3] = *(const uint32_t*)(smc + pa + 8 * ROWB + 16);
#pragma unroll
            for (int ns = 0; ns < 8; ns++) {
                uint32_t ba = vb + (ns * 8 + grp) * ROWB + kk * 32 + qd * 4;
                uint32_t b0 = *(const uint32_t*)(smc + ba);
                uint32_t b1 = *(const uint32_t*)(smc + ba + 16);
                mma_f16(oacc[ns], a, b0, b1);
            }
        }
        __syncwarp();

        __syncthreads();
        if (t + 2 <= 24) {
            const char* kp = ksrc + (size_t)(t + 2) * 64 * 128;
            const char* vp = vsrc + (size_t)(t + 2) * 128;
            uint32_t kd = (uint32_t)(ASM_K + (t & 1) * KVBUF);
            uint32_t vd = (uint32_t)(ASM_V + (t & 1) * KVBUF);
#pragma unroll
            for (int it = 0; it < 2; it++) {
                int idx = tid + it * 256;
                int r = idx >> 3, c = idx & 7;
                cp16(smb + kd + r * ROWB + c * 16, kp + r * 128 + c * 16);
                cp16(smb + vd + r * ROWB + c * 16, vp + (size_t)r * (LL * 2) + c * 16);
            }
            cp_commit();
        }
        if (t + 1 <= 24) {
            if (t + 2 <= 24) asm volatile("cp.async.wait_group 1;\n");
            else             asm volatile("cp.async.wait_group 0;\n");
            __syncthreads();
        }
    }

    // ---- reduce row sums; stage O as fp16 [l][d]; store 128B rows ----
    l0 += __shfl_xor_sync(0xFFFFFFFFu, l0, 1);
    l0 += __shfl_xor_sync(0xFFFFFFFFu, l0, 2);
    l1 += __shfl_xor_sync(0xFFFFFFFFu, l1, 1);
    l1 += __shfl_xor_sync(0xFFFFFFFFu, l1, 2);
    const float linv0 = 1.f / l0;
    const float linv1 = 1.f / l1;

    __syncthreads();
    __half* Oth = (__half*)smc;   // [128 l][OP2 d], 22528 B
    {
        int la = warp * 16 + grp, lb = la + 8;
#pragma unroll
        for (int ns = 0; ns < 8; ns++) {
            int d = ns * 8 + qd * 2;
            *(__half2*)&Oth[la * OP2 + d] =
                __floats2half2_rn(oacc[ns][0] * linv0, oacc[ns][1] * linv0);
            *(__half2*)&Oth[lb * OP2 + d] =
                __floats2half2_rn(oacc[ns][2] * linv1, oacc[ns][3] * linv1);
        }
    }
    __syncthreads();

    const int n = nh >> 2, h4 = nh & 3;
    char* ob = (char*)(g_o + ((size_t)n * LL + q_base) * HD + h4 * 64);
#pragma unroll
    for (int it = 0; it < 4; it++) {
        int idx = tid + it * 256;
        int l = idx >> 3, c8 = idx & 7;
        *(float4*)(ob + (size_t)l * (HD * 2) + c8 * 16) =
            *(const float4*)((char*)Oth + l * (OP2 * 2) + c8 * 16);
    }
}

// ---------------------------------------------------------------------------
// Kernel 3: (1,9) conv, fp16 m16n8k16. 400 blocks, 64sp x 64ch tiles,
// k' = kw*256+ci ordering; B tile = ONE cp16 (zero-fill predicated) per
// thread per chunk from ci-contiguous g_o. Double-buffered.
// Fused bias+BN1+residual(x)+relu -> g_y (fp32).
// ---------------------------------------------------------------------------
#define CROW 80                        // bytes per smem row (64B data + pad)
#define CBUF (64 * CROW)               // 5120 B per buffer
extern __shared__ char conv_smc[];
__global__ void __launch_bounds__(256) conv_kernel(
                            const float* __restrict__ x,
                            const float* __restrict__ bias,
                            const float* __restrict__ g1,
                            const float* __restrict__ be1,
                            const float* __restrict__ mu1,
                            const float* __restrict__ va1) {
    char* smc = conv_smc;
    const uint32_t smb = (uint32_t)__cvta_generic_to_shared(smc);
    const uint32_t ASMA = 0;            // [2][64 ch][CROW]
    const uint32_t ASMB = 2 * CBUF;     // [2][64 sp][CROW]

    const int tid = threadIdx.x;
    const int sbase = blockIdx.x * 64;
    const int warp = tid >> 5, lane = tid & 31;
    const int wr = warp >> 1, wc = warp & 1;
    const int r0 = wr * 16, c0 = wc * 32;
    const int grp = lane >> 2, qd = lane & 3;

    // load-thread geometry: row = tid>>2 (0..63), 16B chunk = tid&3
    const int lrow = tid >> 2;
    const int lc16 = tid & 3;
    // B row geometry (spatial)
    const int s = sbase + lrow;
    const int n = s / LL;
    const int rem = s - n * LL;
    const int t = rem / VV;
    const int v = rem - t * VV;
    const char* bsrc0 = (const char*)(g_o + ((size_t)n * LL + rem - 4) * HD);

    auto prefetch = [&](int kb, int buf) {
        const int kw = kb >> 3;
        const int cibase = (kb & 7) * 32;
        // A: g_wt[kw][lrow][cibase + lc16*8 ..]
        const char* asrc = (const char*)(g_wt + ((size_t)(kw * 64 + lrow)) * 256
                                         + cibase) + lc16 * 16;
        cp16(smb + ASMA + buf * CBUF + lrow * CROW + lc16 * 16, asrc);
        // B: g_o[n][rem + kw - 4][cibase ..], zero-fill when v+kw-4 out of range
        const int vi = v + kw - 4;
        const int oksz = (vi >= 0 && vi < VV) ? 16 : 0;
        const char* bsrc = bsrc0 + (size_t)kw * (HD * 2) + cibase * 2 + lc16 * 16;
        cp16z(smb + ASMB + buf * CBUF + lrow * CROW + lc16 * 16, bsrc, oksz);
        cp_commit();
    };

    prefetch(0, 0);
    float acc[4][4] = {};

    for (int kb = 0; kb < 72; kb++) {
        const int cur = kb & 1;
        __syncthreads();
        if (kb < 71) {
            prefetch(kb + 1, cur ^ 1);
            asm volatile("cp.async.wait_group 1;\n");
        } else {
            asm volatile("cp.async.wait_group 0;\n");
        }
        __syncthreads();

        const char* Ac = smc + ASMA + cur * CBUF;
        const char* Bc = smc + ASMB + cur * CBUF;
#pragma unroll
        for (int kk = 0; kk < 2; kk++) {
            uint32_t ao = (uint32_t)((r0 + grp) * CROW + kk * 32 + qd * 4);
            uint32_t a[4];
            a[0] = *(const uint32_t*)(Ac + ao);
            a[1] = *(const uint32_t*)(Ac + ao + 8 * CROW);
            a[2] = *(const uint32_t*)(Ac + ao + 16);
            a[3] = *(const uint32_t*)(Ac + ao + 8 * CROW + 16);
#pragma unroll
            for (int ns = 0; ns < 4; ns++) {
                uint32_t bo = (uint32_t)((c0 + ns * 8 + grp) * CROW + kk * 32 + qd * 4);
                uint32_t b0 = *(const uint32_t*)(Bc + bo);
                uint32_t b1 = *(const uint32_t*)(Bc + bo + 16);
                mma_f16(acc[ns], a, b0, b1);
            }
        }
    }

    // epilogue: bn1(conv + bias) + x, relu
    const int cA = r0 + grp, cB = cA + 8;
    float invA = g1[cA] * rsqrtf(va1[cA] + 1e-5f);
    float addA = be1[cA] - mu1[cA] * invA + bias[cA] * invA;
    float invB = g1[cB] * rsqrtf(va1[cB] + 1e-5f);
    float addB = be1[cB] - mu1[cB] * invB + bias[cB] * invB;
#pragma unroll
    for (int ns = 0; ns < 4; ns++) {
#pragma unroll
        for (int jj = 0; jj < 2; jj++) {
            int ss = sbase + c0 + ns * 8 + qd * 2 + jj;
            int nn2 = ss / LL;
            int rem2 = ss - nn2 * LL;
            size_t aA = ((size_t)(nn2 * CC + cA)) * LL + rem2;
            size_t aB = ((size_t)(nn2 * CC + cB)) * LL + rem2;
            float vA = acc[ns][jj]     * invA + addA + x[aA];
            float vB = acc[ns][jj + 2] * invB + addB + x[aB];
            g_y[aA] = fmaxf(vA, 0.f);
            g_y[aB] = fmaxf(vB, 0.f);
        }
    }
}

// ---------------------------------------------------------------------------
// Kernel 4: 1x1 conv + BN2 + residual + relu (proven scalar).
// ---------------------------------------------------------------------------
__global__ void ff_kernel(const float* __restrict__ Wff,
                          const float* __restrict__ bff,
                          const float* __restrict__ g2,
                          const float* __restrict__ be2,
                          const float* __restrict__ mu2,
                          const float* __restrict__ va2,
                          float* __restrict__ out) {
    __shared__ float Ws[64 * 65];
    __shared__ float Ys[64 * 65];
    const int tid = threadIdx.x;
    const int sbase = blockIdx.x * 64;
    const int n  = sbase / LL;
    const int lo = sbase % LL;

#pragma unroll
    for (int it = 0; it < 16; it++) {
        int idx = tid + it * 256;
        int c = idx >> 6, ci = idx & 63;
        Ws[c * 65 + ci] = Wff[c * 64 + ci];
    }
    const float* yb = g_y + (size_t)n * CC * LL + lo;
#pragma unroll
    for (int it = 0; it < 16; it++) {
        int idx = tid + it * 256;
        int ci = idx >> 6, sl = idx & 63;
        Ys[ci * 65 + sl] = yb[ci * LL + sl];
    }
    __syncthreads();

    const int ty = tid >> 4, tx = tid & 15;
    float acc[4][4] = {};
#pragma unroll
    for (int kk = 0; kk < 64; kk++) {
        float a[4], b[4];
#pragma unroll
        for (int i = 0; i < 4; i++) a[i] = Ws[(ty * 4 + i) * 65 + kk];
#pragma unroll
        for (int j = 0; j < 4; j++) b[j] = Ys[kk * 65 + tx * 4 + j];
#pragma unroll
        for (int i = 0; i < 4; i++)
#pragma unroll
            for (int j = 0; j < 4; j++) acc[i][j] = fmaf(a[i], b[j], acc[i][j]);
    }

#pragma unroll
    for (int i = 0; i < 4; i++) {
        int c = ty * 4 + i;
        float inv = g2[c] * rsqrtf(va2[c] + 1e-5f);
        float add = be2[c] - mu2[c] * inv + bff[c] * inv;
#pragma unroll
        for (int j = 0; j < 4; j++) {
            int sl = tx * 4 + j;
            float resid = Ys[c * 65 + sl];
            float val = acc[i][j] * inv + add + resid;
            out[((size_t)(n * CC + c)) * LL + lo + sl] = fmaxf(val, 0.f);
        }
    }
}

// ---------------------------------------------------------------------------
extern "C" void kernel_launch(void* const* d_in, const int* in_sizes, int n_in,
                              void* d_out, int out_size) {
    const float* x     = (const float*)d_in[0];
    const float* W_qkv = (const float*)d_in[1];
    const float* b_qkv = (const float*)d_in[2];
    const float* W_out = (const float*)d_in[3];
    const float* b_out = (const float*)d_in[4];
    const float* g1    = (const float*)d_in[5];
    const float* be1   = (const float*)d_in[6];
    const float* mu1   = (const float*)d_in[7];
    const float* va1   = (const float*)d_in[8];
    const float* W_ff  = (const float*)d_in[9];
    const float* b_ff  = (const float*)d_in[10];
    const float* g2    = (const float*)d_in[11];
    const float* be2   = (const float*)d_in[12];
    const float* mu2   = (const float*)d_in[13];
    const float* va2   = (const float*)d_in[14];
    float* out = (float*)d_out;

    cudaFuncSetAttribute(attn_kernel,
                         cudaFuncAttributeMaxDynamicSharedMemorySize, ASM_TOT);
    const int CONV_SMEM = 4 * CBUF;   // 20480 B
    cudaFuncSetAttribute(conv_kernel,
                         cudaFuncAttributeMaxDynamicSharedMemorySize, CONV_SMEM);

    wt_kernel<<<576, 256>>>(W_out);
    qkv_kernel<<<dim3(12, 400), 256>>>(x, W_qkv, b_qkv);
    attn_kernel<<<dim3(13, 64), 256, ASM_TOT>>>();
    conv_kernel<<<400, 256, CONV_SMEM>>>(x, b_out, g1, be1, mu1, va1);
    ff_kernel<<<400, 256>>>(W_ff, b_ff, g2, be2, mu2, va2, out);
}

// round 13
// speedup vs baseline: 1.9123x; 1.0512x over previous
#include <cuda_runtime.h>
#include <cuda_fp16.h>
#include <math.h>
#include <stdint.h>

// Problem constants
#define NB 16      // batch
#define CC 64      // channels
#define TT 64      // time
#define VV 25      // vertices
#define HH 4       // heads
#define DD 64      // head dim
#define LL (TT*VV) // 1600 tokens
#define HD (HH*DD) // 256

// Scratch (device globals; no runtime allocation allowed)
__device__ __half g_q[NB*HH*LL*DD];   // [nh][l][d], pre-scaled by 0.125
__device__ __half g_k[NB*HH*LL*DD];   // [nh][l][d]
__device__ __half g_v[NB*HH*DD*LL];   // [nh][d][l]  (TRANSPOSED)
__device__ __half g_o[NB*LL*HD];      // attention out, [n][l][ci]  (fp16)
__device__ __half g_wt[9*64*256];     // W_out as [kw][c][ci]  (fp16)

// ---- fp16 mma m16n8k16 ------------------------------------------------------
__device__ __forceinline__ void mma_f16(float c[4], const uint32_t a[4],
                                        uint32_t b0, uint32_t b1) {
    asm("mma.sync.aligned.m16n8k16.row.col.f32.f16.f16.f32 "
        "{%0,%1,%2,%3},{%4,%5,%6,%7},{%8,%9},{%0,%1,%2,%3};"
        : "+f"(c[0]), "+f"(c[1]), "+f"(c[2]), "+f"(c[3])
        : "r"(a[0]), "r"(a[1]), "r"(a[2]), "r"(a[3]), "r"(b0), "r"(b1));
}
__device__ __forceinline__ uint32_t h2bits(float lo, float hi) {
    __half2 h = __floats2half2_rn(lo, hi);
    return *(uint32_t*)&h;
}

// ---- cp.async helpers -------------------------------------------------------
__device__ __forceinline__ void cp16(uint32_t saddr, const void* gptr) {
    asm volatile("cp.async.cg.shared.global [%0], [%1], 16;\n"
                 :: "r"(saddr), "l"(gptr));
}
__device__ __forceinline__ void cp16z(uint32_t saddr, const void* gptr, int srcsz) {
    asm volatile("cp.async.cg.shared.global [%0], [%1], 16, %2;\n"
                 :: "r"(saddr), "l"(gptr), "r"(srcsz));
}
__device__ __forceinline__ void cp_commit() {
    asm volatile("cp.async.commit_group;\n");
}

// ---------------------------------------------------------------------------
// Kernel 0: W_out [c][ci*9+kw] -> g_wt[kw][c][ci]  (fp16)
// ---------------------------------------------------------------------------
__global__ void wt_kernel(const float* __restrict__ W) {
    int idx = blockIdx.x * 256 + threadIdx.x;
    if (idx < 9 * 64 * 256) {
        int ci = idx & 255;
        int c  = (idx >> 8) & 63;
        int kw = idx >> 14;
        g_wt[idx] = __float2half_rn(W[c * 2304 + ci * 9 + kw]);
    }
}

// ---------------------------------------------------------------------------
// Kernel 1: QKV projection, fp16 m16n8k16.
// Xh[l][c] (A, row-major), Wh[j][c] (B, col-major-by-row) staged fp16,
// 144B row pad (proven conflict-free). q pre-scaled 0.125; v transposed.
// ---------------------------------------------------------------------------
__global__ void __launch_bounds__(256) qkv_kernel(
                           const float* __restrict__ x,
                           const float* __restrict__ Wq,
                           const float* __restrict__ bq) {
    __shared__ __half Xh[64 * 72];     // [l][c], 144B rows
    __shared__ __half Wh[64 * 72];     // [j][c], 144B rows
    __shared__ __half Vt2[64 * 72];    // V transpose stage [d][l]
    char* Xc = (char*)Xh;
    char* Wc = (char*)Wh;
    const int bx = blockIdx.x;
    const int by = blockIdx.y;
    const int tid = threadIdx.x;
    const int warp = tid >> 5, lane = tid & 31;
    const int wr = warp >> 1, wc = warp & 1;
    const int r0 = wr * 16, c0 = wc * 32;
    const int grp = lane >> 2, qd = lane & 3;

    const int row_base = by * 64;
    const int n  = row_base / LL;
    const int l0 = row_base % LL;

    const float* xb = x + (size_t)n * CC * LL + l0;
#pragma unroll
    for (int it = 0; it < 16; it++) {
        int idx = tid + it * 256;
        int c = idx >> 6, ll = idx & 63;
        Xh[ll * 72 + c] = __float2half_rn(xb[c * LL + ll]);
    }
    const float* wb = Wq + bx * 64;
#pragma unroll
    for (int it = 0; it < 16; it++) {
        int idx = tid + it * 256;
        int c = idx >> 6, j = idx & 63;
        Wh[j * 72 + c] = __float2half_rn(wb[c * 768 + j]);
    }
    __syncthreads();

    float acc[4][4] = {};
#pragma unroll
    for (int kk = 0; kk < 4; kk++) {
        uint32_t ao = (uint32_t)((r0 + grp) * 144 + kk * 32 + qd * 4);
        uint32_t a[4];
        a[0] = *(const uint32_t*)(Xc + ao);
        a[1] = *(const uint32_t*)(Xc + ao + 8 * 144);
        a[2] = *(const uint32_t*)(Xc + ao + 16);
        a[3] = *(const uint32_t*)(Xc + ao + 8 * 144 + 16);
#pragma unroll
        for (int ns = 0; ns < 4; ns++) {
            uint32_t bo = (uint32_t)((c0 + ns * 8 + grp) * 144 + kk * 32 + qd * 4);
            uint32_t b0 = *(const uint32_t*)(Wc + bo);
            uint32_t b1 = *(const uint32_t*)(Wc + bo + 16);
            mma_f16(acc[ns], a, b0, b1);
        }
    }

    const int part = bx >> 2;
    const int h    = bx & 3;
    const int nh   = n * HH + h;

    if (part == 2) {
        // stage V transposed in smem, then coalesced fp16 store to [nh][d][L]
#pragma unroll
        for (int ns = 0; ns < 4; ns++) {
            int d = c0 + ns * 8 + qd * 2;
            float bb0 = bq[bx * 64 + d];
            float bb1 = bq[bx * 64 + d + 1];
            int la = r0 + grp, lb = la + 8;
            Vt2[(d)     * 72 + la] = __float2half_rn(acc[ns][0] + bb0);
            Vt2[(d + 1) * 72 + la] = __float2half_rn(acc[ns][1] + bb1);
            Vt2[(d)     * 72 + lb] = __float2half_rn(acc[ns][2] + bb0);
            Vt2[(d + 1) * 72 + lb] = __float2half_rn(acc[ns][3] + bb1);
        }
        __syncthreads();
        __half2* gv2 = (__half2*)g_v;
#pragma unroll
        for (int it = 0; it < 8; it++) {
            int idx = tid + it * 256;
            int d = idx >> 5, lh = idx & 31;
            __half2 hv = *(__half2*)&Vt2[d * 72 + lh * 2];
            gv2[(((size_t)nh * 64 + d) * LL + l0) / 2 + lh] = hv;
        }
    } else {
        const float scale = (part == 0) ? 0.125f : 1.f;
        __half2* dst2 = (__half2*)((part == 0) ? g_q : g_k);
        const int lA = l0 + r0 + grp;
        const int lB = lA + 8;
#pragma unroll
        for (int ns = 0; ns < 4; ns++) {
            int d = c0 + ns * 8 + qd * 2;
            float bb0 = bq[bx * 64 + d];
            float bb1 = bq[bx * 64 + d + 1];
            __half2 hA = __floats2half2_rn((acc[ns][0] + bb0) * scale,
                                           (acc[ns][1] + bb1) * scale);
            __half2 hB = __floats2half2_rn((acc[ns][2] + bb0) * scale,
                                           (acc[ns][3] + bb1) * scale);
            dst2[(((size_t)nh * LL + lA) * 64 + d) >> 1] = hA;
            dst2[(((size_t)nh * LL + lB) * 64 + d) >> 1] = hB;
        }
    }
}

// ---------------------------------------------------------------------------
// Kernel 2: fp16 flash attention (proven R12; byte-identical).
// ---------------------------------------------------------------------------
#define ROWB 144
#define ASM_Q 0
#define ASM_K 18432
#define ASM_V 36864
#define ASM_P 55296
#define ASM_TOT 73728
#define KVBUF 9216
#define OP2 88

extern __shared__ char attn_smc[];
__global__ void __launch_bounds__(256) attn_kernel() {
    char* smc = attn_smc;
    const uint32_t smb = (uint32_t)__cvta_generic_to_shared(smc);
    const int qb = blockIdx.x, nh = blockIdx.y;
    const int tid = threadIdx.x;
    const int warp = tid >> 5, lane = tid & 31;
    const int grp = lane >> 2, qd = lane & 3;
    const int q_base = (qb * 128 <= LL - 128) ? qb * 128 : (LL - 128);

    const char* qsrc = (const char*)(g_q + ((size_t)nh * LL + q_base) * 64);
    const char* ksrc = (const char*)(g_k + (size_t)nh * LL * 64);
    const char* vsrc = (const char*)(g_v + (size_t)nh * 64 * LL);

#pragma unroll
    for (int it = 0; it < 4; it++) {
        int idx = tid + it * 256;
        int r = idx >> 3, c = idx & 7;
        cp16(smb + ASM_Q + r * ROWB + c * 16, qsrc + r * 128 + c * 16);
    }
#pragma unroll
    for (int it = 0; it < 2; it++) {
        int idx = tid + it * 256;
        int r = idx >> 3, c = idx & 7;
        cp16(smb + ASM_K + r * ROWB + c * 16, ksrc + r * 128 + c * 16);
    }
#pragma unroll
    for (int it = 0; it < 2; it++) {
        int idx = tid + it * 256;
        int r = idx >> 3, c = idx & 7;
        cp16(smb + ASM_V + r * ROWB + c * 16, vsrc + (size_t)r * (LL * 2) + c * 16);
    }
    cp_commit();
#pragma unroll
    for (int it = 0; it < 2; it++) {
        int idx = tid + it * 256;
        int r = idx >> 3, c = idx & 7;
        cp16(smb + ASM_K + KVBUF + r * ROWB + c * 16,
             ksrc + 128 * 64 + r * 128 + c * 16);
        cp16(smb + ASM_V + KVBUF + r * ROWB + c * 16,
             vsrc + (size_t)r * (LL * 2) + 128 + c * 16);
    }
    cp_commit();
    asm volatile("cp.async.wait_group 1;\n");
    __syncthreads();

    uint32_t qfrag[4][4];
    {
        const uint32_t qr = (uint32_t)((warp * 16 + grp) * ROWB);
#pragma unroll
        for (int kk = 0; kk < 4; kk++) {
            uint32_t base = (uint32_t)(ASM_Q) + qr + kk * 32 + qd * 4;
            qfrag[kk][0] = *(const uint32_t*)(smc + base);
            qfrag[kk][1] = *(const uint32_t*)(smc + base + 8 * ROWB);
            qfrag[kk][2] = *(const uint32_t*)(smc + base + 16);
            qfrag[kk][3] = *(const uint32_t*)(smc + base + 8 * ROWB + 16);
        }
    }

    float oacc[8][4] = {};
    float l0 = 0.f, l1 = 0.f;
    const uint32_t pw = (uint32_t)(ASM_P + warp * 16 * ROWB);

    for (int t = 0; t < 25; t++) {
        const uint32_t kb = (uint32_t)(ASM_K + (t & 1) * KVBUF);
        const uint32_t vb = (uint32_t)(ASM_V + (t & 1) * KVBUF);

        float sacc[8][4] = {};
#pragma unroll
        for (int kk = 0; kk < 4; kk++) {
#pragma unroll
            for (int ns = 0; ns < 8; ns++) {
                uint32_t ba = kb + (ns * 8 + grp) * ROWB + kk * 32 + qd * 4;
                uint32_t b0 = *(const uint32_t*)(smc + ba);
                uint32_t b1 = *(const uint32_t*)(smc + ba + 16);
                mma_f16(sacc[ns], qfrag[kk], b0, b1);
            }
        }

#pragma unroll
        for (int ns = 0; ns < 8; ns++) {
            float p0 = __expf(sacc[ns][0] - 8.f);
            float p1 = __expf(sacc[ns][1] - 8.f);
            float p2 = __expf(sacc[ns][2] - 8.f);
            float p3 = __expf(sacc[ns][3] - 8.f);
            l0 += p0 + p1;
            l1 += p2 + p3;
            uint32_t po = pw + grp * ROWB + ns * 16 + qd * 4;
            *(uint32_t*)(smc + po)            = h2bits(p0, p1);
            *(uint32_t*)(smc + po + 8 * ROWB) = h2bits(p2, p3);
        }
        __syncwarp();

#pragma unroll
        for (int kk = 0; kk < 4; kk++) {
            uint32_t pa = pw + grp * ROWB + kk * 32 + qd * 4;
            uint32_t a[4];
            a[0] = *(const uint32_t*)(smc + pa);
            a[1] = *(const uint32_t*)(smc + pa + 8 * ROWB);
            a[2] = *(const uint32_t*)(smc + pa + 16);
            a[3] = *(const uint32_t*)(smc + pa + 8 * ROWB + 16);
#pragma unroll
            for (int ns = 0; ns < 8; ns++) {
                uint32_t ba = vb + (ns * 8 + grp) * ROWB + kk * 32 + qd * 4;
                uint32_t b0 = *(const uint32_t*)(smc + ba);
                uint32_t b1 = *(const uint32_t*)(smc + ba + 16);
                mma_f16(oacc[ns], a, b0, b1);
            }
        }
        __syncwarp();

        __syncthreads();
        if (t + 2 <= 24) {
            const char* kp = ksrc + (size_t)(t + 2) * 64 * 128;
            const char* vp = vsrc + (size_t)(t + 2) * 128;
            uint32_t kd = (uint32_t)(ASM_K + (t & 1) * KVBUF);
            uint32_t vd = (uint32_t)(ASM_V + (t & 1) * KVBUF);
#pragma unroll
            for (int it = 0; it < 2; it++) {
                int idx = tid + it * 256;
                int r = idx >> 3, c = idx & 7;
                cp16(smb + kd + r * ROWB + c * 16, kp + r * 128 + c * 16);
                cp16(smb + vd + r * ROWB + c * 16, vp + (size_t)r * (LL * 2) + c * 16);
            }
            cp_commit();
        }
        if (t + 1 <= 24) {
            if (t + 2 <= 24) asm volatile("cp.async.wait_group 1;\n");
            else             asm volatile("cp.async.wait_group 0;\n");
            __syncthreads();
        }
    }

    l0 += __shfl_xor_sync(0xFFFFFFFFu, l0, 1);
    l0 += __shfl_xor_sync(0xFFFFFFFFu, l0, 2);
    l1 += __shfl_xor_sync(0xFFFFFFFFu, l1, 1);
    l1 += __shfl_xor_sync(0xFFFFFFFFu, l1, 2);
    const float linv0 = 1.f / l0;
    const float linv1 = 1.f / l1;

    __syncthreads();
    __half* Oth = (__half*)smc;   // [128 l][OP2 d]
    {
        int la = warp * 16 + grp, lb = la + 8;
#pragma unroll
        for (int ns = 0; ns < 8; ns++) {
            int d = ns * 8 + qd * 2;
            *(__half2*)&Oth[la * OP2 + d] =
                __floats2half2_rn(oacc[ns][0] * linv0, oacc[ns][1] * linv0);
            *(__half2*)&Oth[lb * OP2 + d] =
                __floats2half2_rn(oacc[ns][2] * linv1, oacc[ns][3] * linv1);
        }
    }
    __syncthreads();

    const int n = nh >> 2, h4 = nh & 3;
    char* ob = (char*)(g_o + ((size_t)n * LL + q_base) * HD + h4 * 64);
#pragma unroll
    for (int it = 0; it < 4; it++) {
        int idx = tid + it * 256;
        int l = idx >> 3, c8 = idx & 7;
        *(float4*)(ob + (size_t)l * (HD * 2) + c8 * 16) =
            *(const float4*)((char*)Oth + l * (OP2 * 2) + c8 * 16);
    }
}

// ---------------------------------------------------------------------------
// Kernel 3: (1,9) conv + BN1 + res(x) + relu  FUSED WITH  1x1 conv + BN2 +
// res(y) + relu -> out. fp16 m16n8k16 throughout; residual y stays in regs
// (fp32-exact; both GEMMs share the same warp-tile mapping).
// ---------------------------------------------------------------------------
#define CROW 80                        // conv buffer row bytes
#define CBUF (64 * CROW)               // 5120 B per buffer
#define YROW 144                       // ff stage row bytes (72 halves)
extern __shared__ char conv_smc[];
__global__ void __launch_bounds__(256) conv_kernel(
                            const float* __restrict__ x,
                            const float* __restrict__ bias,
                            const float* __restrict__ g1,
                            const float* __restrict__ be1,
                            const float* __restrict__ mu1,
                            const float* __restrict__ va1,
                            const float* __restrict__ Wff,
                            const float* __restrict__ bff,
                            const float* __restrict__ g2,
                            const float* __restrict__ be2,
                            const float* __restrict__ mu2,
                            const float* __restrict__ va2,
                            float* __restrict__ out) {
    char* smc = conv_smc;
    const uint32_t smb = (uint32_t)__cvta_generic_to_shared(smc);
    const uint32_t ASMA = 0;              // [2][64 ch][CROW]
    const uint32_t ASMB = 2 * CBUF;       // [2][64 sp][CROW]
    const uint32_t ASMY = 4 * CBUF;       // [64 sp][YROW]  fp16 y (B of ff)
    const uint32_t ASMW = ASMY + 64*YROW; // [64 c][YROW]   fp16 Wff (A of ff)

    const int tid = threadIdx.x;
    const int sbase = blockIdx.x * 64;
    const int warp = tid >> 5, lane = tid & 31;
    const int wr = warp >> 1, wc = warp & 1;
    const int r0 = wr * 16, c0 = wc * 32;
    const int grp = lane >> 2, qd = lane & 3;

    // stage Wff fp16 [c][ci] (A operand of ff; row-major)
#pragma unroll
    for (int it = 0; it < 16; it++) {
        int idx = tid + it * 256;
        int c = idx >> 6, ci = idx & 63;
        *(__half*)(smc + ASMW + c * YROW + ci * 2) =
            __float2half_rn(Wff[c * 64 + ci]);
    }

    // load-thread geometry: row = tid>>2 (0..63), 16B chunk = tid&3
    const int lrow = tid >> 2;
    const int lc16 = tid & 3;
    const int s = sbase + lrow;
    const int n = s / LL;
    const int rem = s - n * LL;
    const int t = rem / VV;
    const int v = rem - t * VV;
    const char* bsrc0 = (const char*)(g_o + ((size_t)n * LL + rem - 4) * HD);

    auto prefetch = [&](int kb, int buf) {
        const int kw = kb >> 3;
        const int cibase = (kb & 7) * 32;
        const char* asrc = (const char*)(g_wt + ((size_t)(kw * 64 + lrow)) * 256
                                         + cibase) + lc16 * 16;
        cp16(smb + ASMA + buf * CBUF + lrow * CROW + lc16 * 16, asrc);
        const int vi = v + kw - 4;
        const int oksz = (vi >= 0 && vi < VV) ? 16 : 0;
        const char* bsrc = bsrc0 + (size_t)kw * (HD * 2) + cibase * 2 + lc16 * 16;
        cp16z(smb + ASMB + buf * CBUF + lrow * CROW + lc16 * 16, bsrc, oksz);
        cp_commit();
    };

    prefetch(0, 0);
    float acc[4][4] = {};

    for (int kb = 0; kb < 72; kb++) {
        const int cur = kb & 1;
        __syncthreads();
        if (kb < 71) {
            prefetch(kb + 1, cur ^ 1);
            asm volatile("cp.async.wait_group 1;\n");
        } else {
            asm volatile("cp.async.wait_group 0;\n");
        }
        __syncthreads();

        const char* Ac = smc + ASMA + cur * CBUF;
        const char* Bc = smc + ASMB + cur * CBUF;
#pragma unroll
        for (int kk = 0; kk < 2; kk++) {
            uint32_t ao = (uint32_t)((r0 + grp) * CROW + kk * 32 + qd * 4);
            uint32_t a[4];
            a[0] = *(const uint32_t*)(Ac + ao);
            a[1] = *(const uint32_t*)(Ac + ao + 8 * CROW);
            a[2] = *(const uint32_t*)(Ac + ao + 16);
            a[3] = *(const uint32_t*)(Ac + ao + 8 * CROW + 16);
#pragma unroll
            for (int ns = 0; ns < 4; ns++) {
                uint32_t bo = (uint32_t)((c0 + ns * 8 + grp) * CROW + kk * 32 + qd * 4);
                uint32_t b0 = *(const uint32_t*)(Bc + bo);
                uint32_t b1 = *(const uint32_t*)(Bc + bo + 16);
                mma_f16(acc[ns], a, b0, b1);
            }
        }
    }

    // ---- epilogue 1: y = relu(bn1(conv+bias) + x); keep in regs + stage fp16
    const int cA = r0 + grp, cB = cA + 8;
    float yreg[4][4];
    {
        float invA = g1[cA] * rsqrtf(va1[cA] + 1e-5f);
        float addA = be1[cA] - mu1[cA] * invA + bias[cA] * invA;
        float invB = g1[cB] * rsqrtf(va1[cB] + 1e-5f);
        float addB = be1[cB] - mu1[cB] * invB + bias[cB] * invB;
#pragma unroll
        for (int ns = 0; ns < 4; ns++) {
#pragma unroll
            for (int jj = 0; jj < 2; jj++) {
                int col = c0 + ns * 8 + qd * 2 + jj;
                int ss = sbase + col;
                int nn2 = ss / LL;
                int rem2 = ss - nn2 * LL;
                float xA = x[((size_t)(nn2 * CC + cA)) * LL + rem2];
                float xB = x[((size_t)(nn2 * CC + cB)) * LL + rem2];
                float yA = fmaxf(acc[ns][jj]     * invA + addA + xA, 0.f);
                float yB = fmaxf(acc[ns][jj + 2] * invB + addB + xB, 0.f);
                yreg[ns][jj]     = yA;
                yreg[ns][jj + 2] = yB;
                // stage y as fp16 B operand: Yh[sp][ci]
                *(__half*)(smc + ASMY + col * YROW + cA * 2) = __float2half_rn(yA);
                *(__half*)(smc + ASMY + col * YROW + cB * 2) = __float2half_rn(yB);
            }
        }
    }
    __syncthreads();

    // ---- ff GEMM: z[c][sp] = sum_ci Wff[c][ci] * y[sp][ci] ----
    float fac[4][4] = {};
#pragma unroll
    for (int kk = 0; kk < 4; kk++) {
        uint32_t ao = (uint32_t)(ASMW + (r0 + grp) * YROW + kk * 32 + qd * 4);
        uint32_t a[4];
        a[0] = *(const uint32_t*)(smc + ao);
        a[1] = *(const uint32_t*)(smc + ao + 8 * YROW);
        a[2] = *(const uint32_t*)(smc + ao + 16);
        a[3] = *(const uint32_t*)(smc + ao + 8 * YROW + 16);
#pragma unroll
        for (int ns = 0; ns < 4; ns++) {
            uint32_t bo = (uint32_t)(ASMY + (c0 + ns * 8 + grp) * YROW + kk * 32 + qd * 4);
            uint32_t b0 = *(const uint32_t*)(smc + bo);
            uint32_t b1 = *(const uint32_t*)(smc + bo + 16);
            mma_f16(fac[ns], a, b0, b1);
        }
    }

    // ---- epilogue 2: out = relu(bn2(z + bff) + y)  (y residual from regs) --
    {
        float invA = g2[cA] * rsqrtf(va2[cA] + 1e-5f);
        float addA = be2[cA] - mu2[cA] * invA + bff[cA] * invA;
        float invB = g2[cB] * rsqrtf(va2[cB] + 1e-5f);
        float addB = be2[cB] - mu2[cB] * invB + bff[cB] * invB;
#pragma unroll
        for (int ns = 0; ns < 4; ns++) {
#pragma unroll
            for (int jj = 0; jj < 2; jj++) {
                int ss = sbase + c0 + ns * 8 + qd * 2 + jj;
                int nn2 = ss / LL;
                int rem2 = ss - nn2 * LL;
                float zA = fac[ns][jj]     * invA + addA + yreg[ns][jj];
                float zB = fac[ns][jj + 2] * invB + addB + yreg[ns][jj + 2];
                out[((size_t)(nn2 * CC + cA)) * LL + rem2] = fmaxf(zA, 0.f);
                out[((size_t)(nn2 * CC + cB)) * LL + rem2] = fmaxf(zB, 0.f);
            }
        }
    }
}

// ---------------------------------------------------------------------------
extern "C" void kernel_launch(void* const* d_in, const int* in_sizes, int n_in,
                              void* d_out, int out_size) {
    const float* x     = (const float*)d_in[0];
    const float* W_qkv = (const float*)d_in[1];
    const float* b_qkv = (const float*)d_in[2];
    const float* W_out = (const float*)d_in[3];
    const float* b_out = (const float*)d_in[4];
    const float* g1    = (const float*)d_in[5];
    const float* be1   = (const float*)d_in[6];
    const float* mu1   = (const float*)d_in[7];
    const float* va1   = (const float*)d_in[8];
    const float* W_ff  = (const float*)d_in[9];
    const float* b_ff  = (const float*)d_in[10];
    const float* g2    = (const float*)d_in[11];
    const float* be2   = (const float*)d_in[12];
    const float* mu2   = (const float*)d_in[13];
    const float* va2   = (const float*)d_in[14];
    float* out = (float*)d_out;

    cudaFuncSetAttribute(attn_kernel,
                         cudaFuncAttributeMaxDynamicSharedMemorySize, ASM_TOT);
    const int CONV_SMEM = 4 * CBUF + 2 * 64 * YROW;   // 20480 + 18432 = 38912
    cudaFuncSetAttribute(conv_kernel,
                         cudaFuncAttributeMaxDynamicSharedMemorySize, CONV_SMEM);

    wt_kernel<<<576, 256>>>(W_out);
    qkv_kernel<<<dim3(12, 400), 256>>>(x, W_qkv, b_qkv);
    attn_kernel<<<dim3(13, 64), 256, ASM_TOT>>>();
    conv_kernel<<<400, 256, CONV_SMEM>>>(x, b_out, g1, be1, mu1, va1,
                                         W_ff, b_ff, g2, be2, mu2, va2, out);
}

// round 14
// speedup vs baseline: 2.1657x; 1.1325x over previous
#include <cuda_runtime.h>
#include <cuda_fp16.h>
#include <math.h>
#include <stdint.h>

// Problem constants
#define NB 16      // batch
#define CC 64      // channels
#define TT 64      // time
#define VV 25      // vertices
#define HH 4       // heads
#define DD 64      // head dim
#define LL (TT*VV) // 1600 tokens
#define HD (HH*DD) // 256

// Scratch (device globals; no runtime allocation allowed)
__device__ __half g_q[NB*HH*LL*DD];   // [nh][l][d], pre-scaled by 0.125*log2e
__device__ __half g_k[NB*HH*LL*DD];   // [nh][l][d]
__device__ __half g_v[NB*HH*DD*LL];   // [nh][d][l]  (TRANSPOSED)
__device__ __half g_o[NB*LL*HD];      // attention out, [n][l][ci]  (fp16)
__device__ __half g_wt[9*64*256];     // W_out as [kw][c][ci]  (fp16)

// ---- fp16 mma m16n8k16 ------------------------------------------------------
__device__ __forceinline__ void mma_f16(float c[4], const uint32_t a[4],
                                        uint32_t b0, uint32_t b1) {
    asm("mma.sync.aligned.m16n8k16.row.col.f32.f16.f16.f32 "
        "{%0,%1,%2,%3},{%4,%5,%6,%7},{%8,%9},{%0,%1,%2,%3};"
        : "+f"(c[0]), "+f"(c[1]), "+f"(c[2]), "+f"(c[3])
        : "r"(a[0]), "r"(a[1]), "r"(a[2]), "r"(a[3]), "r"(b0), "r"(b1));
}
__device__ __forceinline__ uint32_t h2bits(float lo, float hi) {
    __half2 h = __floats2half2_rn(lo, hi);
    return *(uint32_t*)&h;
}
__device__ __forceinline__ float ex2(float v) {
    float r; asm("ex2.approx.ftz.f32 %0, %1;" : "=f"(r) : "f"(v)); return r;
}

// ---- cp.async helpers -------------------------------------------------------
__device__ __forceinline__ void cp16(uint32_t saddr, const void* gptr) {
    asm volatile("cp.async.cg.shared.global [%0], [%1], 16;\n"
                 :: "r"(saddr), "l"(gptr));
}
__device__ __forceinline__ void cp16z(uint32_t saddr, const void* gptr, int srcsz) {
    asm volatile("cp.async.cg.shared.global [%0], [%1], 16, %2;\n"
                 :: "r"(saddr), "l"(gptr), "r"(srcsz));
}
__device__ __forceinline__ void cp_commit() {
    asm volatile("cp.async.commit_group;\n");
}

// ---------------------------------------------------------------------------
// Kernel 0: W_out [c][ci*9+kw] -> g_wt[kw][c][ci]  (fp16)
// ---------------------------------------------------------------------------
__global__ void wt_kernel(const float* __restrict__ W) {
    int idx = blockIdx.x * 256 + threadIdx.x;
    if (idx < 9 * 64 * 256) {
        int ci = idx & 255;
        int c  = (idx >> 8) & 63;
        int kw = idx >> 14;
        g_wt[idx] = __float2half_rn(W[c * 2304 + ci * 9 + kw]);
    }
}

// ---------------------------------------------------------------------------
// Kernel 1: QKV projection, fp16 m16n8k16 (proven R13).
// q pre-scaled by 0.125*log2(e) for exp2 softmax; v transposed.
// ---------------------------------------------------------------------------
__global__ void __launch_bounds__(256) qkv_kernel(
                           const float* __restrict__ x,
                           const float* __restrict__ Wq,
                           const float* __restrict__ bq) {
    __shared__ __half Xh[64 * 72];     // [l][c], 144B rows
    __shared__ __half Wh[64 * 72];     // [j][c], 144B rows
    __shared__ __half Vt2[64 * 72];    // V transpose stage [d][l]
    char* Xc = (char*)Xh;
    char* Wc = (char*)Wh;
    const int bx = blockIdx.x;
    const int by = blockIdx.y;
    const int tid = threadIdx.x;
    const int warp = tid >> 5, lane = tid & 31;
    const int wr = warp >> 1, wc = warp & 1;
    const int r0 = wr * 16, c0 = wc * 32;
    const int grp = lane >> 2, qd = lane & 3;

    const int row_base = by * 64;
    const int n  = row_base / LL;
    const int l0 = row_base % LL;

    const float* xb = x + (size_t)n * CC * LL + l0;
#pragma unroll
    for (int it = 0; it < 16; it++) {
        int idx = tid + it * 256;
        int c = idx >> 6, ll = idx & 63;
        Xh[ll * 72 + c] = __float2half_rn(xb[c * LL + ll]);
    }
    const float* wb = Wq + bx * 64;
#pragma unroll
    for (int it = 0; it < 16; it++) {
        int idx = tid + it * 256;
        int c = idx >> 6, j = idx & 63;
        Wh[j * 72 + c] = __float2half_rn(wb[c * 768 + j]);
    }
    __syncthreads();

    float acc[4][4] = {};
#pragma unroll
    for (int kk = 0; kk < 4; kk++) {
        uint32_t ao = (uint32_t)((r0 + grp) * 144 + kk * 32 + qd * 4);
        uint32_t a[4];
        a[0] = *(const uint32_t*)(Xc + ao);
        a[1] = *(const uint32_t*)(Xc + ao + 8 * 144);
        a[2] = *(const uint32_t*)(Xc + ao + 16);
        a[3] = *(const uint32_t*)(Xc + ao + 8 * 144 + 16);
#pragma unroll
        for (int ns = 0; ns < 4; ns++) {
            uint32_t bo = (uint32_t)((c0 + ns * 8 + grp) * 144 + kk * 32 + qd * 4);
            uint32_t b0 = *(const uint32_t*)(Wc + bo);
            uint32_t b1 = *(const uint32_t*)(Wc + bo + 16);
            mma_f16(acc[ns], a, b0, b1);
        }
    }

    const int part = bx >> 2;
    const int h    = bx & 3;
    const int nh   = n * HH + h;

    if (part == 2) {
#pragma unroll
        for (int ns = 0; ns < 4; ns++) {
            int d = c0 + ns * 8 + qd * 2;
            float bb0 = bq[bx * 64 + d];
            float bb1 = bq[bx * 64 + d + 1];
            int la = r0 + grp, lb = la + 8;
            Vt2[(d)     * 72 + la] = __float2half_rn(acc[ns][0] + bb0);
            Vt2[(d + 1) * 72 + la] = __float2half_rn(acc[ns][1] + bb1);
            Vt2[(d)     * 72 + lb] = __float2half_rn(acc[ns][2] + bb0);
            Vt2[(d + 1) * 72 + lb] = __float2half_rn(acc[ns][3] + bb1);
        }
        __syncthreads();
        __half2* gv2 = (__half2*)g_v;
#pragma unroll
        for (int it = 0; it < 8; it++) {
            int idx = tid + it * 256;
            int d = idx >> 5, lh = idx & 31;
            __half2 hv = *(__half2*)&Vt2[d * 72 + lh * 2];
            gv2[(((size_t)nh * 64 + d) * LL + l0) / 2 + lh] = hv;
        }
    } else {
        // q scale folds 1/sqrt(D)=0.125 AND log2(e) so softmax is raw exp2
        const float scale = (part == 0) ? (0.125f * 1.44269504f) : 1.f;
        __half2* dst2 = (__half2*)((part == 0) ? g_q : g_k);
        const int lA = l0 + r0 + grp;
        const int lB = lA + 8;
#pragma unroll
        for (int ns = 0; ns < 4; ns++) {
            int d = c0 + ns * 8 + qd * 2;
            float bb0 = bq[bx * 64 + d];
            float bb1 = bq[bx * 64 + d + 1];
            __half2 hA = __floats2half2_rn((acc[ns][0] + bb0) * scale,
                                           (acc[ns][1] + bb1) * scale);
            __half2 hB = __floats2half2_rn((acc[ns][2] + bb0) * scale,
                                           (acc[ns][3] + bb1) * scale);
            dst2[(((size_t)nh * LL + lA) * 64 + d) >> 1] = hA;
            dst2[(((size_t)nh * LL + lB) * 64 + d) >> 1] = hB;
        }
    }
}

// ---------------------------------------------------------------------------
// Kernel 2: fp16 flash attention. NEW: P stays in registers — the S C-frag is
// bit-compatible with the PV A-frag (h2bits pack), so no P smem round-trip,
// no syncwarps, smem drops to 55.3 KB. Softmax = raw exp2 (scale pre-folded).
// ---------------------------------------------------------------------------
#define ROWB 144
#define ASM_Q 0
#define ASM_K 18432
#define ASM_V 36864
#define ASM_TOT 55296
#define KVBUF 9216
#define OP2 88
#define ESHIFT 11.5415603f   // 8*log2(e); cancels in normalization

extern __shared__ char attn_smc[];
__global__ void __launch_bounds__(256) attn_kernel() {
    char* smc = attn_smc;
    const uint32_t smb = (uint32_t)__cvta_generic_to_shared(smc);
    const int qb = blockIdx.x, nh = blockIdx.y;
    const int tid = threadIdx.x;
    const int warp = tid >> 5, lane = tid & 31;
    const int grp = lane >> 2, qd = lane & 3;
    const int q_base = (qb * 128 <= LL - 128) ? qb * 128 : (LL - 128);

    const char* qsrc = (const char*)(g_q + ((size_t)nh * LL + q_base) * 64);
    const char* ksrc = (const char*)(g_k + (size_t)nh * LL * 64);
    const char* vsrc = (const char*)(g_v + (size_t)nh * 64 * LL);

#pragma unroll
    for (int it = 0; it < 4; it++) {
        int idx = tid + it * 256;
        int r = idx >> 3, c = idx & 7;
        cp16(smb + ASM_Q + r * ROWB + c * 16, qsrc + r * 128 + c * 16);
    }
#pragma unroll
    for (int it = 0; it < 2; it++) {
        int idx = tid + it * 256;
        int r = idx >> 3, c = idx & 7;
        cp16(smb + ASM_K + r * ROWB + c * 16, ksrc + r * 128 + c * 16);
    }
#pragma unroll
    for (int it = 0; it < 2; it++) {
        int idx = tid + it * 256;
        int r = idx >> 3, c = idx & 7;
        cp16(smb + ASM_V + r * ROWB + c * 16, vsrc + (size_t)r * (LL * 2) + c * 16);
    }
    cp_commit();
#pragma unroll
    for (int it = 0; it < 2; it++) {
        int idx = tid + it * 256;
        int r = idx >> 3, c = idx & 7;
        cp16(smb + ASM_K + KVBUF + r * ROWB + c * 16,
             ksrc + 128 * 64 + r * 128 + c * 16);
        cp16(smb + ASM_V + KVBUF + r * ROWB + c * 16,
             vsrc + (size_t)r * (LL * 2) + 128 + c * 16);
    }
    cp_commit();
    asm volatile("cp.async.wait_group 1;\n");
    __syncthreads();

    uint32_t qfrag[4][4];
    {
        const uint32_t qr = (uint32_t)((warp * 16 + grp) * ROWB);
#pragma unroll
        for (int kk = 0; kk < 4; kk++) {
            uint32_t base = (uint32_t)(ASM_Q) + qr + kk * 32 + qd * 4;
            qfrag[kk][0] = *(const uint32_t*)(smc + base);
            qfrag[kk][1] = *(const uint32_t*)(smc + base + 8 * ROWB);
            qfrag[kk][2] = *(const uint32_t*)(smc + base + 16);
            qfrag[kk][3] = *(const uint32_t*)(smc + base + 8 * ROWB + 16);
        }
    }

    float oacc[8][4] = {};
    float l0 = 0.f, l1 = 0.f;

    for (int t = 0; t < 25; t++) {
        const uint32_t kb = (uint32_t)(ASM_K + (t & 1) * KVBUF);
        const uint32_t vb = (uint32_t)(ASM_V + (t & 1) * KVBUF);

        // ---- S = Q @ K^T ----
        float sacc[8][4] = {};
#pragma unroll
        for (int kk = 0; kk < 4; kk++) {
#pragma unroll
            for (int ns = 0; ns < 8; ns++) {
                uint32_t ba = kb + (ns * 8 + grp) * ROWB + kk * 32 + qd * 4;
                uint32_t b0 = *(const uint32_t*)(smc + ba);
                uint32_t b1 = *(const uint32_t*)(smc + ba + 16);
                mma_f16(sacc[ns], qfrag[kk], b0, b1);
            }
        }

        // ---- softmax: p = exp2(s - ESHIFT), stays in registers ----
#pragma unroll
        for (int ns = 0; ns < 8; ns++) {
            float p0 = ex2(sacc[ns][0] - ESHIFT);
            float p1 = ex2(sacc[ns][1] - ESHIFT);
            float p2 = ex2(sacc[ns][2] - ESHIFT);
            float p3 = ex2(sacc[ns][3] - ESHIFT);
            l0 += p0 + p1;
            l1 += p2 + p3;
            sacc[ns][0] = p0; sacc[ns][1] = p1;
            sacc[ns][2] = p2; sacc[ns][3] = p3;
        }

        // ---- O += P @ V : P A-frags packed directly from S C-frags ----
#pragma unroll
        for (int kk = 0; kk < 4; kk++) {
            uint32_t a[4];
            a[0] = h2bits(sacc[2*kk][0],     sacc[2*kk][1]);
            a[1] = h2bits(sacc[2*kk][2],     sacc[2*kk][3]);
            a[2] = h2bits(sacc[2*kk + 1][0], sacc[2*kk + 1][1]);
            a[3] = h2bits(sacc[2*kk + 1][2], sacc[2*kk + 1][3]);
#pragma unroll
            for (int ns = 0; ns < 8; ns++) {
                uint32_t ba = vb + (ns * 8 + grp) * ROWB + kk * 32 + qd * 4;
                uint32_t b0 = *(const uint32_t*)(smc + ba);
                uint32_t b1 = *(const uint32_t*)(smc + ba + 16);
                mma_f16(oacc[ns], a, b0, b1);
            }
        }

        __syncthreads();                       // all warps done with buf t
        if (t + 2 <= 24) {                     // prefetch t+2 into buf t&1
            const char* kp = ksrc + (size_t)(t + 2) * 64 * 128;
            const char* vp = vsrc + (size_t)(t + 2) * 128;
            uint32_t kd = (uint32_t)(ASM_K + (t & 1) * KVBUF);
            uint32_t vd = (uint32_t)(ASM_V + (t & 1) * KVBUF);
#pragma unroll
            for (int it = 0; it < 2; it++) {
                int idx = tid + it * 256;
                int r = idx >> 3, c = idx & 7;
                cp16(smb + kd + r * ROWB + c * 16, kp + r * 128 + c * 16);
                cp16(smb + vd + r * ROWB + c * 16, vp + (size_t)r * (LL * 2) + c * 16);
            }
            cp_commit();
        }
        if (t + 1 <= 24) {
            if (t + 2 <= 24) asm volatile("cp.async.wait_group 1;\n");
            else             asm volatile("cp.async.wait_group 0;\n");
            __syncthreads();
        }
    }

    // ---- reduce row sums; stage O fp16 [l][d]; 128B-row stores ----
    l0 += __shfl_xor_sync(0xFFFFFFFFu, l0, 1);
    l0 += __shfl_xor_sync(0xFFFFFFFFu, l0, 2);
    l1 += __shfl_xor_sync(0xFFFFFFFFu, l1, 1);
    l1 += __shfl_xor_sync(0xFFFFFFFFu, l1, 2);
    const float linv0 = 1.f / l0;
    const float linv1 = 1.f / l1;

    __syncthreads();
    __half* Oth = (__half*)smc;   // [128 l][OP2 d]
    {
        int la = warp * 16 + grp, lb = la + 8;
#pragma unroll
        for (int ns = 0; ns < 8; ns++) {
            int d = ns * 8 + qd * 2;
            *(__half2*)&Oth[la * OP2 + d] =
                __floats2half2_rn(oacc[ns][0] * linv0, oacc[ns][1] * linv0);
            *(__half2*)&Oth[lb * OP2 + d] =
                __floats2half2_rn(oacc[ns][2] * linv1, oacc[ns][3] * linv1);
        }
    }
    __syncthreads();

    const int n = nh >> 2, h4 = nh & 3;
    char* ob = (char*)(g_o + ((size_t)n * LL + q_base) * HD + h4 * 64);
#pragma unroll
    for (int it = 0; it < 4; it++) {
        int idx = tid + it * 256;
        int l = idx >> 3, c8 = idx & 7;
        *(float4*)(ob + (size_t)l * (HD * 2) + c8 * 16) =
            *(const float4*)((char*)Oth + l * (OP2 * 2) + c8 * 16);
    }
}

// ---------------------------------------------------------------------------
// Kernel 3: (1,9) conv + BN1 + res(x) + relu FUSED WITH 1x1 conv + BN2 +
// res(y) + relu -> out (proven R13, byte-identical).
// ---------------------------------------------------------------------------
#define CROW 80
#define CBUF (64 * CROW)
#define YROW 144
extern __shared__ char conv_smc[];
__global__ void __launch_bounds__(256) conv_kernel(
                            const float* __restrict__ x,
                            const float* __restrict__ bias,
                            const float* __restrict__ g1,
                            const float* __restrict__ be1,
                            const float* __restrict__ mu1,
                            const float* __restrict__ va1,
                            const float* __restrict__ Wff,
                            const float* __restrict__ bff,
                            const float* __restrict__ g2,
                            const float* __restrict__ be2,
                            const float* __restrict__ mu2,
                            const float* __restrict__ va2,
                            float* __restrict__ out) {
    char* smc = conv_smc;
    const uint32_t smb = (uint32_t)__cvta_generic_to_shared(smc);
    const uint32_t ASMA = 0;
    const uint32_t ASMB = 2 * CBUF;
    const uint32_t ASMY = 4 * CBUF;
    const uint32_t ASMW = ASMY + 64*YROW;

    const int tid = threadIdx.x;
    const int sbase = blockIdx.x * 64;
    const int warp = tid >> 5, lane = tid & 31;
    const int wr = warp >> 1, wc = warp & 1;
    const int r0 = wr * 16, c0 = wc * 32;
    const int grp = lane >> 2, qd = lane & 3;

#pragma unroll
    for (int it = 0; it < 16; it++) {
        int idx = tid + it * 256;
        int c = idx >> 6, ci = idx & 63;
        *(__half*)(smc + ASMW + c * YROW + ci * 2) =
            __float2half_rn(Wff[c * 64 + ci]);
    }

    const int lrow = tid >> 2;
    const int lc16 = tid & 3;
    const int s = sbase + lrow;
    const int n = s / LL;
    const int rem = s - n * LL;
    const int t = rem / VV;
    const int v = rem - t * VV;
    const char* bsrc0 = (const char*)(g_o + ((size_t)n * LL + rem - 4) * HD);

    auto prefetch = [&](int kb, int buf) {
        const int kw = kb >> 3;
        const int cibase = (kb & 7) * 32;
        const char* asrc = (const char*)(g_wt + ((size_t)(kw * 64 + lrow)) * 256
                                         + cibase) + lc16 * 16;
        cp16(smb + ASMA + buf * CBUF + lrow * CROW + lc16 * 16, asrc);
        const int vi = v + kw - 4;
        const int oksz = (vi >= 0 && vi < VV) ? 16 : 0;
        const char* bsrc = bsrc0 + (size_t)kw * (HD * 2) + cibase * 2 + lc16 * 16;
        cp16z(smb + ASMB + buf * CBUF + lrow * CROW + lc16 * 16, bsrc, oksz);
        cp_commit();
    };

    prefetch(0, 0);
    float acc[4][4] = {};

    for (int kb = 0; kb < 72; kb++) {
        const int cur = kb & 1;
        __syncthreads();
        if (kb < 71) {
            prefetch(kb + 1, cur ^ 1);
            asm volatile("cp.async.wait_group 1;\n");
        } else {
            asm volatile("cp.async.wait_group 0;\n");
        }
        __syncthreads();

        const char* Ac = smc + ASMA + cur * CBUF;
        const char* Bc = smc + ASMB + cur * CBUF;
#pragma unroll
        for (int kk = 0; kk < 2; kk++) {
            uint32_t ao = (uint32_t)((r0 + grp) * CROW + kk * 32 + qd * 4);
            uint32_t a[4];
            a[0] = *(const uint32_t*)(Ac + ao);
            a[1] = *(const uint32_t*)(Ac + ao + 8 * CROW);
            a[2] = *(const uint32_t*)(Ac + ao + 16);
            a[3] = *(const uint32_t*)(Ac + ao + 8 * CROW + 16);
#pragma unroll
            for (int ns = 0; ns < 4; ns++) {
                uint32_t bo = (uint32_t)((c0 + ns * 8 + grp) * CROW + kk * 32 + qd * 4);
                uint32_t b0 = *(const uint32_t*)(Bc + bo);
                uint32_t b1 = *(const uint32_t*)(Bc + bo + 16);
                mma_f16(acc[ns], a, b0, b1);
            }
        }
    }

    const int cA = r0 + grp, cB = cA + 8;
    float yreg[4][4];
    {
        float invA = g1[cA] * rsqrtf(va1[cA] + 1e-5f);
        float addA = be1[cA] - mu1[cA] * invA + bias[cA] * invA;
        float invB = g1[cB] * rsqrtf(va1[cB] + 1e-5f);
        float addB = be1[cB] - mu1[cB] * invB + bias[cB] * invB;
#pragma unroll
        for (int ns = 0; ns < 4; ns++) {
#pragma unroll
            for (int jj = 0; jj < 2; jj++) {
                int col = c0 + ns * 8 + qd * 2 + jj;
                int ss = sbase + col;
                int nn2 = ss / LL;
                int rem2 = ss - nn2 * LL;
                float xA = x[((size_t)(nn2 * CC + cA)) * LL + rem2];
                float xB = x[((size_t)(nn2 * CC + cB)) * LL + rem2];
                float yA = fmaxf(acc[ns][jj]     * invA + addA + xA, 0.f);
                float yB = fmaxf(acc[ns][jj + 2] * invB + addB + xB, 0.f);
                yreg[ns][jj]     = yA;
                yreg[ns][jj + 2] = yB;
                *(__half*)(smc + ASMY + col * YROW + cA * 2) = __float2half_rn(yA);
                *(__half*)(smc + ASMY + col * YROW + cB * 2) = __float2half_rn(yB);
            }
        }
    }
    __syncthreads();

    float fac[4][4] = {};
#pragma unroll
    for (int kk = 0; kk < 4; kk++) {
        uint32_t ao = (uint32_t)(ASMW + (r0 + grp) * YROW + kk * 32 + qd * 4);
        uint32_t a[4];
        a[0] = *(const uint32_t*)(smc + ao);
        a[1] = *(const uint32_t*)(smc + ao + 8 * YROW);
        a[2] = *(const uint32_t*)(smc + ao + 16);
        a[3] = *(const uint32_t*)(smc + ao + 8 * YROW + 16);
#pragma unroll
        for (int ns = 0; ns < 4; ns++) {
            uint32_t bo = (uint32_t)(ASMY + (c0 + ns * 8 + grp) * YROW + kk * 32 + qd * 4);
            uint32_t b0 = *(const uint32_t*)(smc + bo);
            uint32_t b1 = *(const uint32_t*)(smc + bo + 16);
            mma_f16(fac[ns], a, b0, b1);
        }
    }

    {
        float invA = g2[cA] * rsqrtf(va2[cA] + 1e-5f);
        float addA = be2[cA] - mu2[cA] * invA + bff[cA] * invA;
        float invB = g2[cB] * rsqrtf(va2[cB] + 1e-5f);
        float addB = be2[cB] - mu2[cB] * invB + bff[cB] * invB;
#pragma unroll
        for (int ns = 0; ns < 4; ns++) {
#pragma unroll
            for (int jj = 0; jj < 2; jj++) {
                int ss = sbase + c0 + ns * 8 + qd * 2 + jj;
                int nn2 = ss / LL;
                int rem2 = ss - nn2 * LL;
                float zA = fac[ns][jj]     * invA + addA + yreg[ns][jj];
                float zB = fac[ns][jj + 2] * invB + addB + yreg[ns][jj + 2];
                out[((size_t)(nn2 * CC + cA)) * LL + rem2] = fmaxf(zA, 0.f);
                out[((size_t)(nn2 * CC + cB)) * LL + rem2] = fmaxf(zB, 0.f);
            }
        }
    }
}

// ---------------------------------------------------------------------------
extern "C" void kernel_launch(void* const* d_in, const int* in_sizes, int n_in,
                              void* d_out, int out_size) {
    const float* x     = (const float*)d_in[0];
    const float* W_qkv = (const float*)d_in[1];
    const float* b_qkv = (const float*)d_in[2];
    const float* W_out = (const float*)d_in[3];
    const float* b_out = (const float*)d_in[4];
    const float* g1    = (const float*)d_in[5];
    const float* be1   = (const float*)d_in[6];
    const float* mu1   = (const float*)d_in[7];
    const float* va1   = (const float*)d_in[8];
    const float* W_ff  = (const float*)d_in[9];
    const float* b_ff  = (const float*)d_in[10];
    const float* g2    = (const float*)d_in[11];
    const float* be2   = (const float*)d_in[12];
    const float* mu2   = (const float*)d_in[13];
    const float* va2   = (const float*)d_in[14];
    float* out = (float*)d_out;

    cudaFuncSetAttribute(attn_kernel,
                         cudaFuncAttributeMaxDynamicSharedMemorySize, ASM_TOT);
    const int CONV_SMEM = 4 * CBUF + 2 * 64 * YROW;   // 38912 B
    cudaFuncSetAttribute(conv_kernel,
                         cudaFuncAttributeMaxDynamicSharedMemorySize, CONV_SMEM);

    wt_kernel<<<576, 256>>>(W_out);
    qkv_kernel<<<dim3(12, 400), 256>>>(x, W_qkv, b_qkv);
    attn_kernel<<<dim3(13, 64), 256, ASM_TOT>>>();
    conv_kernel<<<400, 256, CONV_SMEM>>>(x, b_out, g1, be1, mu1, va1,
                                         W_ff, b_ff, g2, be2, mu2, va2, out);
}

// round 15
// speedup vs baseline: 2.2392x; 1.0339x over previous
#include <cuda_runtime.h>
#include <cuda_fp16.h>
#include <math.h>
#include <stdint.h>

// Problem constants
#define NB 16      // batch
#define CC 64      // channels
#define TT 64      // time
#define VV 25      // vertices
#define HH 4       // heads
#define DD 64      // head dim
#define LL (TT*VV) // 1600 tokens
#define HD (HH*DD) // 256

// Scratch (device globals; no runtime allocation allowed)
__device__ __half g_q[NB*HH*LL*DD];   // [nh][l][d], pre-scaled by 0.125*log2e
__device__ __half g_k[NB*HH*LL*DD];   // [nh][l][d]
__device__ __half g_v[NB*HH*DD*LL];   // [nh][d][l]  (TRANSPOSED)
__device__ __half g_o[NB*LL*HD];      // attention out, [n][l][ci]  (fp16)
__device__ __half g_wt[9*64*256];     // W_out as [kw][c][ci]  (fp16)

// ---- fp16 mma m16n8k16 ------------------------------------------------------
__device__ __forceinline__ void mma_f16(float c[4], const uint32_t a[4],
                                        uint32_t b0, uint32_t b1) {
    asm("mma.sync.aligned.m16n8k16.row.col.f32.f16.f16.f32 "
        "{%0,%1,%2,%3},{%4,%5,%6,%7},{%8,%9},{%0,%1,%2,%3};"
        : "+f"(c[0]), "+f"(c[1]), "+f"(c[2]), "+f"(c[3])
        : "r"(a[0]), "r"(a[1]), "r"(a[2]), "r"(a[3]), "r"(b0), "r"(b1));
}
__device__ __forceinline__ uint32_t h2bits(float lo, float hi) {
    __half2 h = __floats2half2_rn(lo, hi);
    return *(uint32_t*)&h;
}
__device__ __forceinline__ float ex2(float v) {
    float r; asm("ex2.approx.ftz.f32 %0, %1;" : "=f"(r) : "f"(v)); return r;
}

// ---- cp.async helpers -------------------------------------------------------
__device__ __forceinline__ void cp16(uint32_t saddr, const void* gptr) {
    asm volatile("cp.async.cg.shared.global [%0], [%1], 16;\n"
                 :: "r"(saddr), "l"(gptr));
}
__device__ __forceinline__ void cp16z(uint32_t saddr, const void* gptr, int srcsz) {
    asm volatile("cp.async.cg.shared.global [%0], [%1], 16, %2;\n"
                 :: "r"(saddr), "l"(gptr), "r"(srcsz));
}
__device__ __forceinline__ void cp_commit() {
    asm volatile("cp.async.commit_group;\n");
}

// ---------------------------------------------------------------------------
// Kernel 0: W_out [c][ci*9+kw] -> g_wt[kw][c][ci]  (fp16)
// ---------------------------------------------------------------------------
__global__ void wt_kernel(const float* __restrict__ W) {
    int idx = blockIdx.x * 256 + threadIdx.x;
    if (idx < 9 * 64 * 256) {
        int ci = idx & 255;
        int c  = (idx >> 8) & 63;
        int kw = idx >> 14;
        g_wt[idx] = __float2half_rn(W[c * 2304 + ci * 9 + kw]);
    }
}

// ---------------------------------------------------------------------------
// Kernel 1: QKV projection, fp16 m16n8k16 (proven R13/R14).
// ---------------------------------------------------------------------------
__global__ void __launch_bounds__(256) qkv_kernel(
                           const float* __restrict__ x,
                           const float* __restrict__ Wq,
                           const float* __restrict__ bq) {
    __shared__ __half Xh[64 * 72];     // [l][c], 144B rows
    __shared__ __half Wh[64 * 72];     // [j][c], 144B rows
    __shared__ __half Vt2[64 * 72];    // V transpose stage [d][l]
    char* Xc = (char*)Xh;
    char* Wc = (char*)Wh;
    const int bx = blockIdx.x;
    const int by = blockIdx.y;
    const int tid = threadIdx.x;
    const int warp = tid >> 5, lane = tid & 31;
    const int wr = warp >> 1, wc = warp & 1;
    const int r0 = wr * 16, c0 = wc * 32;
    const int grp = lane >> 2, qd = lane & 3;

    const int row_base = by * 64;
    const int n  = row_base / LL;
    const int l0 = row_base % LL;

    const float* xb = x + (size_t)n * CC * LL + l0;
#pragma unroll
    for (int it = 0; it < 16; it++) {
        int idx = tid + it * 256;
        int c = idx >> 6, ll = idx & 63;
        Xh[ll * 72 + c] = __float2half_rn(xb[c * LL + ll]);
    }
    const float* wb = Wq + bx * 64;
#pragma unroll
    for (int it = 0; it < 16; it++) {
        int idx = tid + it * 256;
        int c = idx >> 6, j = idx & 63;
        Wh[j * 72 + c] = __float2half_rn(wb[c * 768 + j]);
    }
    __syncthreads();

    float acc[4][4] = {};
#pragma unroll
    for (int kk = 0; kk < 4; kk++) {
        uint32_t ao = (uint32_t)((r0 + grp) * 144 + kk * 32 + qd * 4);
        uint32_t a[4];
        a[0] = *(const uint32_t*)(Xc + ao);
        a[1] = *(const uint32_t*)(Xc + ao + 8 * 144);
        a[2] = *(const uint32_t*)(Xc + ao + 16);
        a[3] = *(const uint32_t*)(Xc + ao + 8 * 144 + 16);
#pragma unroll
        for (int ns = 0; ns < 4; ns++) {
            uint32_t bo = (uint32_t)((c0 + ns * 8 + grp) * 144 + kk * 32 + qd * 4);
            uint32_t b0 = *(const uint32_t*)(Wc + bo);
            uint32_t b1 = *(const uint32_t*)(Wc + bo + 16);
            mma_f16(acc[ns], a, b0, b1);
        }
    }

    const int part = bx >> 2;
    const int h    = bx & 3;
    const int nh   = n * HH + h;

    if (part == 2) {
#pragma unroll
        for (int ns = 0; ns < 4; ns++) {
            int d = c0 + ns * 8 + qd * 2;
            float bb0 = bq[bx * 64 + d];
            float bb1 = bq[bx * 64 + d + 1];
            int la = r0 + grp, lb = la + 8;
            Vt2[(d)     * 72 + la] = __float2half_rn(acc[ns][0] + bb0);
            Vt2[(d + 1) * 72 + la] = __float2half_rn(acc[ns][1] + bb1);
            Vt2[(d)     * 72 + lb] = __float2half_rn(acc[ns][2] + bb0);
            Vt2[(d + 1) * 72 + lb] = __float2half_rn(acc[ns][3] + bb1);
        }
        __syncthreads();
        __half2* gv2 = (__half2*)g_v;
#pragma unroll
        for (int it = 0; it < 8; it++) {
            int idx = tid + it * 256;
            int d = idx >> 5, lh = idx & 31;
            __half2 hv = *(__half2*)&Vt2[d * 72 + lh * 2];
            gv2[(((size_t)nh * 64 + d) * LL + l0) / 2 + lh] = hv;
        }
    } else {
        const float scale = (part == 0) ? (0.125f * 1.44269504f) : 1.f;
        __half2* dst2 = (__half2*)((part == 0) ? g_q : g_k);
        const int lA = l0 + r0 + grp;
        const int lB = lA + 8;
#pragma unroll
        for (int ns = 0; ns < 4; ns++) {
            int d = c0 + ns * 8 + qd * 2;
            float bb0 = bq[bx * 64 + d];
            float bb1 = bq[bx * 64 + d + 1];
            __half2 hA = __floats2half2_rn((acc[ns][0] + bb0) * scale,
                                           (acc[ns][1] + bb1) * scale);
            __half2 hB = __floats2half2_rn((acc[ns][2] + bb0) * scale,
                                           (acc[ns][3] + bb1) * scale);
            dst2[(((size_t)nh * LL + lA) * 64 + d) >> 1] = hA;
            dst2[(((size_t)nh * LL + lB) * 64 + d) >> 1] = hB;
        }
    }
}

// ---------------------------------------------------------------------------
// Kernel 2: fp16 flash attention. NEW: 4 warps (128 threads), each warp owns
// 32 q-rows (2 m-tiles) x all 64 keys — every B-fragment load is shared
// across 2 m-tiles, halving smem bytes per output. P stays in registers.
// ---------------------------------------------------------------------------
#define ROWB 144
#define ASM_Q 0
#define ASM_K 18432
#define ASM_V 36864
#define ASM_TOT 55296
#define KVBUF 9216
#define OP2 88
#define ESHIFT 11.5415603f   // 8*log2(e); cancels in normalization

extern __shared__ char attn_smc[];
__global__ void __launch_bounds__(128) attn_kernel() {
    char* smc = attn_smc;
    const uint32_t smb = (uint32_t)__cvta_generic_to_shared(smc);
    const int qb = blockIdx.x, nh = blockIdx.y;
    const int tid = threadIdx.x;
    const int warp = tid >> 5, lane = tid & 31;
    const int grp = lane >> 2, qd = lane & 3;
    const int q_base = (qb * 128 <= LL - 128) ? qb * 128 : (LL - 128);

    const char* qsrc = (const char*)(g_q + ((size_t)nh * LL + q_base) * 64);
    const char* ksrc = (const char*)(g_k + (size_t)nh * LL * 64);
    const char* vsrc = (const char*)(g_v + (size_t)nh * 64 * LL);

#pragma unroll
    for (int it = 0; it < 8; it++) {           // Q: 128 rows x 8 chunks
        int idx = tid + it * 128;
        int r = idx >> 3, c = idx & 7;
        cp16(smb + ASM_Q + r * ROWB + c * 16, qsrc + r * 128 + c * 16);
    }
#pragma unroll
    for (int it = 0; it < 4; it++) {           // K0
        int idx = tid + it * 128;
        int r = idx >> 3, c = idx & 7;
        cp16(smb + ASM_K + r * ROWB + c * 16, ksrc + r * 128 + c * 16);
    }
#pragma unroll
    for (int it = 0; it < 4; it++) {           // V0
        int idx = tid + it * 128;
        int r = idx >> 3, c = idx & 7;
        cp16(smb + ASM_V + r * ROWB + c * 16, vsrc + (size_t)r * (LL * 2) + c * 16);
    }
    cp_commit();
#pragma unroll
    for (int it = 0; it < 4; it++) {           // K1 + V1
        int idx = tid + it * 128;
        int r = idx >> 3, c = idx & 7;
        cp16(smb + ASM_K + KVBUF + r * ROWB + c * 16,
             ksrc + 128 * 64 + r * 128 + c * 16);
        cp16(smb + ASM_V + KVBUF + r * ROWB + c * 16,
             vsrc + (size_t)r * (LL * 2) + 128 + c * 16);
    }
    cp_commit();
    asm volatile("cp.async.wait_group 1;\n");
    __syncthreads();

    // ---- persistent Q fragments: 2 m-tiles (rows warp*32 + 16*mt + grp/+8)
    uint32_t qfrag[2][4][4];
#pragma unroll
    for (int mt = 0; mt < 2; mt++) {
        const uint32_t qr = (uint32_t)((warp * 32 + mt * 16 + grp) * ROWB);
#pragma unroll
        for (int kk = 0; kk < 4; kk++) {
            uint32_t base = (uint32_t)(ASM_Q) + qr + kk * 32 + qd * 4;
            qfrag[mt][kk][0] = *(const uint32_t*)(smc + base);
            qfrag[mt][kk][1] = *(const uint32_t*)(smc + base + 8 * ROWB);
            qfrag[mt][kk][2] = *(const uint32_t*)(smc + base + 16);
            qfrag[mt][kk][3] = *(const uint32_t*)(smc + base + 8 * ROWB + 16);
        }
    }

    float oacc[2][8][4] = {};
    float lsum[2][2] = {};   // [mt][row-group (grp / grp+8)]

    for (int t = 0; t < 25; t++) {
        const uint32_t kb = (uint32_t)(ASM_K + (t & 1) * KVBUF);
        const uint32_t vb = (uint32_t)(ASM_V + (t & 1) * KVBUF);

        // ---- S = Q @ K^T : B frags loaded ONCE, used by both m-tiles ----
        float sacc[2][8][4] = {};
#pragma unroll
        for (int kk = 0; kk < 4; kk++) {
#pragma unroll
            for (int ns = 0; ns < 8; ns++) {
                uint32_t ba = kb + (ns * 8 + grp) * ROWB + kk * 32 + qd * 4;
                uint32_t b0 = *(const uint32_t*)(smc + ba);
                uint32_t b1 = *(const uint32_t*)(smc + ba + 16);
                mma_f16(sacc[0][ns], qfrag[0][kk], b0, b1);
                mma_f16(sacc[1][ns], qfrag[1][kk], b0, b1);
            }
        }

        // ---- softmax: p = exp2(s - ESHIFT), in registers ----
#pragma unroll
        for (int mt = 0; mt < 2; mt++) {
#pragma unroll
            for (int ns = 0; ns < 8; ns++) {
                float p0 = ex2(sacc[mt][ns][0] - ESHIFT);
                float p1 = ex2(sacc[mt][ns][1] - ESHIFT);
                float p2 = ex2(sacc[mt][ns][2] - ESHIFT);
                float p3 = ex2(sacc[mt][ns][3] - ESHIFT);
                lsum[mt][0] += p0 + p1;
                lsum[mt][1] += p2 + p3;
                sacc[mt][ns][0] = p0; sacc[mt][ns][1] = p1;
                sacc[mt][ns][2] = p2; sacc[mt][ns][3] = p3;
            }
        }

        // ---- O += P @ V : B frags shared across both m-tiles ----
#pragma unroll
        for (int kk = 0; kk < 4; kk++) {
            uint32_t a0[4], a1[4];
            a0[0] = h2bits(sacc[0][2*kk][0],     sacc[0][2*kk][1]);
            a0[1] = h2bits(sacc[0][2*kk][2],     sacc[0][2*kk][3]);
            a0[2] = h2bits(sacc[0][2*kk + 1][0], sacc[0][2*kk + 1][1]);
            a0[3] = h2bits(sacc[0][2*kk + 1][2], sacc[0][2*kk + 1][3]);
            a1[0] = h2bits(sacc[1][2*kk][0],     sacc[1][2*kk][1]);
            a1[1] = h2bits(sacc[1][2*kk][2],     sacc[1][2*kk][3]);
            a1[2] = h2bits(sacc[1][2*kk + 1][0], sacc[1][2*kk + 1][1]);
            a1[3] = h2bits(sacc[1][2*kk + 1][2], sacc[1][2*kk + 1][3]);
#pragma unroll
            for (int ns = 0; ns < 8; ns++) {
                uint32_t ba = vb + (ns * 8 + grp) * ROWB + kk * 32 + qd * 4;
                uint32_t b0 = *(const uint32_t*)(smc + ba);
                uint32_t b1 = *(const uint32_t*)(smc + ba + 16);
                mma_f16(oacc[0][ns], a0, b0, b1);
                mma_f16(oacc[1][ns], a1, b0, b1);
            }
        }

        __syncthreads();                       // all warps done with buf t
        if (t + 2 <= 24) {                     // prefetch t+2 into buf t&1
            const char* kp = ksrc + (size_t)(t + 2) * 64 * 128;
            const char* vp = vsrc + (size_t)(t + 2) * 128;
            uint32_t kd = (uint32_t)(ASM_K + (t & 1) * KVBUF);
            uint32_t vd = (uint32_t)(ASM_V + (t & 1) * KVBUF);
#pragma unroll
            for (int it = 0; it < 4; it++) {
                int idx = tid + it * 128;
                int r = idx >> 3, c = idx & 7;
                cp16(smb + kd + r * ROWB + c * 16, kp + r * 128 + c * 16);
                cp16(smb + vd + r * ROWB + c * 16, vp + (size_t)r * (LL * 2) + c * 16);
            }
            cp_commit();
        }
        if (t + 1 <= 24) {
            if (t + 2 <= 24) asm volatile("cp.async.wait_group 1;\n");
            else             asm volatile("cp.async.wait_group 0;\n");
            __syncthreads();
        }
    }

    // ---- reduce row sums; stage O fp16 [l][d]; 128B-row stores ----
#pragma unroll
    for (int mt = 0; mt < 2; mt++) {
#pragma unroll
        for (int rg = 0; rg < 2; rg++) {
            lsum[mt][rg] += __shfl_xor_sync(0xFFFFFFFFu, lsum[mt][rg], 1);
            lsum[mt][rg] += __shfl_xor_sync(0xFFFFFFFFu, lsum[mt][rg], 2);
        }
    }

    __syncthreads();
    __half* Oth = (__half*)smc;   // [128 l][OP2 d]
#pragma unroll
    for (int mt = 0; mt < 2; mt++) {
        float linv0 = 1.f / lsum[mt][0];
        float linv1 = 1.f / lsum[mt][1];
        int la = warp * 32 + mt * 16 + grp, lb = la + 8;
#pragma unroll
        for (int ns = 0; ns < 8; ns++) {
            int d = ns * 8 + qd * 2;
            *(__half2*)&Oth[la * OP2 + d] =
                __floats2half2_rn(oacc[mt][ns][0] * linv0, oacc[mt][ns][1] * linv0);
            *(__half2*)&Oth[lb * OP2 + d] =
                __floats2half2_rn(oacc[mt][ns][2] * linv1, oacc[mt][ns][3] * linv1);
        }
    }
    __syncthreads();

    const int n = nh >> 2, h4 = nh & 3;
    char* ob = (char*)(g_o + ((size_t)n * LL + q_base) * HD + h4 * 64);
#pragma unroll
    for (int it = 0; it < 8; it++) {
        int idx = tid + it * 128;
        int l = idx >> 3, c8 = idx & 7;
        *(float4*)(ob + (size_t)l * (HD * 2) + c8 * 16) =
            *(const float4*)((char*)Oth + l * (OP2 * 2) + c8 * 16);
    }
}

// ---------------------------------------------------------------------------
// Kernel 3: (1,9) conv + BN1 + res(x) + relu FUSED WITH 1x1 conv + BN2 +
// res(y) + relu -> out (proven R13/R14, byte-identical).
// ---------------------------------------------------------------------------
#define CROW 80
#define CBUF (64 * CROW)
#define YROW 144
extern __shared__ char conv_smc[];
__global__ void __launch_bounds__(256) conv_kernel(
                            const float* __restrict__ x,
                            const float* __restrict__ bias,
                            const float* __restrict__ g1,
                            const float* __restrict__ be1,
                            const float* __restrict__ mu1,
                            const float* __restrict__ va1,
                            const float* __restrict__ Wff,
                            const float* __restrict__ bff,
                            const float* __restrict__ g2,
                            const float* __restrict__ be2,
                            const float* __restrict__ mu2,
                            const float* __restrict__ va2,
                            float* __restrict__ out) {
    char* smc = conv_smc;
    const uint32_t smb = (uint32_t)__cvta_generic_to_shared(smc);
    const uint32_t ASMA = 0;
    const uint32_t ASMB = 2 * CBUF;
    const uint32_t ASMY = 4 * CBUF;
    const uint32_t ASMW = ASMY + 64*YROW;

    const int tid = threadIdx.x;
    const int sbase = blockIdx.x * 64;
    const int warp = tid >> 5, lane = tid & 31;
    const int wr = warp >> 1, wc = warp & 1;
    const int r0 = wr * 16, c0 = wc * 32;
    const int grp = lane >> 2, qd = lane & 3;

#pragma unroll
    for (int it = 0; it < 16; it++) {
        int idx = tid + it * 256;
        int c = idx >> 6, ci = idx & 63;
        *(__half*)(smc + ASMW + c * YROW + ci * 2) =
            __float2half_rn(Wff[c * 64 + ci]);
    }

    const int lrow = tid >> 2;
    const int lc16 = tid & 3;
    const int s = sbase + lrow;
    const int n = s / LL;
    const int rem = s - n * LL;
    const int t = rem / VV;
    const int v = rem - t * VV;
    const char* bsrc0 = (const char*)(g_o + ((size_t)n * LL + rem - 4) * HD);

    auto prefetch = [&](int kb, int buf) {
        const int kw = kb >> 3;
        const int cibase = (kb & 7) * 32;
        const char* asrc = (const char*)(g_wt + ((size_t)(kw * 64 + lrow)) * 256
                                         + cibase) + lc16 * 16;
        cp16(smb + ASMA + buf * CBUF + lrow * CROW + lc16 * 16, asrc);
        const int vi = v + kw - 4;
        const int oksz = (vi >= 0 && vi < VV) ? 16 : 0;
        const char* bsrc = bsrc0 + (size_t)kw * (HD * 2) + cibase * 2 + lc16 * 16;
        cp16z(smb + ASMB + buf * CBUF + lrow * CROW + lc16 * 16, bsrc, oksz);
        cp_commit();
    };

    prefetch(0, 0);
    float acc[4][4] = {};

    for (int kb = 0; kb < 72; kb++) {
        const int cur = kb & 1;
        __syncthreads();
        if (kb < 71) {
            prefetch(kb + 1, cur ^ 1);
            asm volatile("cp.async.wait_group 1;\n");
        } else {
            asm volatile("cp.async.wait_group 0;\n");
        }
        __syncthreads();

        const char* Ac = smc + ASMA + cur * CBUF;
        const char* Bc = smc + ASMB + cur * CBUF;
#pragma unroll
        for (int kk = 0; kk < 2; kk++) {
            uint32_t ao = (uint32_t)((r0 + grp) * CROW + kk * 32 + qd * 4);
            uint32_t a[4];
            a[0] = *(const uint32_t*)(Ac + ao);
            a[1] = *(const uint32_t*)(Ac + ao + 8 * CROW);
            a[2] = *(const uint32_t*)(Ac + ao + 16);
            a[3] = *(const uint32_t*)(Ac + ao + 8 * CROW + 16);
#pragma unroll
            for (int ns = 0; ns < 4; ns++) {
                uint32_t bo = (uint32_t)((c0 + ns * 8 + grp) * CROW + kk * 32 + qd * 4);
                uint32_t b0 = *(const uint32_t*)(Bc + bo);
                uint32_t b1 = *(const uint32_t*)(Bc + bo + 16);
                mma_f16(acc[ns], a, b0, b1);
            }
        }
    }

    const int cA = r0 + grp, cB = cA + 8;
    float yreg[4][4];
    {
        float invA = g1[cA] * rsqrtf(va1[cA] + 1e-5f);
        float addA = be1[cA] - mu1[cA] * invA + bias[cA] * invA;
        float invB = g1[cB] * rsqrtf(va1[cB] + 1e-5f);
        float addB = be1[cB] - mu1[cB] * invB + bias[cB] * invB;
#pragma unroll
        for (int ns = 0; ns < 4; ns++) {
#pragma unroll
            for (int jj = 0; jj < 2; jj++) {
                int col = c0 + ns * 8 + qd * 2 + jj;
                int ss = sbase + col;
                int nn2 = ss / LL;
                int rem2 = ss - nn2 * LL;
                float xA = x[((size_t)(nn2 * CC + cA)) * LL + rem2];
                float xB = x[((size_t)(nn2 * CC + cB)) * LL + rem2];
                float yA = fmaxf(acc[ns][jj]     * invA + addA + xA, 0.f);
                float yB = fmaxf(acc[ns][jj + 2] * invB + addB + xB, 0.f);
                yreg[ns][jj]     = yA;
                yreg[ns][jj + 2] = yB;
                *(__half*)(smc + ASMY + col * YROW + cA * 2) = __float2half_rn(yA);
                *(__half*)(smc + ASMY + col * YROW + cB * 2) = __float2half_rn(yB);
            }
        }
    }
    __syncthreads();

    float fac[4][4] = {};
#pragma unroll
    for (int kk = 0; kk < 4; kk++) {
        uint32_t ao = (uint32_t)(ASMW + (r0 + grp) * YROW + kk * 32 + qd * 4);
        uint32_t a[4];
        a[0] = *(const uint32_t*)(smc + ao);
        a[1] = *(const uint32_t*)(smc + ao + 8 * YROW);
        a[2] = *(const uint32_t*)(smc + ao + 16);
        a[3] = *(const uint32_t*)(smc + ao + 8 * YROW + 16);
#pragma unroll
        for (int ns = 0; ns < 4; ns++) {
            uint32_t bo = (uint32_t)(ASMY + (c0 + ns * 8 + grp) * YROW + kk * 32 + qd * 4);
            uint32_t b0 = *(const uint32_t*)(smc + bo);
            uint32_t b1 = *(const uint32_t*)(smc + bo + 16);
            mma_f16(fac[ns], a, b0, b1);
        }
    }

    {
        float invA = g2[cA] * rsqrtf(va2[cA] + 1e-5f);
        float addA = be2[cA] - mu2[cA] * invA + bff[cA] * invA;
        float invB = g2[cB] * rsqrtf(va2[cB] + 1e-5f);
        float addB = be2[cB] - mu2[cB] * invB + bff[cB] * invB;
#pragma unroll
        for (int ns = 0; ns < 4; ns++) {
#pragma unroll
            for (int jj = 0; jj < 2; jj++) {
                int ss = sbase + c0 + ns * 8 + qd * 2 + jj;
                int nn2 = ss / LL;
                int rem2 = ss - nn2 * LL;
                float zA = fac[ns][jj]     * invA + addA + yreg[ns][jj];
                float zB = fac[ns][jj + 2] * invB + addB + yreg[ns][jj + 2];
                out[((size_t)(nn2 * CC + cA)) * LL + rem2] = fmaxf(zA, 0.f);
                out[((size_t)(nn2 * CC + cB)) * LL + rem2] = fmaxf(zB, 0.f);
            }
        }
    }
}

// ---------------------------------------------------------------------------
extern "C" void kernel_launch(void* const* d_in, const int* in_sizes, int n_in,
                              void* d_out, int out_size) {
    const float* x     = (const float*)d_in[0];
    const float* W_qkv = (const float*)d_in[1];
    const float* b_qkv = (const float*)d_in[2];
    const float* W_out = (const float*)d_in[3];
    const float* b_out = (const float*)d_in[4];
    const float* g1    = (const float*)d_in[5];
    const float* be1   = (const float*)d_in[6];
    const float* mu1   = (const float*)d_in[7];
    const float* va1   = (const float*)d_in[8];
    const float* W_ff  = (const float*)d_in[9];
    const float* b_ff  = (const float*)d_in[10];
    const float* g2    = (const float*)d_in[11];
    const float* be2   = (const float*)d_in[12];
    const float* mu2   = (const float*)d_in[13];
    const float* va2   = (const float*)d_in[14];
    float* out = (float*)d_out;

    cudaFuncSetAttribute(attn_kernel,
                         cudaFuncAttributeMaxDynamicSharedMemorySize, ASM_TOT);
    const int CONV_SMEM = 4 * CBUF + 2 * 64 * YROW;   // 38912 B
    cudaFuncSetAttribute(conv_kernel,
                         cudaFuncAttributeMaxDynamicSharedMemorySize, CONV_SMEM);

    wt_kernel<<<576, 256>>>(W_out);
    qkv_kernel<<<dim3(12, 400), 256>>>(x, W_qkv, b_qkv);
    attn_kernel<<<dim3(13, 64), 128, ASM_TOT>>>();
    conv_kernel<<<400, 256, CONV_SMEM>>>(x, b_out, g1, be1, mu1, va1,
                                         W_ff, b_ff, g2, be2, mu2, va2, out);
}

// round 16
// speedup vs baseline: 2.3804x; 1.0630x over previous
#include <cuda_runtime.h>
#include <cuda_fp16.h>
#include <math.h>
#include <stdint.h>

// Problem constants
#define NB 16      // batch
#define CC 64      // channels
#define TT 64      // time
#define VV 25      // vertices
#define HH 4       // heads
#define DD 64      // head dim
#define LL (TT*VV) // 1600 tokens
#define HD (HH*DD) // 256

// Scratch (device globals; no runtime allocation allowed)
__device__ __half g_q[NB*HH*LL*DD];   // [nh][l][d], pre-scaled by 0.125*log2e
__device__ __half g_k[NB*HH*LL*DD];   // [nh][l][d]
__device__ __half g_v[NB*HH*DD*LL];   // [nh][d][l]  (TRANSPOSED)
__device__ __half g_o[NB*LL*HD];      // attention out, [n][l][ci]  (fp16)
__device__ __half g_wt[9*64*256];     // W_out as [kw][c][ci]  (fp16)
__device__ __half g_wq[768*64];       // W_qkv as [j][c]       (fp16)

// ---- fp16 mma m16n8k16 ------------------------------------------------------
__device__ __forceinline__ void mma_f16(float c[4], const uint32_t a[4],
                                        uint32_t b0, uint32_t b1) {
    asm("mma.sync.aligned.m16n8k16.row.col.f32.f16.f16.f32 "
        "{%0,%1,%2,%3},{%4,%5,%6,%7},{%8,%9},{%0,%1,%2,%3};"
        : "+f"(c[0]), "+f"(c[1]), "+f"(c[2]), "+f"(c[3])
        : "r"(a[0]), "r"(a[1]), "r"(a[2]), "r"(a[3]), "r"(b0), "r"(b1));
}
__device__ __forceinline__ uint32_t h2bits(float lo, float hi) {
    __half2 h = __floats2half2_rn(lo, hi);
    return *(uint32_t*)&h;
}
__device__ __forceinline__ float ex2(float v) {
    float r; asm("ex2.approx.ftz.f32 %0, %1;" : "=f"(r) : "f"(v)); return r;
}

// ---- cp.async helpers -------------------------------------------------------
__device__ __forceinline__ void cp16(uint32_t saddr, const void* gptr) {
    asm volatile("cp.async.cg.shared.global [%0], [%1], 16;\n"
                 :: "r"(saddr), "l"(gptr));
}
__device__ __forceinline__ void cp16z(uint32_t saddr, const void* gptr, int srcsz) {
    asm volatile("cp.async.cg.shared.global [%0], [%1], 16, %2;\n"
                 :: "r"(saddr), "l"(gptr), "r"(srcsz));
}
__device__ __forceinline__ void cp_commit() {
    asm volatile("cp.async.commit_group;\n");
}

// ---------------------------------------------------------------------------
// Kernel 0a: W_out [c][ci*9+kw] -> g_wt[kw][c][ci]  (fp16)
// ---------------------------------------------------------------------------
__global__ void wt_kernel(const float* __restrict__ W) {
    int idx = blockIdx.x * 256 + threadIdx.x;
    if (idx < 9 * 64 * 256) {
        int ci = idx & 255;
        int c  = (idx >> 8) & 63;
        int kw = idx >> 14;
        g_wt[idx] = __float2half_rn(W[c * 2304 + ci * 9 + kw]);
    }
}
// Kernel 0b: W_qkv [c][j] -> g_wq[j][c]  (fp16)
__global__ void wq_kernel(const float* __restrict__ W) {
    int idx = blockIdx.x * 256 + threadIdx.x;
    if (idx < 768 * 64) {
        int c = idx & 63;
        int j = idx >> 6;
        g_wq[idx] = __float2half_rn(W[c * 768 + j]);
    }
}

// ---------------------------------------------------------------------------
// Kernel 1: QKV projection. Grid 400; X tile loaded/converted ONCE per block,
// 12 W tiles streamed fp16 via double-buffered cp.async. fp16 m16n8k16.
// ---------------------------------------------------------------------------
__global__ void __launch_bounds__(256) qkv_kernel(
                           const float* __restrict__ x,
                           const float* __restrict__ bq) {
    __shared__ __half Xh[64 * 72];       // [l][c], 144B rows
    __shared__ __half Wh[2][64 * 72];    // [j][c], 144B rows, double buffer
    __shared__ __half Vt2[64 * 72];      // V transpose stage [d][l]
    char* Xc = (char*)Xh;
    const uint32_t whb = (uint32_t)__cvta_generic_to_shared(Wh);
    const int by = blockIdx.x;
    const int tid = threadIdx.x;
    const int warp = tid >> 5, lane = tid & 31;
    const int wr = warp >> 1, wcc = warp & 1;
    const int r0 = wr * 16, c0 = wcc * 32;
    const int grp = lane >> 2, qd = lane & 3;

    const int row_base = by * 64;
    const int n  = row_base / LL;
    const int l0 = row_base % LL;

    // W-tile prefetch geometry: row = tid>>3 (0..31 -> 2 iters), chunk tid&7
    const int wrow = tid >> 3, wch = tid & 7;
    auto prefW = [&](int jt, int buf) {
        const char* src = (const char*)g_wq + (size_t)jt * 64 * 128;
#pragma unroll
        for (int it = 0; it < 2; it++) {
            int r = wrow + it * 32;
            cp16(whb + (uint32_t)(buf * 9216 + r * 144 + wch * 16),
                 src + r * 128 + wch * 16);
        }
        cp_commit();
    };
    prefW(0, 0);

    // X tile: load fp32, convert, store [l][c] (once)
    const float* xb = x + (size_t)n * CC * LL + l0;
#pragma unroll
    for (int it = 0; it < 16; it++) {
        int idx = tid + it * 256;
        int c = idx >> 6, ll = idx & 63;
        Xh[ll * 72 + c] = __float2half_rn(xb[c * LL + ll]);
    }
    __syncthreads();

    // persistent X fragments
    uint32_t xfrag[4][4];
#pragma unroll
    for (int kk = 0; kk < 4; kk++) {
        uint32_t ao = (uint32_t)((r0 + grp) * 144 + kk * 32 + qd * 4);
        xfrag[kk][0] = *(const uint32_t*)(Xc + ao);
        xfrag[kk][1] = *(const uint32_t*)(Xc + ao + 8 * 144);
        xfrag[kk][2] = *(const uint32_t*)(Xc + ao + 16);
        xfrag[kk][3] = *(const uint32_t*)(Xc + ao + 8 * 144 + 16);
    }

    for (int jt = 0; jt < 12; jt++) {
        const int cur = jt & 1;
        __syncthreads();                  // all warps done reading buf cur^1
        if (jt < 11) {
            prefW(jt + 1, cur ^ 1);
            asm volatile("cp.async.wait_group 1;\n");
        } else {
            asm volatile("cp.async.wait_group 0;\n");
        }
        __syncthreads();

        const char* Wc = (const char*)&Wh[cur][0];
        float acc[4][4] = {};
#pragma unroll
        for (int kk = 0; kk < 4; kk++) {
#pragma unroll
            for (int ns = 0; ns < 4; ns++) {
                uint32_t bo = (uint32_t)((c0 + ns * 8 + grp) * 144 + kk * 32 + qd * 4);
                uint32_t b0 = *(const uint32_t*)(Wc + bo);
                uint32_t b1 = *(const uint32_t*)(Wc + bo + 16);
                mma_f16(acc[ns], xfrag[kk], b0, b1);
            }
        }

        const int part = jt >> 2;
        const int h    = jt & 3;
        const int nh   = n * HH + h;

        if (part == 2) {
#pragma unroll
            for (int ns = 0; ns < 4; ns++) {
                int d = c0 + ns * 8 + qd * 2;
                float bb0 = bq[jt * 64 + d];
                float bb1 = bq[jt * 64 + d + 1];
                int la = r0 + grp, lb = la + 8;
                Vt2[(d)     * 72 + la] = __float2half_rn(acc[ns][0] + bb0);
                Vt2[(d + 1) * 72 + la] = __float2half_rn(acc[ns][1] + bb1);
                Vt2[(d)     * 72 + lb] = __float2half_rn(acc[ns][2] + bb0);
                Vt2[(d + 1) * 72 + lb] = __float2half_rn(acc[ns][3] + bb1);
            }
            __syncthreads();
            __half2* gv2 = (__half2*)g_v;
#pragma unroll
            for (int it = 0; it < 8; it++) {
                int idx = tid + it * 256;
                int d = idx >> 5, lh = idx & 31;
                __half2 hv = *(__half2*)&Vt2[d * 72 + lh * 2];
                gv2[(((size_t)nh * 64 + d) * LL + l0) / 2 + lh] = hv;
            }
        } else {
            const float scale = (part == 0) ? (0.125f * 1.44269504f) : 1.f;
            __half2* dst2 = (__half2*)((part == 0) ? g_q : g_k);
            const int lA = l0 + r0 + grp;
            const int lB = lA + 8;
#pragma unroll
            for (int ns = 0; ns < 4; ns++) {
                int d = c0 + ns * 8 + qd * 2;
                float bb0 = bq[jt * 64 + d];
                float bb1 = bq[jt * 64 + d + 1];
                __half2 hA = __floats2half2_rn((acc[ns][0] + bb0) * scale,
                                               (acc[ns][1] + bb1) * scale);
                __half2 hB = __floats2half2_rn((acc[ns][2] + bb0) * scale,
                                               (acc[ns][3] + bb1) * scale);
                dst2[(((size_t)nh * LL + lA) * 64 + d) >> 1] = hA;
                dst2[(((size_t)nh * LL + lB) * 64 + d) >> 1] = hB;
            }
        }
    }
}

// ---------------------------------------------------------------------------
// Kernel 2: fp16 flash attention (proven R15, byte-identical).
// ---------------------------------------------------------------------------
#define ROWB 144
#define ASM_Q 0
#define ASM_K 18432
#define ASM_V 36864
#define ASM_TOT 55296
#define KVBUF 9216
#define OP2 88
#define ESHIFT 11.5415603f

extern __shared__ char attn_smc[];
__global__ void __launch_bounds__(128) attn_kernel() {
    char* smc = attn_smc;
    const uint32_t smb = (uint32_t)__cvta_generic_to_shared(smc);
    const int qb = blockIdx.x, nh = blockIdx.y;
    const int tid = threadIdx.x;
    const int warp = tid >> 5, lane = tid & 31;
    const int grp = lane >> 2, qd = lane & 3;
    const int q_base = (qb * 128 <= LL - 128) ? qb * 128 : (LL - 128);

    const char* qsrc = (const char*)(g_q + ((size_t)nh * LL + q_base) * 64);
    const char* ksrc = (const char*)(g_k + (size_t)nh * LL * 64);
    const char* vsrc = (const char*)(g_v + (size_t)nh * 64 * LL);

#pragma unroll
    for (int it = 0; it < 8; it++) {
        int idx = tid + it * 128;
        int r = idx >> 3, c = idx & 7;
        cp16(smb + ASM_Q + r * ROWB + c * 16, qsrc + r * 128 + c * 16);
    }
#pragma unroll
    for (int it = 0; it < 4; it++) {
        int idx = tid + it * 128;
        int r = idx >> 3, c = idx & 7;
        cp16(smb + ASM_K + r * ROWB + c * 16, ksrc + r * 128 + c * 16);
    }
#pragma unroll
    for (int it = 0; it < 4; it++) {
        int idx = tid + it * 128;
        int r = idx >> 3, c = idx & 7;
        cp16(smb + ASM_V + r * ROWB + c * 16, vsrc + (size_t)r * (LL * 2) + c * 16);
    }
    cp_commit();
#pragma unroll
    for (int it = 0; it < 4; it++) {
        int idx = tid + it * 128;
        int r = idx >> 3, c = idx & 7;
        cp16(smb + ASM_K + KVBUF + r * ROWB + c * 16,
             ksrc + 128 * 64 + r * 128 + c * 16);
        cp16(smb + ASM_V + KVBUF + r * ROWB + c * 16,
             vsrc + (size_t)r * (LL * 2) + 128 + c * 16);
    }
    cp_commit();
    asm volatile("cp.async.wait_group 1;\n");
    __syncthreads();

    uint32_t qfrag[2][4][4];
#pragma unroll
    for (int mt = 0; mt < 2; mt++) {
        const uint32_t qr = (uint32_t)((warp * 32 + mt * 16 + grp) * ROWB);
#pragma unroll
        for (int kk = 0; kk < 4; kk++) {
            uint32_t base = (uint32_t)(ASM_Q) + qr + kk * 32 + qd * 4;
            qfrag[mt][kk][0] = *(const uint32_t*)(smc + base);
            qfrag[mt][kk][1] = *(const uint32_t*)(smc + base + 8 * ROWB);
            qfrag[mt][kk][2] = *(const uint32_t*)(smc + base + 16);
            qfrag[mt][kk][3] = *(const uint32_t*)(smc + base + 8 * ROWB + 16);
        }
    }

    float oacc[2][8][4] = {};
    float lsum[2][2] = {};

    for (int t = 0; t < 25; t++) {
        const uint32_t kb = (uint32_t)(ASM_K + (t & 1) * KVBUF);
        const uint32_t vb = (uint32_t)(ASM_V + (t & 1) * KVBUF);

        float sacc[2][8][4] = {};
#pragma unroll
        for (int kk = 0; kk < 4; kk++) {
#pragma unroll
            for (int ns = 0; ns < 8; ns++) {
                uint32_t ba = kb + (ns * 8 + grp) * ROWB + kk * 32 + qd * 4;
                uint32_t b0 = *(const uint32_t*)(smc + ba);
                uint32_t b1 = *(const uint32_t*)(smc + ba + 16);
                mma_f16(sacc[0][ns], qfrag[0][kk], b0, b1);
                mma_f16(sacc[1][ns], qfrag[1][kk], b0, b1);
            }
        }

#pragma unroll
        for (int mt = 0; mt < 2; mt++) {
#pragma unroll
            for (int ns = 0; ns < 8; ns++) {
                float p0 = ex2(sacc[mt][ns][0] - ESHIFT);
                float p1 = ex2(sacc[mt][ns][1] - ESHIFT);
                float p2 = ex2(sacc[mt][ns][2] - ESHIFT);
                float p3 = ex2(sacc[mt][ns][3] - ESHIFT);
                lsum[mt][0] += p0 + p1;
                lsum[mt][1] += p2 + p3;
                sacc[mt][ns][0] = p0; sacc[mt][ns][1] = p1;
                sacc[mt][ns][2] = p2; sacc[mt][ns][3] = p3;
            }
        }

#pragma unroll
        for (int kk = 0; kk < 4; kk++) {
            uint32_t a0[4], a1[4];
            a0[0] = h2bits(sacc[0][2*kk][0],     sacc[0][2*kk][1]);
            a0[1] = h2bits(sacc[0][2*kk][2],     sacc[0][2*kk][3]);
            a0[2] = h2bits(sacc[0][2*kk + 1][0], sacc[0][2*kk + 1][1]);
            a0[3] = h2bits(sacc[0][2*kk + 1][2], sacc[0][2*kk + 1][3]);
            a1[0] = h2bits(sacc[1][2*kk][0],     sacc[1][2*kk][1]);
            a1[1] = h2bits(sacc[1][2*kk][2],     sacc[1][2*kk][3]);
            a1[2] = h2bits(sacc[1][2*kk + 1][0], sacc[1][2*kk + 1][1]);
            a1[3] = h2bits(sacc[1][2*kk + 1][2], sacc[1][2*kk + 1][3]);
#pragma unroll
            for (int ns = 0; ns < 8; ns++) {
                uint32_t ba = vb + (ns * 8 + grp) * ROWB + kk * 32 + qd * 4;
                uint32_t b0 = *(const uint32_t*)(smc + ba);
                uint32_t b1 = *(const uint32_t*)(smc + ba + 16);
                mma_f16(oacc[0][ns], a0, b0, b1);
                mma_f16(oacc[1][ns], a1, b0, b1);
            }
        }

        __syncthreads();
        if (t + 2 <= 24) {
            const char* kp = ksrc + (size_t)(t + 2) * 64 * 128;
            const char* vp = vsrc + (size_t)(t + 2) * 128;
            uint32_t kd = (uint32_t)(ASM_K + (t & 1) * KVBUF);
            uint32_t vd = (uint32_t)(ASM_V + (t & 1) * KVBUF);
#pragma unroll
            for (int it = 0; it < 4; it++) {
                int idx = tid + it * 128;
                int r = idx >> 3, c = idx & 7;
                cp16(smb + kd + r * ROWB + c * 16, kp + r * 128 + c * 16);
                cp16(smb + vd + r * ROWB + c * 16, vp + (size_t)r * (LL * 2) + c * 16);
            }
            cp_commit();
        }
        if (t + 1 <= 24) {
            if (t + 2 <= 24) asm volatile("cp.async.wait_group 1;\n");
            else             asm volatile("cp.async.wait_group 0;\n");
            __syncthreads();
        }
    }

#pragma unroll
    for (int mt = 0; mt < 2; mt++) {
#pragma unroll
        for (int rg = 0; rg < 2; rg++) {
            lsum[mt][rg] += __shfl_xor_sync(0xFFFFFFFFu, lsum[mt][rg], 1);
            lsum[mt][rg] += __shfl_xor_sync(0xFFFFFFFFu, lsum[mt][rg], 2);
        }
    }

    __syncthreads();
    __half* Oth = (__half*)smc;
#pragma unroll
    for (int mt = 0; mt < 2; mt++) {
        float linv0 = 1.f / lsum[mt][0];
        float linv1 = 1.f / lsum[mt][1];
        int la = warp * 32 + mt * 16 + grp, lb = la + 8;
#pragma unroll
        for (int ns = 0; ns < 8; ns++) {
            int d = ns * 8 + qd * 2;
            *(__half2*)&Oth[la * OP2 + d] =
                __floats2half2_rn(oacc[mt][ns][0] * linv0, oacc[mt][ns][1] * linv0);
            *(__half2*)&Oth[lb * OP2 + d] =
                __floats2half2_rn(oacc[mt][ns][2] * linv1, oacc[mt][ns][3] * linv1);
        }
    }
    __syncthreads();

    const int n = nh >> 2, h4 = nh & 3;
    char* ob = (char*)(g_o + ((size_t)n * LL + q_base) * HD + h4 * 64);
#pragma unroll
    for (int it = 0; it < 8; it++) {
        int idx = tid + it * 128;
        int l = idx >> 3, c8 = idx & 7;
        *(float4*)(ob + (size_t)l * (HD * 2) + c8 * 16) =
            *(const float4*)((char*)Oth + l * (OP2 * 2) + c8 * 16);
    }
}

// ---------------------------------------------------------------------------
// Kernel 3: fused conv+ff (R14 semantics) with 64-wide K chunks:
// 36 chunks (barriers halved), 16 MMAs/stage, 144B rows.
// ---------------------------------------------------------------------------
#define CROW2 144
#define CBUF2 (64 * CROW2)             // 9216 B per buffer
#define YROW 144
extern __shared__ char conv_smc[];
__global__ void __launch_bounds__(256) conv_kernel(
                            const float* __restrict__ x,
                            const float* __restrict__ bias,
                            const float* __restrict__ g1,
                            const float* __restrict__ be1,
                            const float* __restrict__ mu1,
                            const float* __restrict__ va1,
                            const float* __restrict__ Wff,
                            const float* __restrict__ bff,
                            const float* __restrict__ g2,
                            const float* __restrict__ be2,
                            const float* __restrict__ mu2,
                            const float* __restrict__ va2,
                            float* __restrict__ out) {
    char* smc = conv_smc;
    const uint32_t smb = (uint32_t)__cvta_generic_to_shared(smc);
    const uint32_t ASMA = 0;               // [2][64 ch][CROW2]
    const uint32_t ASMB = 2 * CBUF2;       // [2][64 sp][CROW2]
    const uint32_t ASMY = 4 * CBUF2;       // [64 sp][YROW]
    const uint32_t ASMW = ASMY + 64*YROW;  // [64 c][YROW]

    const int tid = threadIdx.x;
    const int sbase = blockIdx.x * 64;
    const int warp = tid >> 5, lane = tid & 31;
    const int wr = warp >> 1, wcc = warp & 1;
    const int r0 = wr * 16, c0 = wcc * 32;
    const int grp = lane >> 2, qd = lane & 3;

#pragma unroll
    for (int it = 0; it < 16; it++) {
        int idx = tid + it * 256;
        int c = idx >> 6, ci = idx & 63;
        *(__half*)(smc + ASMW + c * YROW + ci * 2) =
            __float2half_rn(Wff[c * 64 + ci]);
    }

    // load geometry: row = tid>>2 (0..63), chunks (tid&3) and (tid&3)+4
    const int lrow = tid >> 2;
    const int lc = tid & 3;
    const int s = sbase + lrow;
    const int n = s / LL;
    const int rem = s - n * LL;
    const int t = rem / VV;
    const int v = rem - t * VV;
    const char* bsrc0 = (const char*)(g_o + ((size_t)n * LL + rem - 4) * HD);

    auto prefetch = [&](int kb, int buf) {
        const int kw = kb >> 2;
        const int cibase = (kb & 3) * 64;
        const char* asrc = (const char*)(g_wt + ((size_t)(kw * 64 + lrow)) * 256
                                         + cibase);
        uint32_t ad = smb + ASMA + buf * CBUF2 + lrow * CROW2;
        cp16(ad + lc * 16,       asrc + lc * 16);
        cp16(ad + (lc + 4) * 16, asrc + (lc + 4) * 16);
        const int vi = v + kw - 4;
        const int oksz = (vi >= 0 && vi < VV) ? 16 : 0;
        const char* bsrc = bsrc0 + (size_t)kw * (HD * 2) + cibase * 2;
        uint32_t bd = smb + ASMB + buf * CBUF2 + lrow * CROW2;
        cp16z(bd + lc * 16,       bsrc + lc * 16,       oksz);
        cp16z(bd + (lc + 4) * 16, bsrc + (lc + 4) * 16, oksz);
        cp_commit();
    };

    prefetch(0, 0);
    float acc[4][4] = {};

    for (int kb = 0; kb < 36; kb++) {
        const int cur = kb & 1;
        __syncthreads();
        if (kb < 35) {
            prefetch(kb + 1, cur ^ 1);
            asm volatile("cp.async.wait_group 1;\n");
        } else {
            asm volatile("cp.async.wait_group 0;\n");
        }
        __syncthreads();

        const char* Ac = smc + ASMA + cur * CBUF2;
        const char* Bc = smc + ASMB + cur * CBUF2;
#pragma unroll
        for (int kk = 0; kk < 4; kk++) {
            uint32_t ao = (uint32_t)((r0 + grp) * CROW2 + kk * 32 + qd * 4);
            uint32_t a[4];
            a[0] = *(const uint32_t*)(Ac + ao);
            a[1] = *(const uint32_t*)(Ac + ao + 8 * CROW2);
            a[2] = *(const uint32_t*)(Ac + ao + 16);
            a[3] = *(const uint32_t*)(Ac + ao + 8 * CROW2 + 16);
#pragma unroll
            for (int ns = 0; ns < 4; ns++) {
                uint32_t bo = (uint32_t)((c0 + ns * 8 + grp) * CROW2 + kk * 32 + qd * 4);
                uint32_t b0 = *(const uint32_t*)(Bc + bo);
                uint32_t b1 = *(const uint32_t*)(Bc + bo + 16);
                mma_f16(acc[ns], a, b0, b1);
            }
        }
    }

    const int cA = r0 + grp, cB = cA + 8;
    float yreg[4][4];
    {
        float invA = g1[cA] * rsqrtf(va1[cA] + 1e-5f);
        float addA = be1[cA] - mu1[cA] * invA + bias[cA] * invA;
        float invB = g1[cB] * rsqrtf(va1[cB] + 1e-5f);
        float addB = be1[cB] - mu1[cB] * invB + bias[cB] * invB;
#pragma unroll
        for (int ns = 0; ns < 4; ns++) {
#pragma unroll
            for (int jj = 0; jj < 2; jj++) {
                int col = c0 + ns * 8 + qd * 2 + jj;
                int ss = sbase + col;
                int nn2 = ss / LL;
                int rem2 = ss - nn2 * LL;
                float xA = x[((size_t)(nn2 * CC + cA)) * LL + rem2];
                float xB = x[((size_t)(nn2 * CC + cB)) * LL + rem2];
                float yA = fmaxf(acc[ns][jj]     * invA + addA + xA, 0.f);
                float yB = fmaxf(acc[ns][jj + 2] * invB + addB + xB, 0.f);
                yreg[ns][jj]     = yA;
                yreg[ns][jj + 2] = yB;
                *(__half*)(smc + ASMY + col * YROW + cA * 2) = __float2half_rn(yA);
                *(__half*)(smc + ASMY + col * YROW + cB * 2) = __float2half_rn(yB);
            }
        }
    }
    __syncthreads();

    float fac[4][4] = {};
#pragma unroll
    for (int kk = 0; kk < 4; kk++) {
        uint32_t ao = (uint32_t)(ASMW + (r0 + grp) * YROW + kk * 32 + qd * 4);
        uint32_t a[4];
        a[0] = *(const uint32_t*)(smc + ao);
        a[1] = *(const uint32_t*)(smc + ao + 8 * YROW);
        a[2] = *(const uint32_t*)(smc + ao + 16);
        a[3] = *(const uint32_t*)(smc + ao + 8 * YROW + 16);
#pragma unroll
        for (int ns = 0; ns < 4; ns++) {
            uint32_t bo = (uint32_t)(ASMY + (c0 + ns * 8 + grp) * YROW + kk * 32 + qd * 4);
            uint32_t b0 = *(const uint32_t*)(smc + bo);
            uint32_t b1 = *(const uint32_t*)(smc + bo + 16);
            mma_f16(fac[ns], a, b0, b1);
        }
    }

    {
        float invA = g2[cA] * rsqrtf(va2[cA] + 1e-5f);
        float addA = be2[cA] - mu2[cA] * invA + bff[cA] * invA;
        float invB = g2[cB] * rsqrtf(va2[cB] + 1e-5f);
        float addB = be2[cB] - mu2[cB] * invB + bff[cB] * invB;
#pragma unroll
        for (int ns = 0; ns < 4; ns++) {
#pragma unroll
            for (int jj = 0; jj < 2; jj++) {
                int ss = sbase + c0 + ns * 8 + qd * 2 + jj;
                int nn2 = ss / LL;
                int rem2 = ss - nn2 * LL;
                float zA = fac[ns][jj]     * invA + addA + yreg[ns][jj];
                float zB = fac[ns][jj + 2] * invB + addB + yreg[ns][jj + 2];
                out[((size_t)(nn2 * CC + cA)) * LL + rem2] = fmaxf(zA, 0.f);
                out[((size_t)(nn2 * CC + cB)) * LL + rem2] = fmaxf(zB, 0.f);
            }
        }
    }
}

// ---------------------------------------------------------------------------
extern "C" void kernel_launch(void* const* d_in, const int* in_sizes, int n_in,
                              void* d_out, int out_size) {
    const float* x     = (const float*)d_in[0];
    const float* W_qkv = (const float*)d_in[1];
    const float* b_qkv = (const float*)d_in[2];
    const float* W_out = (const float*)d_in[3];
    const float* b_out = (const float*)d_in[4];
    const float* g1    = (const float*)d_in[5];
    const float* be1   = (const float*)d_in[6];
    const float* mu1   = (const float*)d_in[7];
    const float* va1   = (const float*)d_in[8];
    const float* W_ff  = (const float*)d_in[9];
    const float* b_ff  = (const float*)d_in[10];
    const float* g2    = (const float*)d_in[11];
    const float* be2   = (const float*)d_in[12];
    const float* mu2   = (const float*)d_in[13];
    const float* va2   = (const float*)d_in[14];
    float* out = (float*)d_out;

    cudaFuncSetAttribute(attn_kernel,
                         cudaFuncAttributeMaxDynamicSharedMemorySize, ASM_TOT);
    const int CONV_SMEM = 4 * CBUF2 + 2 * 64 * YROW;   // 36864+18432 = 55296
    cudaFuncSetAttribute(conv_kernel,
                         cudaFuncAttributeMaxDynamicSharedMemorySize, CONV_SMEM);

    wt_kernel<<<576, 256>>>(W_out);
    wq_kernel<<<192, 256>>>(W_qkv);
    qkv_kernel<<<400, 256>>>(x, b_qkv);
    attn_kernel<<<dim3(13, 64), 128, ASM_TOT>>>();
    conv_kernel<<<400, 256, CONV_SMEM>>>(x, b_out, g1, be1, mu1, va1,
                                         W_ff, b_ff, g2, be2, mu2, va2, out);
}

// round 17
// speedup vs baseline: 2.6216x; 1.1014x over previous
#include <cuda_runtime.h>
#include <cuda_fp16.h>
#include <math.h>
#include <stdint.h>

// Problem constants
#define NB 16      // batch
#define CC 64      // channels
#define TT 64      // time
#define VV 25      // vertices
#define HH 4       // heads
#define DD 64      // head dim
#define LL (TT*VV) // 1600 tokens
#define HD (HH*DD) // 256

// Scratch (device globals; no runtime allocation allowed)
__device__ __half g_q[NB*HH*LL*DD];   // [nh][l][d], pre-scaled by 0.125*log2e
__device__ __half g_k[NB*HH*LL*DD];   // [nh][l][d]
__device__ __half g_v[NB*HH*DD*LL];   // [nh][d][l]  (TRANSPOSED)
__device__ __half g_o[NB*LL*HD];      // attention out, [n][l][ci]  (fp16)
__device__ __half g_wt[9*64*256];     // W_out as [kw][c][ci]  (fp16)
__device__ __half g_wq[768*64];       // W_qkv as [j][c]       (fp16)

// ---- fp16 mma m16n8k16, fp32 C ---------------------------------------------
__device__ __forceinline__ void mma_f16(float c[4], const uint32_t a[4],
                                        uint32_t b0, uint32_t b1) {
    asm("mma.sync.aligned.m16n8k16.row.col.f32.f16.f16.f32 "
        "{%0,%1,%2,%3},{%4,%5,%6,%7},{%8,%9},{%0,%1,%2,%3};"
        : "+f"(c[0]), "+f"(c[1]), "+f"(c[2]), "+f"(c[3])
        : "r"(a[0]), "r"(a[1]), "r"(a[2]), "r"(a[3]), "r"(b0), "r"(b1));
}
// ---- fp16 mma m16n8k16, fp16 C/D (S-GEMM: output pre-packed half2) ---------
__device__ __forceinline__ void mma_f16h(uint32_t c[2], const uint32_t a[4],
                                         uint32_t b0, uint32_t b1) {
    asm("mma.sync.aligned.m16n8k16.row.col.f16.f16.f16.f16 "
        "{%0,%1},{%2,%3,%4,%5},{%6,%7},{%0,%1};"
        : "+r"(c[0]), "+r"(c[1])
        : "r"(a[0]), "r"(a[1]), "r"(a[2]), "r"(a[3]), "r"(b0), "r"(b1));
}
__device__ __forceinline__ uint32_t h2bits(float lo, float hi) {
    __half2 h = __floats2half2_rn(lo, hi);
    return *(uint32_t*)&h;
}
// packed exp2(v - 4.0) on half2 (0x4400 = half(4.0))
__device__ __forceinline__ uint32_t hex2(uint32_t v) {
    uint32_t r;
    asm("{\n\t.reg .b32 t;\n\t"
        "sub.f16x2 t, %1, %2;\n\t"
        "ex2.approx.f16x2 %0, t;\n\t}"
        : "=r"(r) : "r"(v), "r"(0x44004400u));
    return r;
}

// ---- cp.async helpers -------------------------------------------------------
__device__ __forceinline__ void cp16(uint32_t saddr, const void* gptr) {
    asm volatile("cp.async.cg.shared.global [%0], [%1], 16;\n"
                 :: "r"(saddr), "l"(gptr));
}
__device__ __forceinline__ void cp16z(uint32_t saddr, const void* gptr, int srcsz) {
    asm volatile("cp.async.cg.shared.global [%0], [%1], 16, %2;\n"
                 :: "r"(saddr), "l"(gptr), "r"(srcsz));
}
__device__ __forceinline__ void cp_commit() {
    asm volatile("cp.async.commit_group;\n");
}

// ---------------------------------------------------------------------------
// Kernel 0a: W_out [c][ci*9+kw] -> g_wt[kw][c][ci]  (fp16)
// ---------------------------------------------------------------------------
__global__ void wt_kernel(const float* __restrict__ W) {
    int idx = blockIdx.x * 256 + threadIdx.x;
    if (idx < 9 * 64 * 256) {
        int ci = idx & 255;
        int c  = (idx >> 8) & 63;
        int kw = idx >> 14;
        g_wt[idx] = __float2half_rn(W[c * 2304 + ci * 9 + kw]);
    }
}
// Kernel 0b: W_qkv [c][j] -> g_wq[j][c]  (fp16)
__global__ void wq_kernel(const float* __restrict__ W) {
    int idx = blockIdx.x * 256 + threadIdx.x;
    if (idx < 768 * 64) {
        int c = idx & 63;
        int j = idx >> 6;
        g_wq[idx] = __float2half_rn(W[c * 768 + j]);
    }
}

// ---------------------------------------------------------------------------
// Kernel 1: QKV projection (proven R16, byte-identical).
// ---------------------------------------------------------------------------
__global__ void __launch_bounds__(256) qkv_kernel(
                           const float* __restrict__ x,
                           const float* __restrict__ bq) {
    __shared__ __half Xh[64 * 72];
    __shared__ __half Wh[2][64 * 72];
    __shared__ __half Vt2[64 * 72];
    char* Xc = (char*)Xh;
    const uint32_t whb = (uint32_t)__cvta_generic_to_shared(Wh);
    const int by = blockIdx.x;
    const int tid = threadIdx.x;
    const int warp = tid >> 5, lane = tid & 31;
    const int wr = warp >> 1, wcc = warp & 1;
    const int r0 = wr * 16, c0 = wcc * 32;
    const int grp = lane >> 2, qd = lane & 3;

    const int row_base = by * 64;
    const int n  = row_base / LL;
    const int l0 = row_base % LL;

    const int wrow = tid >> 3, wch = tid & 7;
    auto prefW = [&](int jt, int buf) {
        const char* src = (const char*)g_wq + (size_t)jt * 64 * 128;
#pragma unroll
        for (int it = 0; it < 2; it++) {
            int r = wrow + it * 32;
            cp16(whb + (uint32_t)(buf * 9216 + r * 144 + wch * 16),
                 src + r * 128 + wch * 16);
        }
        cp_commit();
    };
    prefW(0, 0);

    const float* xb = x + (size_t)n * CC * LL + l0;
#pragma unroll
    for (int it = 0; it < 16; it++) {
        int idx = tid + it * 256;
        int c = idx >> 6, ll = idx & 63;
        Xh[ll * 72 + c] = __float2half_rn(xb[c * LL + ll]);
    }
    __syncthreads();

    uint32_t xfrag[4][4];
#pragma unroll
    for (int kk = 0; kk < 4; kk++) {
        uint32_t ao = (uint32_t)((r0 + grp) * 144 + kk * 32 + qd * 4);
        xfrag[kk][0] = *(const uint32_t*)(Xc + ao);
        xfrag[kk][1] = *(const uint32_t*)(Xc + ao + 8 * 144);
        xfrag[kk][2] = *(const uint32_t*)(Xc + ao + 16);
        xfrag[kk][3] = *(const uint32_t*)(Xc + ao + 8 * 144 + 16);
    }

    for (int jt = 0; jt < 12; jt++) {
        const int cur = jt & 1;
        __syncthreads();
        if (jt < 11) {
            prefW(jt + 1, cur ^ 1);
            asm volatile("cp.async.wait_group 1;\n");
        } else {
            asm volatile("cp.async.wait_group 0;\n");
        }
        __syncthreads();

        const char* Wc = (const char*)&Wh[cur][0];
        float acc[4][4] = {};
#pragma unroll
        for (int kk = 0; kk < 4; kk++) {
#pragma unroll
            for (int ns = 0; ns < 4; ns++) {
                uint32_t bo = (uint32_t)((c0 + ns * 8 + grp) * 144 + kk * 32 + qd * 4);
                uint32_t b0 = *(const uint32_t*)(Wc + bo);
                uint32_t b1 = *(const uint32_t*)(Wc + bo + 16);
                mma_f16(acc[ns], xfrag[kk], b0, b1);
            }
        }

        const int part = jt >> 2;
        const int h    = jt & 3;
        const int nh   = n * HH + h;

        if (part == 2) {
#pragma unroll
            for (int ns = 0; ns < 4; ns++) {
                int d = c0 + ns * 8 + qd * 2;
                float bb0 = bq[jt * 64 + d];
                float bb1 = bq[jt * 64 + d + 1];
                int la = r0 + grp, lb = la + 8;
                Vt2[(d)     * 72 + la] = __float2half_rn(acc[ns][0] + bb0);
                Vt2[(d + 1) * 72 + la] = __float2half_rn(acc[ns][1] + bb1);
                Vt2[(d)     * 72 + lb] = __float2half_rn(acc[ns][2] + bb0);
                Vt2[(d + 1) * 72 + lb] = __float2half_rn(acc[ns][3] + bb1);
            }
            __syncthreads();
            __half2* gv2 = (__half2*)g_v;
#pragma unroll
            for (int it = 0; it < 8; it++) {
                int idx = tid + it * 256;
                int d = idx >> 5, lh = idx & 31;
                __half2 hv = *(__half2*)&Vt2[d * 72 + lh * 2];
                gv2[(((size_t)nh * 64 + d) * LL + l0) / 2 + lh] = hv;
            }
        } else {
            const float scale = (part == 0) ? (0.125f * 1.44269504f) : 1.f;
            __half2* dst2 = (__half2*)((part == 0) ? g_q : g_k);
            const int lA = l0 + r0 + grp;
            const int lB = lA + 8;
#pragma unroll
            for (int ns = 0; ns < 4; ns++) {
                int d = c0 + ns * 8 + qd * 2;
                float bb0 = bq[jt * 64 + d];
                float bb1 = bq[jt * 64 + d + 1];
                __half2 hA = __floats2half2_rn((acc[ns][0] + bb0) * scale,
                                               (acc[ns][1] + bb1) * scale);
                __half2 hB = __floats2half2_rn((acc[ns][2] + bb0) * scale,
                                               (acc[ns][3] + bb1) * scale);
                dst2[(((size_t)nh * LL + lA) * 64 + d) >> 1] = hA;
                dst2[(((size_t)nh * LL + lB) * 64 + d) >> 1] = hB;
            }
        }
    }
}

// ---------------------------------------------------------------------------
// Kernel 2: fp16 flash attention v5.
//  - S-GEMM uses fp16 C/D: output D-frag == PV A-frag (no cvt/pack at all)
//  - softmax = sub.f16x2 + ex2.approx.f16x2 (MUFU halved)
//  - row sums via ones-column MMA (V rows 64..71: row 64 = 1.0h)
// ---------------------------------------------------------------------------
#define ROWB 144
#define ASM_Q 0
#define ASM_K 18432
#define ASM_V 36864
#define KVBUF_K 9216
#define KVBUF_V 10368            // 72 rows x 144 B
#define ASM_TOT (36864 + 2*10368)  // 57600
#define OP2 88

extern __shared__ char attn_smc[];
__global__ void __launch_bounds__(128, 3) attn_kernel() {
    char* smc = attn_smc;
    const uint32_t smb = (uint32_t)__cvta_generic_to_shared(smc);
    const int qb = blockIdx.x, nh = blockIdx.y;
    const int tid = threadIdx.x;
    const int warp = tid >> 5, lane = tid & 31;
    const int grp = lane >> 2, qd = lane & 3;
    const int q_base = (qb * 128 <= LL - 128) ? qb * 128 : (LL - 128);

    const char* qsrc = (const char*)(g_q + ((size_t)nh * LL + q_base) * 64);
    const char* ksrc = (const char*)(g_k + (size_t)nh * LL * 64);
    const char* vsrc = (const char*)(g_v + (size_t)nh * 64 * LL);

#pragma unroll
    for (int it = 0; it < 8; it++) {           // Q
        int idx = tid + it * 128;
        int r = idx >> 3, c = idx & 7;
        cp16(smb + ASM_Q + r * ROWB + c * 16, qsrc + r * 128 + c * 16);
    }
#pragma unroll
    for (int it = 0; it < 4; it++) {           // K0
        int idx = tid + it * 128;
        int r = idx >> 3, c = idx & 7;
        cp16(smb + ASM_K + r * ROWB + c * 16, ksrc + r * 128 + c * 16);
    }
#pragma unroll
    for (int it = 0; it < 4; it++) {           // V0
        int idx = tid + it * 128;
        int r = idx >> 3, c = idx & 7;
        cp16(smb + ASM_V + r * ROWB + c * 16, vsrc + (size_t)r * (LL * 2) + c * 16);
    }
    cp_commit();
#pragma unroll
    for (int it = 0; it < 4; it++) {           // K1 + V1
        int idx = tid + it * 128;
        int r = idx >> 3, c = idx & 7;
        cp16(smb + ASM_K + KVBUF_K + r * ROWB + c * 16,
             ksrc + 128 * 64 + r * 128 + c * 16);
        cp16(smb + ASM_V + KVBUF_V + r * ROWB + c * 16,
             vsrc + (size_t)r * (LL * 2) + 128 + c * 16);
    }
    cp_commit();

    // init lsum rows (64..71) of BOTH V buffers: row 64 = 1.0h, rest 0
    for (int idx = tid; idx < 2 * 8 * 36; idx += 128) {
        int buf = idx / (8 * 36);
        int rr  = (idx / 36) & 7;
        int cc  = idx % 36;
        uint32_t val = (rr == 0) ? 0x3C003C00u : 0u;
        *(uint32_t*)(smc + ASM_V + buf * KVBUF_V + (64 + rr) * ROWB + cc * 4) = val;
    }

    asm volatile("cp.async.wait_group 1;\n");
    __syncthreads();

    uint32_t qfrag[2][4][4];
#pragma unroll
    for (int mt = 0; mt < 2; mt++) {
        const uint32_t qr = (uint32_t)((warp * 32 + mt * 16 + grp) * ROWB);
#pragma unroll
        for (int kk = 0; kk < 4; kk++) {
            uint32_t base = (uint32_t)(ASM_Q) + qr + kk * 32 + qd * 4;
            qfrag[mt][kk][0] = *(const uint32_t*)(smc + base);
            qfrag[mt][kk][1] = *(const uint32_t*)(smc + base + 8 * ROWB);
            qfrag[mt][kk][2] = *(const uint32_t*)(smc + base + 16);
            qfrag[mt][kk][3] = *(const uint32_t*)(smc + base + 8 * ROWB + 16);
        }
    }

    float oacc[2][8][4] = {};
    float oex[2][4] = {};            // ones-column C-frags (row sums)

    for (int t = 0; t < 25; t++) {
        const uint32_t kb = (uint32_t)(ASM_K + (t & 1) * KVBUF_K);
        const uint32_t vb = (uint32_t)(ASM_V + (t & 1) * KVBUF_V);

        // ---- S = Q @ K^T (fp16 C/D: output pre-packed) ----
        uint32_t sacc[2][8][2] = {};
#pragma unroll
        for (int kk = 0; kk < 4; kk++) {
#pragma unroll
            for (int ns = 0; ns < 8; ns++) {
                uint32_t ba = kb + (ns * 8 + grp) * ROWB + kk * 32 + qd * 4;
                uint32_t b0 = *(const uint32_t*)(smc + ba);
                uint32_t b1 = *(const uint32_t*)(smc + ba + 16);
                mma_f16h(sacc[0][ns], qfrag[0][kk], b0, b1);
                mma_f16h(sacc[1][ns], qfrag[1][kk], b0, b1);
            }
        }

        // ---- softmax: packed p = exp2(s - 4) (in-place, stays in regs) ----
#pragma unroll
        for (int mt = 0; mt < 2; mt++)
#pragma unroll
            for (int ns = 0; ns < 8; ns++) {
                sacc[mt][ns][0] = hex2(sacc[mt][ns][0]);
                sacc[mt][ns][1] = hex2(sacc[mt][ns][1]);
            }

        // ---- O += P @ V ; lsum via ones-column (V rows 64..71) ----
#pragma unroll
        for (int kk = 0; kk < 4; kk++) {
            uint32_t a0[4], a1[4];
            a0[0] = sacc[0][2*kk][0];     a0[1] = sacc[0][2*kk][1];
            a0[2] = sacc[0][2*kk + 1][0]; a0[3] = sacc[0][2*kk + 1][1];
            a1[0] = sacc[1][2*kk][0];     a1[1] = sacc[1][2*kk][1];
            a1[2] = sacc[1][2*kk + 1][0]; a1[3] = sacc[1][2*kk + 1][1];
#pragma unroll
            for (int ns = 0; ns < 8; ns++) {
                uint32_t ba = vb + (ns * 8 + grp) * ROWB + kk * 32 + qd * 4;
                uint32_t b0 = *(const uint32_t*)(smc + ba);
                uint32_t b1 = *(const uint32_t*)(smc + ba + 16);
                mma_f16(oacc[0][ns], a0, b0, b1);
                mma_f16(oacc[1][ns], a1, b0, b1);
            }
            {   // ones-column block (rows 64..71; only row 64 nonzero)
                uint32_t ba = vb + (64 + grp) * ROWB + kk * 32 + qd * 4;
                uint32_t b0 = *(const uint32_t*)(smc + ba);
                uint32_t b1 = *(const uint32_t*)(smc + ba + 16);
                mma_f16(oex[0], a0, b0, b1);
                mma_f16(oex[1], a1, b0, b1);
            }
        }

        __syncthreads();
        if (t + 2 <= 24) {
            const char* kp = ksrc + (size_t)(t + 2) * 64 * 128;
            const char* vp = vsrc + (size_t)(t + 2) * 128;
            uint32_t kd = (uint32_t)(ASM_K + (t & 1) * KVBUF_K);
            uint32_t vd = (uint32_t)(ASM_V + (t & 1) * KVBUF_V);
#pragma unroll
            for (int it = 0; it < 4; it++) {
                int idx = tid + it * 128;
                int r = idx >> 3, c = idx & 7;
                cp16(smb + kd + r * ROWB + c * 16, kp + r * 128 + c * 16);
                cp16(smb + vd + r * ROWB + c * 16, vp + (size_t)r * (LL * 2) + c * 16);
            }
            cp_commit();
        }
        if (t + 1 <= 24) {
            if (t + 2 <= 24) asm volatile("cp.async.wait_group 1;\n");
            else             asm volatile("cp.async.wait_group 0;\n");
            __syncthreads();
        }
    }

    // ---- row sums live in oex at qd==0 (cols 64): broadcast across quad ----
    __syncthreads();
    __half* Oth = (__half*)smc;   // [128 l][OP2 d]
#pragma unroll
    for (int mt = 0; mt < 2; mt++) {
        int src = (lane & ~3);    // qd==0 lane of this quad
        float s0 = __shfl_sync(0xFFFFFFFFu, oex[mt][0], src);
        float s1 = __shfl_sync(0xFFFFFFFFu, oex[mt][2], src);
        float linv0 = 1.f / s0;
        float linv1 = 1.f / s1;
        int la = warp * 32 + mt * 16 + grp, lb = la + 8;
#pragma unroll
        for (int ns = 0; ns < 8; ns++) {
            int d = ns * 8 + qd * 2;
            *(__half2*)&Oth[la * OP2 + d] =
                __floats2half2_rn(oacc[mt][ns][0] * linv0, oacc[mt][ns][1] * linv0);
            *(__half2*)&Oth[lb * OP2 + d] =
                __floats2half2_rn(oacc[mt][ns][2] * linv1, oacc[mt][ns][3] * linv1);
        }
    }
    __syncthreads();

    const int n = nh >> 2, h4 = nh & 3;
    char* ob = (char*)(g_o + ((size_t)n * LL + q_base) * HD + h4 * 64);
#pragma unroll
    for (int it = 0; it < 8; it++) {
        int idx = tid + it * 128;
        int l = idx >> 3, c8 = idx & 7;
        *(float4*)(ob + (size_t)l * (HD * 2) + c8 * 16) =
            *(const float4*)((char*)Oth + l * (OP2 * 2) + c8 * 16);
    }
}

// ---------------------------------------------------------------------------
// Kernel 3: fused conv+ff (proven R16, byte-identical).
// ---------------------------------------------------------------------------
#define CROW2 144
#define CBUF2 (64 * CROW2)
#define YROW 144
extern __shared__ char conv_smc[];
__global__ void __launch_bounds__(256) conv_kernel(
                            const float* __restrict__ x,
                            const float* __restrict__ bias,
                            const float* __restrict__ g1,
                            const float* __restrict__ be1,
                            const float* __restrict__ mu1,
                            const float* __restrict__ va1,
                            const float* __restrict__ Wff,
                            const float* __restrict__ bff,
                            const float* __restrict__ g2,
                            const float* __restrict__ be2,
                            const float* __restrict__ mu2,
                            const float* __restrict__ va2,
                            float* __restrict__ out) {
    char* smc = conv_smc;
    const uint32_t smb = (uint32_t)__cvta_generic_to_shared(smc);
    const uint32_t ASMA = 0;
    const uint32_t ASMB = 2 * CBUF2;
    const uint32_t ASMY = 4 * CBUF2;
    const uint32_t ASMW = ASMY + 64*YROW;

    const int tid = threadIdx.x;
    const int sbase = blockIdx.x * 64;
    const int warp = tid >> 5, lane = tid & 31;
    const int wr = warp >> 1, wcc = warp & 1;
    const int r0 = wr * 16, c0 = wcc * 32;
    const int grp = lane >> 2, qd = lane & 3;

#pragma unroll
    for (int it = 0; it < 16; it++) {
        int idx = tid + it * 256;
        int c = idx >> 6, ci = idx & 63;
        *(__half*)(smc + ASMW + c * YROW + ci * 2) =
            __float2half_rn(Wff[c * 64 + ci]);
    }

    const int lrow = tid >> 2;
    const int lc = tid & 3;
    const int s = sbase + lrow;
    const int n = s / LL;
    const int rem = s - n * LL;
    const int t = rem / VV;
    const int v = rem - t * VV;
    const char* bsrc0 = (const char*)(g_o + ((size_t)n * LL + rem - 4) * HD);

    auto prefetch = [&](int kb, int buf) {
        const int kw = kb >> 2;
        const int cibase = (kb & 3) * 64;
        const char* asrc = (const char*)(g_wt + ((size_t)(kw * 64 + lrow)) * 256
                                         + cibase);
        uint32_t ad = smb + ASMA + buf * CBUF2 + lrow * CROW2;
        cp16(ad + lc * 16,       asrc + lc * 16);
        cp16(ad + (lc + 4) * 16, asrc + (lc + 4) * 16);
        const int vi = v + kw - 4;
        const int oksz = (vi >= 0 && vi < VV) ? 16 : 0;
        const char* bsrc = bsrc0 + (size_t)kw * (HD * 2) + cibase * 2;
        uint32_t bd = smb + ASMB + buf * CBUF2 + lrow * CROW2;
        cp16z(bd + lc * 16,       bsrc + lc * 16,       oksz);
        cp16z(bd + (lc + 4) * 16, bsrc + (lc + 4) * 16, oksz);
        cp_commit();
    };

    prefetch(0, 0);
    float acc[4][4] = {};

    for (int kb = 0; kb < 36; kb++) {
        const int cur = kb & 1;
        __syncthreads();
        if (kb < 35) {
            prefetch(kb + 1, cur ^ 1);
            asm volatile("cp.async.wait_group 1;\n");
        } else {
            asm volatile("cp.async.wait_group 0;\n");
        }
        __syncthreads();

        const char* Ac = smc + ASMA + cur * CBUF2;
        const char* Bc = smc + ASMB + cur * CBUF2;
#pragma unroll
        for (int kk = 0; kk < 4; kk++) {
            uint32_t ao = (uint32_t)((r0 + grp) * CROW2 + kk * 32 + qd * 4);
            uint32_t a[4];
            a[0] = *(const uint32_t*)(Ac + ao);
            a[1] = *(const uint32_t*)(Ac + ao + 8 * CROW2);
            a[2] = *(const uint32_t*)(Ac + ao + 16);
            a[3] = *(const uint32_t*)(Ac + ao + 8 * CROW2 + 16);
#pragma unroll
            for (int ns = 0; ns < 4; ns++) {
                uint32_t bo = (uint32_t)((c0 + ns * 8 + grp) * CROW2 + kk * 32 + qd * 4);
                uint32_t b0 = *(const uint32_t*)(Bc + bo);
                uint32_t b1 = *(const uint32_t*)(Bc + bo + 16);
                mma_f16(acc[ns], a, b0, b1);
            }
        }
    }

    const int cA = r0 + grp, cB = cA + 8;
    float yreg[4][4];
    {
        float invA = g1[cA] * rsqrtf(va1[cA] + 1e-5f);
        float addA = be1[cA] - mu1[cA] * invA + bias[cA] * invA;
        float invB = g1[cB] * rsqrtf(va1[cB] + 1e-5f);
        float addB = be1[cB] - mu1[cB] * invB + bias[cB] * invB;
#pragma unroll
        for (int ns = 0; ns < 4; ns++) {
#pragma unroll
            for (int jj = 0; jj < 2; jj++) {
                int col = c0 + ns * 8 + qd * 2 + jj;
                int ss = sbase + col;
                int nn2 = ss / LL;
                int rem2 = ss - nn2 * LL;
                float xA = x[((size_t)(nn2 * CC + cA)) * LL + rem2];
                float xB = x[((size_t)(nn2 * CC + cB)) * LL + rem2];
                float yA = fmaxf(acc[ns][jj]     * invA + addA + xA, 0.f);
                float yB = fmaxf(acc[ns][jj + 2] * invB + addB + xB, 0.f);
                yreg[ns][jj]     = yA;
                yreg[ns][jj + 2] = yB;
                *(__half*)(smc + ASMY + col * YROW + cA * 2) = __float2half_rn(yA);
                *(__half*)(smc + ASMY + col * YROW + cB * 2) = __float2half_rn(yB);
            }
        }
    }
    __syncthreads();

    float fac[4][4] = {};
#pragma unroll
    for (int kk = 0; kk < 4; kk++) {
        uint32_t ao = (uint32_t)(ASMW + (r0 + grp) * YROW + kk * 32 + qd * 4);
        uint32_t a[4];
        a[0] = *(const uint32_t*)(smc + ao);
        a[1] = *(const uint32_t*)(smc + ao + 8 * YROW);
        a[2] = *(const uint32_t*)(smc + ao + 16);
        a[3] = *(const uint32_t*)(smc + ao + 8 * YROW + 16);
#pragma unroll
        for (int ns = 0; ns < 4; ns++) {
            uint32_t bo = (uint32_t)(ASMY + (c0 + ns * 8 + grp) * YROW + kk * 32 + qd * 4);
            uint32_t b0 = *(const uint32_t*)(smc + bo);
            uint32_t b1 = *(const uint32_t*)(smc + bo + 16);
            mma_f16(fac[ns], a, b0, b1);
        }
    }

    {
        float invA = g2[cA] * rsqrtf(va2[cA] + 1e-5f);
        float addA = be2[cA] - mu2[cA] * invA + bff[cA] * invA;
        float invB = g2[cB] * rsqrtf(va2[cB] + 1e-5f);
        float addB = be2[cB] - mu2[cB] * invB + bff[cB] * invB;
#pragma unroll
        for (int ns = 0; ns < 4; ns++) {
#pragma unroll
            for (int jj = 0; jj < 2; jj++) {
                int ss = sbase + c0 + ns * 8 + qd * 2 + jj;
                int nn2 = ss / LL;
                int rem2 = ss - nn2 * LL;
                float zA = fac[ns][jj]     * invA + addA + yreg[ns][jj];
                float zB = fac[ns][jj + 2] * invB + addB + yreg[ns][jj + 2];
                out[((size_t)(nn2 * CC + cA)) * LL + rem2] = fmaxf(zA, 0.f);
                out[((size_t)(nn2 * CC + cB)) * LL + rem2] = fmaxf(zB, 0.f);
            }
        }
    }
}

// ---------------------------------------------------------------------------
extern "C" void kernel_launch(void* const* d_in, const int* in_sizes, int n_in,
                              void* d_out, int out_size) {
    const float* x     = (const float*)d_in[0];
    const float* W_qkv = (const float*)d_in[1];
    const float* b_qkv = (const float*)d_in[2];
    const float* W_out = (const float*)d_in[3];
    const float* b_out = (const float*)d_in[4];
    const float* g1    = (const float*)d_in[5];
    const float* be1   = (const float*)d_in[6];
    const float* mu1   = (const float*)d_in[7];
    const float* va1   = (const float*)d_in[8];
    const float* W_ff  = (const float*)d_in[9];
    const float* b_ff  = (const float*)d_in[10];
    const float* g2    = (const float*)d_in[11];
    const float* be2   = (const float*)d_in[12];
    const float* mu2   = (const float*)d_in[13];
    const float* va2   = (const float*)d_in[14];
    float* out = (float*)d_out;

    cudaFuncSetAttribute(attn_kernel,
                         cudaFuncAttributeMaxDynamicSharedMemorySize, ASM_TOT);
    const int CONV_SMEM = 4 * CBUF2 + 2 * 64 * YROW;   // 55296
    cudaFuncSetAttribute(conv_kernel,
                         cudaFuncAttributeMaxDynamicSharedMemorySize, CONV_SMEM);

    wt_kernel<<<576, 256>>>(W_out);
    wq_kernel<<<192, 256>>>(W_qkv);
    qkv_kernel<<<400, 256>>>(x, b_qkv);
    attn_kernel<<<dim3(13, 64), 128, ASM_TOT>>>();
    conv_kernel<<<400, 256, CONV_SMEM>>>(x, b_out, g1, be1, mu1, va1,
                                         W_ff, b_ff, g2, be2, mu2, va2, out);
}